// round 2
// baseline (speedup 1.0000x reference)
#include <cuda_runtime.h>
#include <math.h>

#define NB 4
#define NC 512
#define NL 2048
#define NCI 512
#define NH 8
#define ND 64

// Scratch (device globals; no allocations allowed)
__device__ float d_proj[3 * NB * NCI * NL];   // [which][b][ci][l]; which: 0=g, 1=theta, 2=phi
__device__ float d_y[NB * NCI * NL];          // attention output [b][ci][l]
__device__ float d_wy[NB * NC * NL];          // final conv output (pre-BN)
__device__ float d_bnmean[NC];
__device__ float d_bnrstd[NC];

// ---------------------------------------------------------------------------
// Shared 128x64 fp32 GEMM body: out[m,n] = sum_k A[m,k] * X[k,n] + bias[m]
// A: [512,512] row-major, X: [512,NL], out: [512,NL]. BK=16, 256 threads,
// 8m x 4n per thread.
// ---------------------------------------------------------------------------
__device__ __forceinline__ void gemm_body(
    const float* __restrict__ A,
    const float* __restrict__ X,
    const float* __restrict__ bias,
    float* __restrict__ out)
{
    __shared__ float As[16 * 128];
    __shared__ float Bs[16 * 64];
    const int tid = threadIdx.x;
    const int tx = tid & 15;
    const int ty = tid >> 4;
    const int m0 = blockIdx.y * 128;
    const int n0 = blockIdx.x * 64;

    float acc[8][4];
#pragma unroll
    for (int i = 0; i < 8; i++)
#pragma unroll
        for (int j = 0; j < 4; j++) acc[i][j] = 0.f;

    const int ag = tid & 3;    // A k-group (float4)
    const int am = tid >> 2;   // 0..63
    const int bn_ = tid & 63;
    const int bk = tid >> 6;   // 0..3

    for (int k0 = 0; k0 < 512; k0 += 16) {
#pragma unroll
        for (int r = 0; r < 2; r++) {
            int mm = am + r * 64;
            float4 a = *reinterpret_cast<const float4*>(&A[(m0 + mm) * 512 + k0 + ag * 4]);
            As[(ag * 4 + 0) * 128 + mm] = a.x;
            As[(ag * 4 + 1) * 128 + mm] = a.y;
            As[(ag * 4 + 2) * 128 + mm] = a.z;
            As[(ag * 4 + 3) * 128 + mm] = a.w;
        }
#pragma unroll
        for (int r = 0; r < 4; r++)
            Bs[(bk + r * 4) * 64 + bn_] = X[(k0 + bk + r * 4) * NL + n0 + bn_];
        __syncthreads();
#pragma unroll
        for (int kk = 0; kk < 16; kk++) {
            float4 a0 = *reinterpret_cast<const float4*>(&As[kk * 128 + ty * 8]);
            float4 a1 = *reinterpret_cast<const float4*>(&As[kk * 128 + ty * 8 + 4]);
            float4 bv = *reinterpret_cast<const float4*>(&Bs[kk * 64 + tx * 4]);
            float amr[8] = {a0.x, a0.y, a0.z, a0.w, a1.x, a1.y, a1.z, a1.w};
            float bnr[4] = {bv.x, bv.y, bv.z, bv.w};
#pragma unroll
            for (int i = 0; i < 8; i++)
#pragma unroll
                for (int j = 0; j < 4; j++) acc[i][j] = fmaf(amr[i], bnr[j], acc[i][j]);
        }
        __syncthreads();
    }
#pragma unroll
    for (int i = 0; i < 8; i++) {
        int m = m0 + ty * 8 + i;
        float bi = bias[m];
        float4 o = make_float4(acc[i][0] + bi, acc[i][1] + bi, acc[i][2] + bi, acc[i][3] + bi);
        *reinterpret_cast<float4*>(&out[m * NL + n0 + tx * 4]) = o;
    }
}

// grid: (NL/64=32, 512/128=4, 3*NB=12)
__global__ void __launch_bounds__(256) proj_kernel(
    const float* __restrict__ x,
    const float* __restrict__ gw, const float* __restrict__ gb,
    const float* __restrict__ tw, const float* __restrict__ tb,
    const float* __restrict__ pw, const float* __restrict__ pb)
{
    int z = blockIdx.z;
    int which = z >> 2;   // 0..2
    int b = z & 3;
    const float* A = (which == 0) ? gw : (which == 1) ? tw : pw;
    const float* bias = (which == 0) ? gb : (which == 1) ? tb : pb;
    gemm_body(A, x + (size_t)b * NC * NL, bias,
              d_proj + ((size_t)which * NB + b) * NCI * NL);
}

// grid: (32, 4, NB)
__global__ void __launch_bounds__(256) gemm2_kernel(
    const float* __restrict__ ww, const float* __restrict__ wb)
{
    int b = blockIdx.z;
    gemm_body(ww, d_y + (size_t)b * NCI * NL, wb, d_wy + (size_t)b * NC * NL);
}

// ---------------------------------------------------------------------------
// Flash attention: per (b,h), Q=theta^T [L,64], K=phi [64,L], V=g [64,L].
// q-tile=128, k-tile=64, 256 threads, thread tile 8q x 4{k|d}.
// grid: (NL/128=16, NB*NH=32). Dynamic smem ~99KB.
// ---------------------------------------------------------------------------
#define ATT_SMEM ((64 * 128 + 64 * 64 + 64 * 65 + 128 * 65) * 4)

__global__ void __launch_bounds__(256, 2) attn_kernel()
{
    extern __shared__ float sm[];
    float* Qs = sm;                  // [64 d][128 q], pitch 128
    float* Ks = Qs + 64 * 128;       // [64 d][64 k], pitch 64
    float* Vs = Ks + 64 * 64;        // [64 d][64 k], pitch 65
    float* Ps = Vs + 64 * 65;        // [128 q][64 k], pitch 65 (reused as [64 d][128 q] pitch 129)

    const int tid = threadIdx.x;
    const int tx = tid & 15;   // k/d dimension (4 each)
    const int ty = tid >> 4;   // q dimension (8 each)
    const int q0 = blockIdx.x * 128;
    const int bh = blockIdx.y;
    const int b = bh >> 3;
    const int h = bh & 7;

    const float* theta = d_proj + ((size_t)(1 * NB + b) * NCI + h * ND) * NL;
    const float* phi   = d_proj + ((size_t)(2 * NB + b) * NCI + h * ND) * NL;
    const float* gx    = d_proj + ((size_t)(0 * NB + b) * NCI + h * ND) * NL;

    // Load Q tile (scaled by 1/sqrt(D) here)
    for (int i = tid; i < 64 * 128; i += 256) {
        int d = i >> 7, q = i & 127;
        Qs[i] = theta[d * NL + q0 + q] * 0.125f;
    }

    float m[8], l[8], acc[8][4];
#pragma unroll
    for (int i = 0; i < 8; i++) {
        m[i] = -1e30f; l[i] = 0.f;
#pragma unroll
        for (int j = 0; j < 4; j++) acc[i][j] = 0.f;
    }

    for (int k0 = 0; k0 < NL; k0 += 64) {
        __syncthreads();  // prior-iter readers done (also orders Q load, iter 0)
        for (int i = tid; i < 64 * 64; i += 256) {
            int d = i >> 6, k = i & 63;
            float kv = phi[d * NL + k0 + k];
            float vv = gx[d * NL + k0 + k];
            Ks[d * 64 + k] = kv;
            Vs[d * 65 + k] = vv;
        }
        __syncthreads();

        // S = Q K : s[8q][4k]
        float s[8][4];
#pragma unroll
        for (int i = 0; i < 8; i++)
#pragma unroll
            for (int j = 0; j < 4; j++) s[i][j] = 0.f;

#pragma unroll 8
        for (int d = 0; d < 64; d++) {
            float4 qa = *reinterpret_cast<const float4*>(Qs + d * 128 + ty * 8);
            float4 qb = *reinterpret_cast<const float4*>(Qs + d * 128 + ty * 8 + 4);
            float4 kv = *reinterpret_cast<const float4*>(Ks + d * 64 + tx * 4);
            float qm[8] = {qa.x, qa.y, qa.z, qa.w, qb.x, qb.y, qb.z, qb.w};
            float kn[4] = {kv.x, kv.y, kv.z, kv.w};
#pragma unroll
            for (int i = 0; i < 8; i++)
#pragma unroll
                for (int j = 0; j < 4; j++) s[i][j] = fmaf(qm[i], kn[j], s[i][j]);
        }

        // Online softmax per q row (reduce across the 16 tx lanes)
#pragma unroll
        for (int qi = 0; qi < 8; qi++) {
            float tmax = fmaxf(fmaxf(s[qi][0], s[qi][1]), fmaxf(s[qi][2], s[qi][3]));
#pragma unroll
            for (int msk = 1; msk < 16; msk <<= 1)
                tmax = fmaxf(tmax, __shfl_xor_sync(0xffffffffu, tmax, msk));
            float mn = fmaxf(m[qi], tmax);
            float corr = __expf(m[qi] - mn);
            float psum = 0.f;
#pragma unroll
            for (int ki = 0; ki < 4; ki++) {
                float p = __expf(s[qi][ki] - mn);
                s[qi][ki] = p;
                psum += p;
            }
#pragma unroll
            for (int msk = 1; msk < 16; msk <<= 1)
                psum += __shfl_xor_sync(0xffffffffu, psum, msk);
            l[qi] = l[qi] * corr + psum;
            m[qi] = mn;
#pragma unroll
            for (int di = 0; di < 4; di++) acc[qi][di] *= corr;
            int row = ty * 8 + qi;
#pragma unroll
            for (int ki = 0; ki < 4; ki++) Ps[row * 65 + tx * 4 + ki] = s[qi][ki];
        }
        __syncthreads();

        // acc += P V^T : acc[8q][4d]
#pragma unroll 8
        for (int k = 0; k < 64; k++) {
            float vv[4];
#pragma unroll
            for (int di = 0; di < 4; di++) vv[di] = Vs[(tx * 4 + di) * 65 + k];
#pragma unroll
            for (int qi = 0; qi < 8; qi++) {
                float p = Ps[(ty * 8 + qi) * 65 + k];
#pragma unroll
                for (int di = 0; di < 4; di++) acc[qi][di] = fmaf(p, vv[di], acc[qi][di]);
            }
        }
    }
    __syncthreads();

    // Epilogue: normalize, transpose via smem (reuse Ps as [64 d][128 q] pitch 129)
#pragma unroll
    for (int qi = 0; qi < 8; qi++) {
        float inv = 1.0f / l[qi];
#pragma unroll
        for (int di = 0; di < 4; di++)
            Ps[(tx * 4 + di) * 129 + ty * 8 + qi] = acc[qi][di] * inv;
    }
    __syncthreads();

    float* yout = d_y + ((size_t)b * NCI + h * ND) * NL;
    for (int i = tid; i < 64 * 128; i += 256) {
        int d = i >> 7, q = i & 127;
        yout[d * NL + q0 + q] = Ps[d * 129 + q];
    }
}

// ---------------------------------------------------------------------------
// BatchNorm1d (training mode, biased stats) over (B, L) per channel.
// ---------------------------------------------------------------------------
__global__ void __launch_bounds__(256) bn_stats_kernel()
{
    const int c = blockIdx.x;
    const int tid = threadIdx.x;
    double s = 0.0, s2 = 0.0;
    for (int i = tid; i < NB * NL; i += 256) {
        int b = i >> 11, l = i & 2047;
        float v = d_wy[((size_t)b * NC + c) * NL + l];
        s += (double)v;
        s2 += (double)v * (double)v;
    }
    __shared__ double sh[256], sh2[256];
    sh[tid] = s; sh2[tid] = s2;
    __syncthreads();
    for (int off = 128; off > 0; off >>= 1) {
        if (tid < off) { sh[tid] += sh[tid + off]; sh2[tid] += sh2[tid + off]; }
        __syncthreads();
    }
    if (tid == 0) {
        double mean = sh[0] / (double)(NB * NL);
        double var = sh2[0] / (double)(NB * NL) - mean * mean;
        d_bnmean[c] = (float)mean;
        d_bnrstd[c] = (float)(1.0 / sqrt(var + 1e-5));
    }
}

__global__ void __launch_bounds__(256) bn_apply_kernel(
    const float* __restrict__ gamma, const float* __restrict__ beta,
    float* __restrict__ out)
{
    int idx = blockIdx.x * 256 + threadIdx.x;
    int c = (idx >> 11) & (NC - 1);
    out[idx] = (d_wy[idx] - d_bnmean[c]) * d_bnrstd[c] * gamma[c] + beta[c];
}

// ---------------------------------------------------------------------------
extern "C" void kernel_launch(void* const* d_in, const int* in_sizes, int n_in,
                              void* d_out, int out_size)
{
    const float* x     = (const float*)d_in[0];
    const float* gw    = (const float*)d_in[1];
    const float* gb    = (const float*)d_in[2];
    const float* tw    = (const float*)d_in[3];
    const float* tb    = (const float*)d_in[4];
    const float* pw    = (const float*)d_in[5];
    const float* pb    = (const float*)d_in[6];
    const float* ww    = (const float*)d_in[7];
    const float* wb    = (const float*)d_in[8];
    const float* gamma = (const float*)d_in[9];
    const float* beta  = (const float*)d_in[10];
    float* out = (float*)d_out;

    cudaFuncSetAttribute(attn_kernel, cudaFuncAttributeMaxDynamicSharedMemorySize, ATT_SMEM);

    proj_kernel<<<dim3(NL / 64, 4, 3 * NB), 256>>>(x, gw, gb, tw, tb, pw, pb);
    attn_kernel<<<dim3(NL / 128, NB * NH), 256, ATT_SMEM>>>();
    gemm2_kernel<<<dim3(NL / 64, 4, NB), 256>>>(ww, wb);
    bn_stats_kernel<<<NC, 256>>>();
    bn_apply_kernel<<<(NB * NC * NL) / 256, 256>>>(gamma, beta, out);
}

// round 4
// speedup vs baseline: 2.0035x; 2.0035x over previous
#include <cuda_runtime.h>
#include <cstdint>
#include <math.h>

#define NB 4
#define NC 512
#define NL 2048
#define NCI 512
#define NH 8
#define ND 64

__device__ float d_proj[3 * NB * NCI * NL];   // [which][b][ci][l]; 0=g,1=theta,2=phi
__device__ float d_y[NB * NCI * NL];
__device__ float d_wy[NB * NC * NL];
__device__ float d_bnmean[NC];
__device__ float d_bnrstd[NC];

// ---------------- helpers ----------------
__device__ __forceinline__ float tfr(float x) {        // round-to-nearest tf32
    uint32_t u;
    asm("cvt.rna.tf32.f32 %0, %1;" : "=r"(u) : "f"(x));
    return __uint_as_float(u);
}
__device__ __forceinline__ uint32_t fu(float x) { return __float_as_uint(x); }

__device__ __forceinline__ void mma8(float* c,
                                     uint32_t a0, uint32_t a1, uint32_t a2, uint32_t a3,
                                     uint32_t b0, uint32_t b1) {
    asm("mma.sync.aligned.m16n8k8.row.col.f32.tf32.tf32.f32 "
        "{%0,%1,%2,%3},{%4,%5,%6,%7},{%8,%9},{%0,%1,%2,%3};"
        : "+f"(c[0]), "+f"(c[1]), "+f"(c[2]), "+f"(c[3])
        : "r"(a0), "r"(a1), "r"(a2), "r"(a3), "r"(b0), "r"(b1));
}

// permuted-k position within a 16-slab: float4 at (lane&3)*4 yields k = c, c+4, c+8, c+12
__device__ __forceinline__ int kperm16(int k) { return ((k & 3) << 2) | ((k >> 2) & 3); }

// ---------------------------------------------------------------------------
// Dense GEMM (3xTF32): out[co][l] = sum_k W[co][k] * X[k][l] + bias[co]
// CTA: 128 co x 128 l, k=512 in 16-slabs. 8 warps: wm=w>>2 (64co), wn=w&3 (32l)
// smem pitch 20 floats (80B, 16B-aligned) to break staging conflicts.
// ---------------------------------------------------------------------------
#define AP 20

__device__ __forceinline__ void gemm_body_tc(
    const float* __restrict__ X,     // [512][NL]
    const float* __restrict__ Wt,    // rows of 512, already offset to co0
    const float* __restrict__ bias,  // offset to co0
    float* __restrict__ out,         // offset to co0*NL
    int l0)
{
    __shared__ float Ah[128 * AP], Al[128 * AP], Bh[128 * AP], Bl[128 * AP];
    const int tid = threadIdx.x, lane = tid & 31, w = tid >> 5;
    const int wm = w >> 2, wn = w & 3;

    float acc[4][4][4];
#pragma unroll
    for (int i = 0; i < 4; i++)
#pragma unroll
        for (int j = 0; j < 4; j++)
#pragma unroll
            for (int k = 0; k < 4; k++) acc[i][j][k] = 0.f;

    for (int kt = 0; kt < 32; kt++) {
        // stage A = W tile [128 co][16 k], hi/lo
        {
            const int co = tid >> 1, half = tid & 1;
            const float* wp = Wt + (size_t)co * 512 + kt * 16 + half * 8;
            float4 t0 = *(const float4*)wp;
            float4 t1 = *(const float4*)(wp + 4);
            float v[8] = {t0.x, t0.y, t0.z, t0.w, t1.x, t1.y, t1.z, t1.w};
#pragma unroll
            for (int j = 0; j < 8; j++) {
                int k = half * 8 + j;
                int pos = kperm16(k);
                float hi = tfr(v[j]);
                Ah[co * AP + pos] = hi;
                Al[co * AP + pos] = tfr(v[j] - hi);
            }
        }
        // stage B = X tile [16 k][128 l] -> Bs[l][kperm], lane-skewed stores
        {
            const int kl = tid >> 4, lb = (tid & 15) * 8;
            const float* xp = X + (size_t)(kt * 16 + kl) * NL + l0 + lb;
            float4 t0 = *(const float4*)xp;
            float4 t1 = *(const float4*)(xp + 4);
            float v[8] = {t0.x, t0.y, t0.z, t0.w, t1.x, t1.y, t1.z, t1.w};
            const int posk = kperm16(kl);
#pragma unroll
            for (int jj = 0; jj < 8; jj++) {
                int j = (jj + lane) & 7;
                int l = lb + j;
                float hi = tfr(v[j]);
                Bh[l * AP + posk] = hi;
                Bl[l * AP + posk] = tfr(v[j] - hi);
            }
        }
        __syncthreads();

        float4 bhf[4], blf[4];
#pragma unroll
        for (int in = 0; in < 4; in++) {
            int col = wn * 32 + in * 8 + (lane >> 2);
            bhf[in] = *(const float4*)&Bh[col * AP + (lane & 3) * 4];
            blf[in] = *(const float4*)&Bl[col * AP + (lane & 3) * 4];
        }
#pragma unroll
        for (int im = 0; im < 4; im++) {
            int r = wm * 64 + im * 16 + (lane >> 2);
            float4 a0h = *(const float4*)&Ah[r * AP + (lane & 3) * 4];
            float4 a1h = *(const float4*)&Ah[(r + 8) * AP + (lane & 3) * 4];
            float4 a0l = *(const float4*)&Al[r * AP + (lane & 3) * 4];
            float4 a1l = *(const float4*)&Al[(r + 8) * AP + (lane & 3) * 4];
#pragma unroll
            for (int s = 0; s < 2; s++) {
                uint32_t ah0 = fu(s ? a0h.z : a0h.x), ah1 = fu(s ? a1h.z : a1h.x);
                uint32_t ah2 = fu(s ? a0h.w : a0h.y), ah3 = fu(s ? a1h.w : a1h.y);
                uint32_t al0 = fu(s ? a0l.z : a0l.x), al1 = fu(s ? a1l.z : a1l.x);
                uint32_t al2 = fu(s ? a0l.w : a0l.y), al3 = fu(s ? a1l.w : a1l.y);
#pragma unroll
                for (int in = 0; in < 4; in++)
                    mma8(acc[im][in], ah0, ah1, ah2, ah3,
                         fu(s ? bhf[in].z : bhf[in].x), fu(s ? bhf[in].w : bhf[in].y));
#pragma unroll
                for (int in = 0; in < 4; in++)
                    mma8(acc[im][in], ah0, ah1, ah2, ah3,
                         fu(s ? blf[in].z : blf[in].x), fu(s ? blf[in].w : blf[in].y));
#pragma unroll
                for (int in = 0; in < 4; in++)
                    mma8(acc[im][in], al0, al1, al2, al3,
                         fu(s ? bhf[in].z : bhf[in].x), fu(s ? bhf[in].w : bhf[in].y));
            }
        }
        __syncthreads();
    }

#pragma unroll
    for (int im = 0; im < 4; im++) {
        int row = wm * 64 + im * 16 + (lane >> 2);
        float b0 = bias[row], b1 = bias[row + 8];
#pragma unroll
        for (int in = 0; in < 4; in++) {
            int col = l0 + wn * 32 + in * 8 + (lane & 3) * 2;
            float2 lo = make_float2(acc[im][in][0] + b0, acc[im][in][1] + b0);
            float2 hi = make_float2(acc[im][in][2] + b1, acc[im][in][3] + b1);
            *(float2*)&out[(size_t)row * NL + col] = lo;
            *(float2*)&out[(size_t)(row + 8) * NL + col] = hi;
        }
    }
}

// grid: (16 l-tiles, 12 = which*4 + co_tile, 4 b)
__global__ void __launch_bounds__(256) proj_tc(
    const float* __restrict__ x,
    const float* __restrict__ gw, const float* __restrict__ gb,
    const float* __restrict__ tw, const float* __restrict__ tbb,
    const float* __restrict__ pw, const float* __restrict__ pb)
{
    const int which = blockIdx.y >> 2;
    const int co0 = (blockIdx.y & 3) * 128;
    const int b = blockIdx.z;
    const float* W = (which == 0 ? gw : which == 1 ? tw : pw);
    const float* bias = (which == 0 ? gb : which == 1 ? tbb : pb);
    gemm_body_tc(x + (size_t)b * NC * NL, W + (size_t)co0 * 512, bias + co0,
                 d_proj + ((size_t)which * NB + b) * NCI * NL + (size_t)co0 * NL,
                 blockIdx.x * 128);
}

// grid: (16, 4, 4)
__global__ void __launch_bounds__(256) gemm2_tc(
    const float* __restrict__ ww, const float* __restrict__ wb)
{
    const int co0 = blockIdx.y * 128;
    const int b = blockIdx.z;
    gemm_body_tc(d_y + (size_t)b * NCI * NL, ww + (size_t)co0 * 512, wb + co0,
                 d_wy + (size_t)b * NC * NL + (size_t)co0 * NL, blockIdx.x * 128);
}

// ---------------------------------------------------------------------------
// Attention: q-tile 128, k-tile 64, d=64, tf32 mma.sync, no online max.
// 8 warps: wm = w>>1 (32 q each), wn = w&1 (32 kk for QK / 32 d for PV).
// smem pitch 68 floats. Dynamic smem 105472 B, 2 CTAs/SM.
// ---------------------------------------------------------------------------
#define QP 68
#define AT_SMEM ((128 * QP + 64 * QP + 64 * QP + 128 * QP + 256) * 4)

__device__ __forceinline__ int posd64(int d) { return ((d >> 4) << 4) | kperm16(d & 15); }

__global__ void __launch_bounds__(256, 2) attn_tc()
{
    extern __shared__ float sm[];
    float* Qs = sm;                       // [128 q][QP]
    float* Ks = Qs + 128 * QP;            // [64 kk][QP]
    float* Vs = Ks + 64 * QP;             // [64 d][QP]  (kk-permuted cols)
    float* Ps = Vs + 64 * QP;             // [128 q][QP] (kk-permuted cols)
    float* rsum = Ps + 128 * QP;          // [2][128]

    const int tid = threadIdx.x, lane = tid & 31, w = tid >> 5;
    const int wm = w >> 1, wn = w & 1;
    const int q0 = blockIdx.x * 128;
    const int b = blockIdx.y >> 3, h = blockIdx.y & 7;

    const float* theta = d_proj + ((size_t)(1 * NB + b) * NCI + h * ND) * NL;
    const float* phi   = d_proj + ((size_t)(2 * NB + b) * NCI + h * ND) * NL;
    const float* gx    = d_proj + ((size_t)(0 * NB + b) * NCI + h * ND) * NL;

    // stage Q: [q][d_perm], scaled by 1/8
    {
        const int d = tid >> 2, qoff = tid & 3;
        const int pd = posd64(d);
        const float* tp = theta + (size_t)d * NL + q0;
#pragma unroll 8
        for (int j = 0; j < 32; j++) {
            int q = qoff + 4 * j;
            Qs[q * QP + pd] = tfr(tp[q] * 0.125f);
        }
    }

    float acc_o[2][4][4];
#pragma unroll
    for (int i = 0; i < 2; i++)
#pragma unroll
        for (int j = 0; j < 4; j++)
#pragma unroll
            for (int k = 0; k < 4; k++) acc_o[i][j][k] = 0.f;
    float psum[2][2] = {{0.f, 0.f}, {0.f, 0.f}};

    for (int it = 0; it < 32; it++) {
        const int kk0 = it * 64;
        __syncthreads();  // prior-iter K/V/P readers done (covers Q staging on it 0)

        // stage K: [kk][d_perm]
        {
            const int d = tid >> 2, koff = tid & 3;
            const int pd = posd64(d);
            const float* pp = phi + (size_t)d * NL + kk0;
#pragma unroll 4
            for (int j = 0; j < 16; j++) {
                int kk = koff + 4 * j;
                Ks[kk * QP + pd] = tfr(pp[kk]);
            }
        }
        // stage V: [d][kk_perm]
        {
            const int d = tid >> 2, kb = (tid & 3) * 16;
            const float* gp = gx + (size_t)d * NL + kk0 + kb;
#pragma unroll
            for (int c = 0; c < 4; c++) {
                float4 v = *(const float4*)(gp + c * 4);
                float vv[4] = {v.x, v.y, v.z, v.w};
#pragma unroll
                for (int j = 0; j < 4; j++) {
                    int kk = kb + c * 4 + j;
                    Vs[d * QP + posd64(kk)] = tfr(vv[j]);
                }
            }
        }
        __syncthreads();

        // S = Q K^T  (warp tile 32q x 32kk)
        float s_acc[2][4][4];
#pragma unroll
        for (int i = 0; i < 2; i++)
#pragma unroll
            for (int j = 0; j < 4; j++)
#pragma unroll
                for (int k = 0; k < 4; k++) s_acc[i][j][k] = 0.f;

#pragma unroll
        for (int slab = 0; slab < 4; slab++) {
            float4 qlo[2], qhi[2], kf[4];
#pragma unroll
            for (int im = 0; im < 2; im++) {
                int r = wm * 32 + im * 16 + (lane >> 2);
                qlo[im] = *(const float4*)&Qs[r * QP + slab * 16 + (lane & 3) * 4];
                qhi[im] = *(const float4*)&Qs[(r + 8) * QP + slab * 16 + (lane & 3) * 4];
            }
#pragma unroll
            for (int in = 0; in < 4; in++) {
                int c = wn * 32 + in * 8 + (lane >> 2);
                kf[in] = *(const float4*)&Ks[c * QP + slab * 16 + (lane & 3) * 4];
            }
#pragma unroll
            for (int s = 0; s < 2; s++)
#pragma unroll
                for (int im = 0; im < 2; im++) {
                    uint32_t a0 = fu(s ? qlo[im].z : qlo[im].x), a1 = fu(s ? qhi[im].z : qhi[im].x);
                    uint32_t a2 = fu(s ? qlo[im].w : qlo[im].y), a3 = fu(s ? qhi[im].w : qhi[im].y);
#pragma unroll
                    for (int in = 0; in < 4; in++)
                        mma8(s_acc[im][in], a0, a1, a2, a3,
                             fu(s ? kf[in].z : kf[in].x), fu(s ? kf[in].w : kf[in].y));
                }
        }

        // exp + P store + partial row sums
#pragma unroll
        for (int im = 0; im < 2; im++) {
            int r = wm * 32 + im * 16 + (lane >> 2);
#pragma unroll
            for (int in = 0; in < 4; in++) {
                int kk = wn * 32 + in * 8 + (lane & 3) * 2;
                float p0 = tfr(__expf(s_acc[im][in][0]));
                float p1 = tfr(__expf(s_acc[im][in][1]));
                float p2 = tfr(__expf(s_acc[im][in][2]));
                float p3 = tfr(__expf(s_acc[im][in][3]));
                psum[im][0] += p0 + p1;
                psum[im][1] += p2 + p3;
                Ps[r * QP + posd64(kk)] = p0;
                Ps[r * QP + posd64(kk + 1)] = p1;
                Ps[(r + 8) * QP + posd64(kk)] = p2;
                Ps[(r + 8) * QP + posd64(kk + 1)] = p3;
            }
        }
        __syncthreads();

        // O += P V^T  (warp tile 32q x 32d, inner kk=64)
#pragma unroll
        for (int slab = 0; slab < 4; slab++) {
            float4 plo[2], phi_[2], vf[4];
#pragma unroll
            for (int im = 0; im < 2; im++) {
                int r = wm * 32 + im * 16 + (lane >> 2);
                plo[im] = *(const float4*)&Ps[r * QP + slab * 16 + (lane & 3) * 4];
                phi_[im] = *(const float4*)&Ps[(r + 8) * QP + slab * 16 + (lane & 3) * 4];
            }
#pragma unroll
            for (int in = 0; in < 4; in++) {
                int c = wn * 32 + in * 8 + (lane >> 2);
                vf[in] = *(const float4*)&Vs[c * QP + slab * 16 + (lane & 3) * 4];
            }
#pragma unroll
            for (int s = 0; s < 2; s++)
#pragma unroll
                for (int im = 0; im < 2; im++) {
                    uint32_t a0 = fu(s ? plo[im].z : plo[im].x), a1 = fu(s ? phi_[im].z : phi_[im].x);
                    uint32_t a2 = fu(s ? plo[im].w : plo[im].y), a3 = fu(s ? phi_[im].w : phi_[im].y);
#pragma unroll
                    for (int in = 0; in < 4; in++)
                        mma8(acc_o[im][in], a0, a1, a2, a3,
                             fu(s ? vf[in].z : vf[in].x), fu(s ? vf[in].w : vf[in].y));
                }
        }
    }

    // reduce row sums across quad lanes, then across the 2 n-warps via smem
#pragma unroll
    for (int im = 0; im < 2; im++)
#pragma unroll
        for (int hl = 0; hl < 2; hl++) {
            float v = psum[im][hl];
            v += __shfl_xor_sync(0xffffffffu, v, 1);
            v += __shfl_xor_sync(0xffffffffu, v, 2);
            if ((lane & 3) == 0)
                rsum[wn * 128 + wm * 32 + im * 16 + (lane >> 2) + hl * 8] = v;
        }
    __syncthreads();

    float* yout = d_y + ((size_t)b * NCI + h * ND) * NL;
#pragma unroll
    for (int im = 0; im < 2; im++) {
        int r = wm * 32 + im * 16 + (lane >> 2);
        float inv0 = 1.0f / (rsum[r] + rsum[128 + r]);
        float inv1 = 1.0f / (rsum[r + 8] + rsum[128 + r + 8]);
#pragma unroll
        for (int in = 0; in < 4; in++) {
            int d = wn * 32 + in * 8 + (lane & 3) * 2;
            yout[(size_t)d * NL + q0 + r] = acc_o[im][in][0] * inv0;
            yout[(size_t)(d + 1) * NL + q0 + r] = acc_o[im][in][1] * inv0;
            yout[(size_t)d * NL + q0 + r + 8] = acc_o[im][in][2] * inv1;
            yout[(size_t)(d + 1) * NL + q0 + r + 8] = acc_o[im][in][3] * inv1;
        }
    }
}

// ---------------------------------------------------------------------------
// BatchNorm
// ---------------------------------------------------------------------------
__global__ void __launch_bounds__(256) bn_stats_kernel()
{
    const int c = blockIdx.x;
    const int tid = threadIdx.x;
    double s0 = 0, s1 = 0, s2 = 0, s3 = 0, q0 = 0, q1 = 0, q2 = 0, q3 = 0;
#pragma unroll
    for (int r = 0; r < 8; r++) {
        int f = tid + 256 * r;
        int b = f >> 9, l4 = f & 511;
        float4 v = *reinterpret_cast<const float4*>(&d_wy[((size_t)b * NC + c) * NL + l4 * 4]);
        s0 += v.x; s1 += v.y; s2 += v.z; s3 += v.w;
        q0 += (double)v.x * v.x; q1 += (double)v.y * v.y;
        q2 += (double)v.z * v.z; q3 += (double)v.w * v.w;
    }
    __shared__ double sh[256], sh2[256];
    sh[tid] = (s0 + s1) + (s2 + s3);
    sh2[tid] = (q0 + q1) + (q2 + q3);
    __syncthreads();
    for (int off = 128; off > 0; off >>= 1) {
        if (tid < off) { sh[tid] += sh[tid + off]; sh2[tid] += sh2[tid + off]; }
        __syncthreads();
    }
    if (tid == 0) {
        double mean = sh[0] / (double)(NB * NL);
        double var = sh2[0] / (double)(NB * NL) - mean * mean;
        d_bnmean[c] = (float)mean;
        d_bnrstd[c] = (float)(1.0 / sqrt(var + 1e-5));
    }
}

__global__ void __launch_bounds__(256) bn_apply_kernel(
    const float* __restrict__ gamma, const float* __restrict__ beta,
    float* __restrict__ out)
{
    int i4 = blockIdx.x * 256 + threadIdx.x;
    int c = (i4 >> 9) & (NC - 1);
    float4 v = reinterpret_cast<const float4*>(d_wy)[i4];
    float m = d_bnmean[c], rs = d_bnrstd[c] * gamma[c], bt = beta[c];
    float4 o = make_float4((v.x - m) * rs + bt, (v.y - m) * rs + bt,
                           (v.z - m) * rs + bt, (v.w - m) * rs + bt);
    reinterpret_cast<float4*>(out)[i4] = o;
}

// ---------------------------------------------------------------------------
extern "C" void kernel_launch(void* const* d_in, const int* in_sizes, int n_in,
                              void* d_out, int out_size)
{
    const float* x     = (const float*)d_in[0];
    const float* gw    = (const float*)d_in[1];
    const float* gb    = (const float*)d_in[2];
    const float* tw    = (const float*)d_in[3];
    const float* tb    = (const float*)d_in[4];
    const float* pw    = (const float*)d_in[5];
    const float* pb    = (const float*)d_in[6];
    const float* ww    = (const float*)d_in[7];
    const float* wb    = (const float*)d_in[8];
    const float* gamma = (const float*)d_in[9];
    const float* beta  = (const float*)d_in[10];
    float* out = (float*)d_out;

    cudaFuncSetAttribute(attn_tc, cudaFuncAttributeMaxDynamicSharedMemorySize, AT_SMEM);

    proj_tc<<<dim3(16, 12, 4), 256>>>(x, gw, gb, tw, tb, pw, pb);
    attn_tc<<<dim3(16, 32), 256, AT_SMEM>>>();
    gemm2_tc<<<dim3(16, 4, 4), 256>>>(ww, wb);
    bn_stats_kernel<<<NC, 256>>>();
    bn_apply_kernel<<<(NB * NC * NL) / 1024, 256>>>(gamma, beta, out);
}

// round 5
// speedup vs baseline: 3.4292x; 1.7117x over previous
#include <cuda_runtime.h>
#include <cstdint>
#include <math.h>

#define NB 4
#define NC 512
#define NL 2048
#define NCI 512
#define NH 8
#define ND 64

__device__ __align__(256) float d_proj[3 * NB * NCI * NL]; // [which][b][ci][l]; 0=g,1=theta,2=phi
__device__ __align__(256) float d_y[NB * NCI * NL];
__device__ __align__(256) float d_wy[NB * NC * NL];
__device__ __align__(256) float d_wprep[4 * 512 * 512];    // [m][co][k-perm] tf32-rounded
__device__ __align__(256) float d_xprep[NB * NL * 512];    // [b][l][ci-perm]
__device__ __align__(256) float d_yprep[NB * NL * 512];    // [b][l][ci-perm]
__device__ float d_bnmean[NC];
__device__ float d_bnrstd[NC];

// ---------------- helpers ----------------
__device__ __forceinline__ float tfr(float x) {
    uint32_t u;
    asm("cvt.rna.tf32.f32 %0, %1;" : "=r"(u) : "f"(x));
    return __uint_as_float(u);
}
__device__ __forceinline__ uint32_t fu(float x) { return __float_as_uint(x); }

__device__ __forceinline__ void mma8(float* c,
                                     uint32_t a0, uint32_t a1, uint32_t a2, uint32_t a3,
                                     uint32_t b0, uint32_t b1) {
    asm("mma.sync.aligned.m16n8k8.row.col.f32.tf32.tf32.f32 "
        "{%0,%1,%2,%3},{%4,%5,%6,%7},{%8,%9},{%0,%1,%2,%3};"
        : "+f"(c[0]), "+f"(c[1]), "+f"(c[2]), "+f"(c[3])
        : "r"(a0), "r"(a1), "r"(a2), "r"(a3), "r"(b0), "r"(b1));
}

__device__ __forceinline__ uint32_t smem_u32(const void* p) {
    uint32_t a;
    asm("{ .reg .u64 t; cvta.to.shared.u64 t, %1; cvt.u32.u64 %0, t; }" : "=r"(a) : "l"(p));
    return a;
}
__device__ __forceinline__ void cpa16(uint32_t dst, const void* src) {
    asm volatile("cp.async.ca.shared.global [%0], [%1], 16;" :: "r"(dst), "l"(src));
}
#define CP_COMMIT() asm volatile("cp.async.commit_group;" ::: "memory")
#define CP_WAIT2()  asm volatile("cp.async.wait_group 2;" ::: "memory")
#define CP_WAIT0()  asm volatile("cp.async.wait_group 0;" ::: "memory")

// pos p of 16-slab holds logical k with kperm16(k)=p; float4 at 4t -> k = t,t+4,t+8,t+12
__device__ __forceinline__ int kperm16(int k) { return ((k & 3) << 2) | ((k >> 2) & 3); }
__device__ __forceinline__ int cip512(int k) { return (k & ~15) | kperm16(k & 15); }

// ---------------------------------------------------------------------------
// Prep kernels: tf32-round + permute (and transpose for X/Y planes)
// ---------------------------------------------------------------------------
// 4 matrices [512][512] -> d_wprep[m][co][k-perm]; grid 1024 x 256 thr
__global__ void __launch_bounds__(256) prep_w(
    const float* __restrict__ gw, const float* __restrict__ tw,
    const float* __restrict__ pw, const float* __restrict__ ww)
{
    int gid = blockIdx.x * 256 + threadIdx.x;          // per float4
    int m = gid >> 16;                                 // 512*512/4 = 65536 per matrix
    int rem = gid & 65535;
    int co = rem >> 7, k4 = (rem & 127) * 4;
    const float* src = (m == 0) ? gw : (m == 1) ? tw : (m == 2) ? pw : ww;
    float4 v = *(const float4*)(src + (size_t)co * 512 + k4);
    float vv[4] = {v.x, v.y, v.z, v.w};
    float* dst = d_wprep + ((size_t)m * 512 + co) * 512;
#pragma unroll
    for (int j = 0; j < 4; j++) dst[cip512(k4 + j)] = tfr(vv[j]);
}

// transpose [b][512 ci][2048 l] -> [b][l][ci-perm]; grid (32 lt, 8 cit, 4 b)
__device__ __forceinline__ void prep_T(const float* __restrict__ in, float* __restrict__ out)
{
    __shared__ float sm[64][65];
    const int tid = threadIdx.x;
    const int l0 = blockIdx.x * 64, ci0 = blockIdx.y * 64, b = blockIdx.z;
    const float* src = in + (size_t)b * 512 * NL;
    float* dst = out + (size_t)b * NL * 512;
#pragma unroll
    for (int it = 0; it < 4; it++) {
        int ci = (tid >> 4) + 16 * it;
        int ll = (tid & 15) * 4;
        float4 v = *(const float4*)(src + (size_t)(ci0 + ci) * NL + l0 + ll);
        sm[ci][ll] = v.x; sm[ci][ll + 1] = v.y; sm[ci][ll + 2] = v.z; sm[ci][ll + 3] = v.w;
    }
    __syncthreads();
#pragma unroll
    for (int it = 0; it < 4; it++) {
        int ll = (tid >> 4) + 16 * it;
        int cb = (tid & 15) * 4;
#pragma unroll
        for (int j = 0; j < 4; j++)
            dst[(size_t)(l0 + ll) * 512 + cip512(ci0 + cb + j)] = tfr(sm[cb + j][ll]);
    }
}
__global__ void __launch_bounds__(256) prep_x(const float* __restrict__ x) { prep_T(x, d_xprep); }
__global__ void __launch_bounds__(256) prep_y() { prep_T(d_y, d_yprep); }

// ---------------------------------------------------------------------------
// Dense GEMM, 1x tf32, cp.async 4-deep pipeline.
// out[co][l] = sum_k W[co][k] * X[k][l] + bias[co]; CTA 128co x 128l, k=512.
// smem: sA[4 buf][128 co][16], sB[4 buf][128 l][16] = 64KB dynamic.
// 8 warps: wm=w>>2 (64 co), wn=w&3 (32 l); per-warp tile 64x32.
// ---------------------------------------------------------------------------
#define DS_SMEM 65536

__device__ __forceinline__ void gemm_body_tc(
    const float* __restrict__ Wp,    // wprep rows, offset to co0 (pitch 512)
    const float* __restrict__ Xp,    // xprep/yprep [l][512-perm]
    const float* __restrict__ bias,  // offset to co0
    float* __restrict__ out,         // offset to co0*NL
    int l0)
{
    extern __shared__ float ds[];
    const uint32_t sbA = smem_u32(ds);
    const uint32_t sbB = sbA + 32768;
    const int tid = threadIdx.x, lane = tid & 31, w = tid >> 5;
    const int wm = w >> 2, wn = w & 3;
    const int row2 = tid >> 2, c4 = (tid & 3) * 16;     // chunk mapping r=0
    const char* srcWb = (const char*)Wp;
    const char* srcXb = (const char*)(Xp + (size_t)l0 * 512);

    float acc[4][4][4];
#pragma unroll
    for (int i = 0; i < 4; i++)
#pragma unroll
        for (int j = 0; j < 4; j++)
#pragma unroll
            for (int k = 0; k < 4; k++) acc[i][j][k] = 0.f;

#define ISSUE_SLAB(kt) do { \
    int bs_ = (kt) & 3; \
    uint32_t da_ = sbA + bs_ * 8192, db_ = sbB + bs_ * 8192; \
    cpa16(da_ + row2 * 64 + c4, srcWb + (size_t)row2 * 2048 + (kt) * 64 + c4); \
    cpa16(da_ + (row2 + 64) * 64 + c4, srcWb + (size_t)(row2 + 64) * 2048 + (kt) * 64 + c4); \
    cpa16(db_ + row2 * 64 + c4, srcXb + (size_t)row2 * 2048 + (kt) * 64 + c4); \
    cpa16(db_ + (row2 + 64) * 64 + c4, srcXb + (size_t)(row2 + 64) * 2048 + (kt) * 64 + c4); \
    CP_COMMIT(); \
} while (0)

    ISSUE_SLAB(0); ISSUE_SLAB(1); ISSUE_SLAB(2);

    for (int kt = 0; kt < 32; kt++) {
        if (kt < 29) CP_WAIT2(); else CP_WAIT0();
        __syncthreads();
        if (kt + 3 < 32) ISSUE_SLAB(kt + 3);

        const int bs = kt & 3;
        const float* bufA = ds + bs * 2048;
        const float* bufB = ds + 8192 + bs * 2048;

        float4 bf[4];
#pragma unroll
        for (int in = 0; in < 4; in++) {
            int n = wn * 32 + in * 8 + (lane >> 2);
            bf[in] = *(const float4*)(bufB + n * 16 + (lane & 3) * 4);
        }
#pragma unroll
        for (int im = 0; im < 4; im++) {
            int r = wm * 64 + im * 16 + (lane >> 2);
            float4 a0 = *(const float4*)(bufA + r * 16 + (lane & 3) * 4);
            float4 a1 = *(const float4*)(bufA + (r + 8) * 16 + (lane & 3) * 4);
#pragma unroll
            for (int s = 0; s < 2; s++) {
                uint32_t r0 = fu(s ? a0.z : a0.x), r1 = fu(s ? a1.z : a1.x);
                uint32_t r2 = fu(s ? a0.w : a0.y), r3 = fu(s ? a1.w : a1.y);
#pragma unroll
                for (int in = 0; in < 4; in++)
                    mma8(acc[im][in], r0, r1, r2, r3,
                         fu(s ? bf[in].z : bf[in].x), fu(s ? bf[in].w : bf[in].y));
            }
        }
        __syncthreads();
    }
#undef ISSUE_SLAB

#pragma unroll
    for (int im = 0; im < 4; im++) {
        int row = wm * 64 + im * 16 + (lane >> 2);
        float b0 = bias[row], b1 = bias[row + 8];
#pragma unroll
        for (int in = 0; in < 4; in++) {
            int col = l0 + wn * 32 + in * 8 + (lane & 3) * 2;
            float2 lo = make_float2(acc[im][in][0] + b0, acc[im][in][1] + b0);
            float2 hi = make_float2(acc[im][in][2] + b1, acc[im][in][3] + b1);
            *(float2*)&out[(size_t)row * NL + col] = lo;
            *(float2*)&out[(size_t)(row + 8) * NL + col] = hi;
        }
    }
}

// grid: (16 l-tiles, 12 = which*4 + co_tile, 4 b)
__global__ void __launch_bounds__(256) proj_tc(
    const float* __restrict__ gb, const float* __restrict__ tbb, const float* __restrict__ pb)
{
    const int which = blockIdx.y >> 2;
    const int co0 = (blockIdx.y & 3) * 128;
    const int b = blockIdx.z;
    const float* bias = (which == 0 ? gb : which == 1 ? tbb : pb);
    gemm_body_tc(d_wprep + ((size_t)which * 512 + co0) * 512,
                 d_xprep + (size_t)b * NL * 512,
                 bias + co0,
                 d_proj + ((size_t)which * NB + b) * NCI * NL + (size_t)co0 * NL,
                 blockIdx.x * 128);
}

// grid: (16, 4, 4)
__global__ void __launch_bounds__(256) gemm2_tc(const float* __restrict__ wb)
{
    const int co0 = blockIdx.y * 128;
    const int b = blockIdx.z;
    gemm_body_tc(d_wprep + ((size_t)3 * 512 + co0) * 512,
                 d_yprep + (size_t)b * NL * 512,
                 wb + co0,
                 d_wy + (size_t)b * NC * NL + (size_t)co0 * NL, blockIdx.x * 128);
}

// ---------------------------------------------------------------------------
// Attention: UNCHANGED from round 4 (passing, rel_err-validated).
// ---------------------------------------------------------------------------
#define QP 68
#define AT_SMEM ((128 * QP + 64 * QP + 64 * QP + 128 * QP + 256) * 4)

__device__ __forceinline__ int posd64(int d) { return ((d >> 4) << 4) | kperm16(d & 15); }

__global__ void __launch_bounds__(256, 2) attn_tc()
{
    extern __shared__ float sm[];
    float* Qs = sm;
    float* Ks = Qs + 128 * QP;
    float* Vs = Ks + 64 * QP;
    float* Ps = Vs + 64 * QP;
    float* rsum = Ps + 128 * QP;

    const int tid = threadIdx.x, lane = tid & 31, w = tid >> 5;
    const int wm = w >> 1, wn = w & 1;
    const int q0 = blockIdx.x * 128;
    const int b = blockIdx.y >> 3, h = blockIdx.y & 7;

    const float* theta = d_proj + ((size_t)(1 * NB + b) * NCI + h * ND) * NL;
    const float* phi   = d_proj + ((size_t)(2 * NB + b) * NCI + h * ND) * NL;
    const float* gx    = d_proj + ((size_t)(0 * NB + b) * NCI + h * ND) * NL;

    {
        const int d = tid >> 2, qoff = tid & 3;
        const int pd = posd64(d);
        const float* tp = theta + (size_t)d * NL + q0;
#pragma unroll 8
        for (int j = 0; j < 32; j++) {
            int q = qoff + 4 * j;
            Qs[q * QP + pd] = tfr(tp[q] * 0.125f);
        }
    }

    float acc_o[2][4][4];
#pragma unroll
    for (int i = 0; i < 2; i++)
#pragma unroll
        for (int j = 0; j < 4; j++)
#pragma unroll
            for (int k = 0; k < 4; k++) acc_o[i][j][k] = 0.f;
    float psum[2][2] = {{0.f, 0.f}, {0.f, 0.f}};

    for (int it = 0; it < 32; it++) {
        const int kk0 = it * 64;
        __syncthreads();

        {
            const int d = tid >> 2, koff = tid & 3;
            const int pd = posd64(d);
            const float* pp = phi + (size_t)d * NL + kk0;
#pragma unroll 4
            for (int j = 0; j < 16; j++) {
                int kk = koff + 4 * j;
                Ks[kk * QP + pd] = tfr(pp[kk]);
            }
        }
        {
            const int d = tid >> 2, kb = (tid & 3) * 16;
            const float* gp = gx + (size_t)d * NL + kk0 + kb;
#pragma unroll
            for (int c = 0; c < 4; c++) {
                float4 v = *(const float4*)(gp + c * 4);
                float vv[4] = {v.x, v.y, v.z, v.w};
#pragma unroll
                for (int j = 0; j < 4; j++) {
                    int kk = kb + c * 4 + j;
                    Vs[d * QP + posd64(kk)] = tfr(vv[j]);
                }
            }
        }
        __syncthreads();

        float s_acc[2][4][4];
#pragma unroll
        for (int i = 0; i < 2; i++)
#pragma unroll
            for (int j = 0; j < 4; j++)
#pragma unroll
                for (int k = 0; k < 4; k++) s_acc[i][j][k] = 0.f;

#pragma unroll
        for (int slab = 0; slab < 4; slab++) {
            float4 qlo[2], qhi[2], kf[4];
#pragma unroll
            for (int im = 0; im < 2; im++) {
                int r = wm * 32 + im * 16 + (lane >> 2);
                qlo[im] = *(const float4*)&Qs[r * QP + slab * 16 + (lane & 3) * 4];
                qhi[im] = *(const float4*)&Qs[(r + 8) * QP + slab * 16 + (lane & 3) * 4];
            }
#pragma unroll
            for (int in = 0; in < 4; in++) {
                int c = wn * 32 + in * 8 + (lane >> 2);
                kf[in] = *(const float4*)&Ks[c * QP + slab * 16 + (lane & 3) * 4];
            }
#pragma unroll
            for (int s = 0; s < 2; s++)
#pragma unroll
                for (int im = 0; im < 2; im++) {
                    uint32_t a0 = fu(s ? qlo[im].z : qlo[im].x), a1 = fu(s ? qhi[im].z : qhi[im].x);
                    uint32_t a2 = fu(s ? qlo[im].w : qlo[im].y), a3 = fu(s ? qhi[im].w : qhi[im].y);
#pragma unroll
                    for (int in = 0; in < 4; in++)
                        mma8(s_acc[im][in], a0, a1, a2, a3,
                             fu(s ? kf[in].z : kf[in].x), fu(s ? kf[in].w : kf[in].y));
                }
        }

#pragma unroll
        for (int im = 0; im < 2; im++) {
            int r = wm * 32 + im * 16 + (lane >> 2);
#pragma unroll
            for (int in = 0; in < 4; in++) {
                int kk = wn * 32 + in * 8 + (lane & 3) * 2;
                float p0 = tfr(__expf(s_acc[im][in][0]));
                float p1 = tfr(__expf(s_acc[im][in][1]));
                float p2 = tfr(__expf(s_acc[im][in][2]));
                float p3 = tfr(__expf(s_acc[im][in][3]));
                psum[im][0] += p0 + p1;
                psum[im][1] += p2 + p3;
                Ps[r * QP + posd64(kk)] = p0;
                Ps[r * QP + posd64(kk + 1)] = p1;
                Ps[(r + 8) * QP + posd64(kk)] = p2;
                Ps[(r + 8) * QP + posd64(kk + 1)] = p3;
            }
        }
        __syncthreads();

#pragma unroll
        for (int slab = 0; slab < 4; slab++) {
            float4 plo[2], phi_[2], vf[4];
#pragma unroll
            for (int im = 0; im < 2; im++) {
                int r = wm * 32 + im * 16 + (lane >> 2);
                plo[im] = *(const float4*)&Ps[r * QP + slab * 16 + (lane & 3) * 4];
                phi_[im] = *(const float4*)&Ps[(r + 8) * QP + slab * 16 + (lane & 3) * 4];
            }
#pragma unroll
            for (int in = 0; in < 4; in++) {
                int c = wn * 32 + in * 8 + (lane >> 2);
                vf[in] = *(const float4*)&Vs[c * QP + slab * 16 + (lane & 3) * 4];
            }
#pragma unroll
            for (int s = 0; s < 2; s++)
#pragma unroll
                for (int im = 0; im < 2; im++) {
                    uint32_t a0 = fu(s ? plo[im].z : plo[im].x), a1 = fu(s ? phi_[im].z : phi_[im].x);
                    uint32_t a2 = fu(s ? plo[im].w : plo[im].y), a3 = fu(s ? phi_[im].w : phi_[im].y);
#pragma unroll
                    for (int in = 0; in < 4; in++)
                        mma8(acc_o[im][in], a0, a1, a2, a3,
                             fu(s ? vf[in].z : vf[in].x), fu(s ? vf[in].w : vf[in].y));
                }
        }
    }

#pragma unroll
    for (int im = 0; im < 2; im++)
#pragma unroll
        for (int hl = 0; hl < 2; hl++) {
            float v = psum[im][hl];
            v += __shfl_xor_sync(0xffffffffu, v, 1);
            v += __shfl_xor_sync(0xffffffffu, v, 2);
            if ((lane & 3) == 0)
                rsum[wn * 128 + wm * 32 + im * 16 + (lane >> 2) + hl * 8] = v;
        }
    __syncthreads();

    float* yout = d_y + ((size_t)b * NCI + h * ND) * NL;
#pragma unroll
    for (int im = 0; im < 2; im++) {
        int r = wm * 32 + im * 16 + (lane >> 2);
        float inv0 = 1.0f / (rsum[r] + rsum[128 + r]);
        float inv1 = 1.0f / (rsum[r + 8] + rsum[128 + r + 8]);
#pragma unroll
        for (int in = 0; in < 4; in++) {
            int d = wn * 32 + in * 8 + (lane & 3) * 2;
            yout[(size_t)d * NL + q0 + r] = acc_o[im][in][0] * inv0;
            yout[(size_t)(d + 1) * NL + q0 + r] = acc_o[im][in][1] * inv0;
            yout[(size_t)d * NL + q0 + r + 8] = acc_o[im][in][2] * inv1;
            yout[(size_t)(d + 1) * NL + q0 + r + 8] = acc_o[im][in][3] * inv1;
        }
    }
}

// ---------------------------------------------------------------------------
// BatchNorm (fp32 stats — fp64 ALU was the round-4 bottleneck)
// ---------------------------------------------------------------------------
__global__ void __launch_bounds__(256) bn_stats_kernel()
{
    const int c = blockIdx.x;
    const int tid = threadIdx.x;
    float s0 = 0, s1 = 0, s2 = 0, s3 = 0, q0 = 0, q1 = 0, q2 = 0, q3 = 0;
#pragma unroll
    for (int r = 0; r < 8; r++) {
        int f = tid + 256 * r;
        int b = f >> 9, l4 = f & 511;
        float4 v = *reinterpret_cast<const float4*>(&d_wy[((size_t)b * NC + c) * NL + l4 * 4]);
        s0 += v.x; s1 += v.y; s2 += v.z; s3 += v.w;
        q0 = fmaf(v.x, v.x, q0); q1 = fmaf(v.y, v.y, q1);
        q2 = fmaf(v.z, v.z, q2); q3 = fmaf(v.w, v.w, q3);
    }
    __shared__ float sh[256], sh2[256];
    sh[tid] = (s0 + s1) + (s2 + s3);
    sh2[tid] = (q0 + q1) + (q2 + q3);
    __syncthreads();
    for (int off = 128; off > 0; off >>= 1) {
        if (tid < off) { sh[tid] += sh[tid + off]; sh2[tid] += sh2[tid + off]; }
        __syncthreads();
    }
    if (tid == 0) {
        float mean = sh[0] * (1.0f / (NB * NL));
        float var = sh2[0] * (1.0f / (NB * NL)) - mean * mean;
        d_bnmean[c] = mean;
        d_bnrstd[c] = rsqrtf(var + 1e-5f);
    }
}

__global__ void __launch_bounds__(256) bn_apply_kernel(
    const float* __restrict__ gamma, const float* __restrict__ beta,
    float* __restrict__ out)
{
    int i4 = blockIdx.x * 256 + threadIdx.x;
    int c = (i4 >> 9) & (NC - 1);
    float4 v = reinterpret_cast<const float4*>(d_wy)[i4];
    float m = d_bnmean[c], rs = d_bnrstd[c] * gamma[c], bt = beta[c];
    float4 o = make_float4((v.x - m) * rs + bt, (v.y - m) * rs + bt,
                           (v.z - m) * rs + bt, (v.w - m) * rs + bt);
    reinterpret_cast<float4*>(out)[i4] = o;
}

// ---------------------------------------------------------------------------
extern "C" void kernel_launch(void* const* d_in, const int* in_sizes, int n_in,
                              void* d_out, int out_size)
{
    const float* x     = (const float*)d_in[0];
    const float* gw    = (const float*)d_in[1];
    const float* gb    = (const float*)d_in[2];
    const float* tw    = (const float*)d_in[3];
    const float* tb    = (const float*)d_in[4];
    const float* pw    = (const float*)d_in[5];
    const float* pb    = (const float*)d_in[6];
    const float* ww    = (const float*)d_in[7];
    const float* wb    = (const float*)d_in[8];
    const float* gamma = (const float*)d_in[9];
    const float* beta  = (const float*)d_in[10];
    float* out = (float*)d_out;

    cudaFuncSetAttribute(proj_tc, cudaFuncAttributeMaxDynamicSharedMemorySize, DS_SMEM);
    cudaFuncSetAttribute(gemm2_tc, cudaFuncAttributeMaxDynamicSharedMemorySize, DS_SMEM);
    cudaFuncSetAttribute(attn_tc, cudaFuncAttributeMaxDynamicSharedMemorySize, AT_SMEM);

    prep_w<<<1024, 256>>>(gw, tw, pw, ww);
    prep_x<<<dim3(32, 8, 4), 256>>>(x);
    proj_tc<<<dim3(16, 12, 4), 256, DS_SMEM>>>(gb, tb, pb);
    attn_tc<<<dim3(16, 32), 256, AT_SMEM>>>();
    prep_y<<<dim3(32, 8, 4), 256>>>();
    gemm2_tc<<<dim3(16, 4, 4), 256, DS_SMEM>>>(wb);
    bn_stats_kernel<<<NC, 256>>>();
    bn_apply_kernel<<<(NB * NC * NL) / 1024, 256>>>(gamma, beta, out);
}

// round 6
// speedup vs baseline: 4.1464x; 1.2091x over previous
#include <cuda_runtime.h>
#include <cstdint>
#include <math.h>

#define NB 4
#define NC 512
#define NL 2048
#define NCI 512
#define NH 8
#define ND 64

__device__ __align__(256) float d_proj[3 * NB * NCI * NL]; // [which][b][ci][l]; 0=g,1=theta,2=phi
__device__ __align__(256) float d_y[NB * NCI * NL];
__device__ __align__(256) float d_wy[NB * NC * NL];
__device__ __align__(256) float d_wprep[4 * 512 * 512];    // [m][co][k-perm] tf32-rounded
__device__ __align__(256) float d_xprep[NB * NL * 512];    // [b][l][ci-perm]
__device__ __align__(256) float d_yprep[NB * NL * 512];    // [b][l][ci-perm]
__device__ float d_bnmean[NC];
__device__ float d_bnrstd[NC];

// ---------------- helpers ----------------
__device__ __forceinline__ float tfr(float x) {
    uint32_t u;
    asm("cvt.rna.tf32.f32 %0, %1;" : "=r"(u) : "f"(x));
    return __uint_as_float(u);
}
__device__ __forceinline__ uint32_t fu(float x) { return __float_as_uint(x); }

__device__ __forceinline__ void mma8(float* c,
                                     uint32_t a0, uint32_t a1, uint32_t a2, uint32_t a3,
                                     uint32_t b0, uint32_t b1) {
    asm("mma.sync.aligned.m16n8k8.row.col.f32.tf32.tf32.f32 "
        "{%0,%1,%2,%3},{%4,%5,%6,%7},{%8,%9},{%0,%1,%2,%3};"
        : "+f"(c[0]), "+f"(c[1]), "+f"(c[2]), "+f"(c[3])
        : "r"(a0), "r"(a1), "r"(a2), "r"(a3), "r"(b0), "r"(b1));
}

__device__ __forceinline__ uint32_t smem_u32(const void* p) {
    uint32_t a;
    asm("{ .reg .u64 t; cvta.to.shared.u64 t, %1; cvt.u32.u64 %0, t; }" : "=r"(a) : "l"(p));
    return a;
}
__device__ __forceinline__ void cpa16(uint32_t dst, const void* src) {
    asm volatile("cp.async.ca.shared.global [%0], [%1], 16;" :: "r"(dst), "l"(src));
}
#define CP_COMMIT() asm volatile("cp.async.commit_group;" ::: "memory")
#define CP_WAIT2()  asm volatile("cp.async.wait_group 2;" ::: "memory")
#define CP_WAIT0()  asm volatile("cp.async.wait_group 0;" ::: "memory")

// pos p of a 16-slab holds logical k with kperm16(k)=p; float4 at 4t -> k = t,t+4,t+8,t+12
__device__ __forceinline__ int kperm16(int k) { return ((k & 3) << 2) | ((k >> 2) & 3); }
__device__ __forceinline__ int cip512(int k) { return (k & ~15) | kperm16(k & 15); }
__device__ __forceinline__ int pcol64(int d) { return (d & 48) | kperm16(d & 15); }

// ---------------------------------------------------------------------------
// Prep kernels (unchanged from round 5)
// ---------------------------------------------------------------------------
__global__ void __launch_bounds__(256) prep_w(
    const float* __restrict__ gw, const float* __restrict__ tw,
    const float* __restrict__ pw, const float* __restrict__ ww)
{
    int gid = blockIdx.x * 256 + threadIdx.x;
    int m = gid >> 16;
    int rem = gid & 65535;
    int co = rem >> 7, k4 = (rem & 127) * 4;
    const float* src = (m == 0) ? gw : (m == 1) ? tw : (m == 2) ? pw : ww;
    float4 v = *(const float4*)(src + (size_t)co * 512 + k4);
    float vv[4] = {v.x, v.y, v.z, v.w};
    float* dst = d_wprep + ((size_t)m * 512 + co) * 512;
#pragma unroll
    for (int j = 0; j < 4; j++) dst[cip512(k4 + j)] = tfr(vv[j]);
}

__device__ __forceinline__ void prep_T(const float* __restrict__ in, float* __restrict__ out)
{
    __shared__ float sm[64][65];
    const int tid = threadIdx.x;
    const int l0 = blockIdx.x * 64, ci0 = blockIdx.y * 64, b = blockIdx.z;
    const float* src = in + (size_t)b * 512 * NL;
    float* dst = out + (size_t)b * NL * 512;
#pragma unroll
    for (int it = 0; it < 4; it++) {
        int ci = (tid >> 4) + 16 * it;
        int ll = (tid & 15) * 4;
        float4 v = *(const float4*)(src + (size_t)(ci0 + ci) * NL + l0 + ll);
        sm[ci][ll] = v.x; sm[ci][ll + 1] = v.y; sm[ci][ll + 2] = v.z; sm[ci][ll + 3] = v.w;
    }
    __syncthreads();
#pragma unroll
    for (int it = 0; it < 4; it++) {
        int ll = (tid >> 4) + 16 * it;
        int cb = (tid & 15) * 4;
#pragma unroll
        for (int j = 0; j < 4; j++)
            dst[(size_t)(l0 + ll) * 512 + cip512(ci0 + cb + j)] = tfr(sm[cb + j][ll]);
    }
}
__global__ void __launch_bounds__(256) prep_x(const float* __restrict__ x) { prep_T(x, d_xprep); }
__global__ void __launch_bounds__(256) prep_y() { prep_T(d_y, d_yprep); }

// ---------------------------------------------------------------------------
// Dense GEMM (unchanged from round 5)
// ---------------------------------------------------------------------------
#define DS_SMEM 65536

__device__ __forceinline__ void gemm_body_tc(
    const float* __restrict__ Wp,
    const float* __restrict__ Xp,
    const float* __restrict__ bias,
    float* __restrict__ out,
    int l0)
{
    extern __shared__ float ds[];
    const uint32_t sbA = smem_u32(ds);
    const uint32_t sbB = sbA + 32768;
    const int tid = threadIdx.x, lane = tid & 31, w = tid >> 5;
    const int wm = w >> 2, wn = w & 3;
    const int row2 = tid >> 2, c4 = (tid & 3) * 16;
    const char* srcWb = (const char*)Wp;
    const char* srcXb = (const char*)(Xp + (size_t)l0 * 512);

    float acc[4][4][4];
#pragma unroll
    for (int i = 0; i < 4; i++)
#pragma unroll
        for (int j = 0; j < 4; j++)
#pragma unroll
            for (int k = 0; k < 4; k++) acc[i][j][k] = 0.f;

#define ISSUE_SLAB(kt) do { \
    int bs_ = (kt) & 3; \
    uint32_t da_ = sbA + bs_ * 8192, db_ = sbB + bs_ * 8192; \
    cpa16(da_ + row2 * 64 + c4, srcWb + (size_t)row2 * 2048 + (kt) * 64 + c4); \
    cpa16(da_ + (row2 + 64) * 64 + c4, srcWb + (size_t)(row2 + 64) * 2048 + (kt) * 64 + c4); \
    cpa16(db_ + row2 * 64 + c4, srcXb + (size_t)row2 * 2048 + (kt) * 64 + c4); \
    cpa16(db_ + (row2 + 64) * 64 + c4, srcXb + (size_t)(row2 + 64) * 2048 + (kt) * 64 + c4); \
    CP_COMMIT(); \
} while (0)

    ISSUE_SLAB(0); ISSUE_SLAB(1); ISSUE_SLAB(2);

    for (int kt = 0; kt < 32; kt++) {
        if (kt < 29) CP_WAIT2(); else CP_WAIT0();
        __syncthreads();
        if (kt + 3 < 32) ISSUE_SLAB(kt + 3);

        const int bs = kt & 3;
        const float* bufA = ds + bs * 2048;
        const float* bufB = ds + 8192 + bs * 2048;

        float4 bf[4];
#pragma unroll
        for (int in = 0; in < 4; in++) {
            int n = wn * 32 + in * 8 + (lane >> 2);
            bf[in] = *(const float4*)(bufB + n * 16 + (lane & 3) * 4);
        }
#pragma unroll
        for (int im = 0; im < 4; im++) {
            int r = wm * 64 + im * 16 + (lane >> 2);
            float4 a0 = *(const float4*)(bufA + r * 16 + (lane & 3) * 4);
            float4 a1 = *(const float4*)(bufA + (r + 8) * 16 + (lane & 3) * 4);
#pragma unroll
            for (int s = 0; s < 2; s++) {
                uint32_t r0 = fu(s ? a0.z : a0.x), r1 = fu(s ? a1.z : a1.x);
                uint32_t r2 = fu(s ? a0.w : a0.y), r3 = fu(s ? a1.w : a1.y);
#pragma unroll
                for (int in = 0; in < 4; in++)
                    mma8(acc[im][in], r0, r1, r2, r3,
                         fu(s ? bf[in].z : bf[in].x), fu(s ? bf[in].w : bf[in].y));
            }
        }
        __syncthreads();
    }
#undef ISSUE_SLAB

#pragma unroll
    for (int im = 0; im < 4; im++) {
        int row = wm * 64 + im * 16 + (lane >> 2);
        float b0 = bias[row], b1 = bias[row + 8];
#pragma unroll
        for (int in = 0; in < 4; in++) {
            int col = l0 + wn * 32 + in * 8 + (lane & 3) * 2;
            float2 lo = make_float2(acc[im][in][0] + b0, acc[im][in][1] + b0);
            float2 hi = make_float2(acc[im][in][2] + b1, acc[im][in][3] + b1);
            *(float2*)&out[(size_t)row * NL + col] = lo;
            *(float2*)&out[(size_t)(row + 8) * NL + col] = hi;
        }
    }
}

__global__ void __launch_bounds__(256) proj_tc(
    const float* __restrict__ gb, const float* __restrict__ tbb, const float* __restrict__ pb)
{
    const int which = blockIdx.y >> 2;
    const int co0 = (blockIdx.y & 3) * 128;
    const int b = blockIdx.z;
    const float* bias = (which == 0 ? gb : which == 1 ? tbb : pb);
    gemm_body_tc(d_wprep + ((size_t)which * 512 + co0) * 512,
                 d_xprep + (size_t)b * NL * 512,
                 bias + co0,
                 d_proj + ((size_t)which * NB + b) * NCI * NL + (size_t)co0 * NL,
                 blockIdx.x * 128);
}

__global__ void __launch_bounds__(256) gemm2_tc(const float* __restrict__ wb)
{
    const int co0 = blockIdx.y * 128;
    const int b = blockIdx.z;
    gemm_body_tc(d_wprep + ((size_t)3 * 512 + co0) * 512,
                 d_yprep + (size_t)b * NL * 512,
                 wb + co0,
                 d_wy + (size_t)b * NC * NL + (size_t)co0 * NL, blockIdx.x * 128);
}

// ---------------------------------------------------------------------------
// Attention v2: warp = 16q x 64kk, P-in-registers via quad shuffles,
// pitch-80 conflict-free fragment loads, no P smem, 80KB smem, 2 CTAs/SM.
// ---------------------------------------------------------------------------
#define PQ 80
#define OSP 132
#define AT_SMEM ((128 + 64 + 64) * PQ * 4)   // 81920 B

__global__ void __launch_bounds__(256, 2) attn_tc()
{
    extern __shared__ float sm[];
    float* Qs = sm;             // [128 q][PQ] cols = d permuted
    float* Ks = Qs + 128 * PQ;  // [64 kk][PQ] cols = d permuted
    float* Vs = Ks + 64 * PQ;   // [64 d][PQ]  cols = kk permuted
    float* Os = Ks;             // epilogue reuse: [64 d][OSP]

    const int tid = threadIdx.x, lane = tid & 31, w = tid >> 5;
    const int r = lane >> 2, j = lane & 3;
    const int q0 = blockIdx.x * 128;
    const int b = blockIdx.y >> 3, h = blockIdx.y & 7;

    const float* theta = d_proj + ((size_t)(1 * NB + b) * NCI + h * ND) * NL;
    const float* phi   = d_proj + ((size_t)(2 * NB + b) * NCI + h * ND) * NL;
    const float* gx    = d_proj + ((size_t)(0 * NB + b) * NCI + h * ND) * NL;

    const int sd = tid >> 2;            // staging: this thread's d row (0..63)
    const int soff = tid & 3;           // staging: quarter index
    const int pcd = pcol64(sd);         // permuted column for d

    // ---- Q staging (once): Qs[q][pcol(d)], scaled 1/8; 2-way store conflicts
    {
        const float* tp = theta + (size_t)sd * NL + q0;
#pragma unroll
        for (int c = 0; c < 8; c++)
#pragma unroll
            for (int u = 0; u < 4; u++) {
                int q = soff + 4 * u + 16 * c;
                Qs[q * PQ + pcd] = tfr(tp[q] * 0.125f);
            }
    }

    float acc_o[8][4];
#pragma unroll
    for (int i = 0; i < 8; i++)
#pragma unroll
        for (int k = 0; k < 4; k++) acc_o[i][k] = 0.f;
    float psum0 = 0.f, psum1 = 0.f;

    const int src1 = (lane & ~3) | (j >> 1);
    const int src2 = src1 + 2;
    const bool jodd = (j & 1);

    for (int it = 0; it < 32; it++) {
        const int kk0 = it * 64;
        __syncthreads();   // prior-iter readers done (covers Q staging on it 0)

        // K staging: Ks[kk][pcol(d)]  (scalar, 2-way conflicts)
        {
            const float* pp = phi + (size_t)sd * NL + kk0;
#pragma unroll
            for (int c = 0; c < 4; c++)
#pragma unroll
                for (int u = 0; u < 4; u++) {
                    int kk = soff + 4 * u + 16 * c;
                    Ks[kk * PQ + pcd] = tfr(pp[kk]);
                }
        }
        // V staging: Vs[d][kperm(kk)] via staggered STS.128 (conflict-free)
        {
            const float* gp = gx + (size_t)sd * NL + kk0 + soff * 16;
            float vv[16];
#pragma unroll
            for (int c = 0; c < 4; c++) {
                float4 t = *(const float4*)(gp + 4 * c);
                vv[4 * c] = tfr(t.x); vv[4 * c + 1] = tfr(t.y);
                vv[4 * c + 2] = tfr(t.z); vv[4 * c + 3] = tfr(t.w);
            }
            float* vrow = Vs + sd * PQ + soff * 16;
#pragma unroll
            for (int cc = 0; cc < 4; cc++) {
                int tp_ = (cc + soff) & 3;
                float4 o = make_float4(vv[tp_], vv[4 + tp_], vv[8 + tp_], vv[12 + tp_]);
                *(float4*)(vrow + 4 * tp_) = o;
            }
        }
        __syncthreads();

        // ---- QK: S[16q][64kk], warp covers q rows [16w, 16w+16)
        float s_acc[8][4];
#pragma unroll
        for (int i = 0; i < 8; i++)
#pragma unroll
            for (int k = 0; k < 4; k++) s_acc[i][k] = 0.f;

#pragma unroll
        for (int s4 = 0; s4 < 4; s4++) {
            float4 qlo = *(const float4*)&Qs[(16 * w + r) * PQ + 16 * s4 + 4 * j];
            float4 qhi = *(const float4*)&Qs[(16 * w + r + 8) * PQ + 16 * s4 + 4 * j];
#pragma unroll
            for (int in = 0; in < 8; in++) {
                float4 kf = *(const float4*)&Ks[(8 * in + r) * PQ + 16 * s4 + 4 * j];
                mma8(s_acc[in], fu(qlo.x), fu(qhi.x), fu(qlo.y), fu(qhi.y), fu(kf.x), fu(kf.y));
                mma8(s_acc[in], fu(qlo.z), fu(qhi.z), fu(qlo.w), fu(qhi.w), fu(kf.z), fu(kf.w));
            }
        }

        // ---- exp (in place) + row sums
#pragma unroll
        for (int in = 0; in < 8; in++) {
            s_acc[in][0] = tfr(__expf(s_acc[in][0]));
            s_acc[in][1] = tfr(__expf(s_acc[in][1]));
            s_acc[in][2] = tfr(__expf(s_acc[in][2]));
            s_acc[in][3] = tfr(__expf(s_acc[in][3]));
            psum0 += s_acc[in][0] + s_acc[in][1];
            psum1 += s_acc[in][2] + s_acc[in][3];
        }

        // ---- PV: O[16q][64d] += P[16q][64kk] V[kk][d]; P via quad shuffles
#pragma unroll
        for (int sv = 0; sv < 4; sv++) {
            uint32_t A0[2][4];  // A frags for kchunks 2sv, 2sv+1
#pragma unroll
            for (int hh = 0; hh < 2; hh++) {
                const int ic = 2 * sv + hh;
                float e0 = __shfl_sync(0xffffffffu, s_acc[ic][0], src1);
                float o0 = __shfl_sync(0xffffffffu, s_acc[ic][1], src1);
                float e1 = __shfl_sync(0xffffffffu, s_acc[ic][2], src1);
                float o1 = __shfl_sync(0xffffffffu, s_acc[ic][3], src1);
                float e2 = __shfl_sync(0xffffffffu, s_acc[ic][0], src2);
                float o2 = __shfl_sync(0xffffffffu, s_acc[ic][1], src2);
                float e3 = __shfl_sync(0xffffffffu, s_acc[ic][2], src2);
                float o3 = __shfl_sync(0xffffffffu, s_acc[ic][3], src2);
                A0[hh][0] = fu(jodd ? o0 : e0);
                A0[hh][1] = fu(jodd ? o1 : e1);
                A0[hh][2] = fu(jodd ? o2 : e2);
                A0[hh][3] = fu(jodd ? o3 : e3);
            }
#pragma unroll
            for (int in = 0; in < 8; in++) {
                float4 vf = *(const float4*)&Vs[(8 * in + r) * PQ + 16 * sv + 4 * j];
                mma8(acc_o[in], A0[0][0], A0[0][1], A0[0][2], A0[0][3], fu(vf.x), fu(vf.y));
                mma8(acc_o[in], A0[1][0], A0[1][1], A0[1][2], A0[1][3], fu(vf.z), fu(vf.w));
            }
        }
    }

    // ---- epilogue: quad-reduce row sums, normalize, transpose via smem, store
    psum0 += __shfl_xor_sync(0xffffffffu, psum0, 1);
    psum0 += __shfl_xor_sync(0xffffffffu, psum0, 2);
    psum1 += __shfl_xor_sync(0xffffffffu, psum1, 1);
    psum1 += __shfl_xor_sync(0xffffffffu, psum1, 2);
    const float inv0 = 1.0f / psum0;
    const float inv1 = 1.0f / psum1;

    __syncthreads();   // all PV reads of Vs done before Os overwrites Ks/Vs
#pragma unroll
    for (int in = 0; in < 8; in++) {
        int d = 8 * in + 2 * j;
        int qq = 16 * w + r;
        Os[d * OSP + qq]           = acc_o[in][0] * inv0;
        Os[(d + 1) * OSP + qq]     = acc_o[in][1] * inv0;
        Os[d * OSP + qq + 8]       = acc_o[in][2] * inv1;
        Os[(d + 1) * OSP + qq + 8] = acc_o[in][3] * inv1;
    }
    __syncthreads();

    float* yout = d_y + ((size_t)b * NCI + h * ND) * NL;
    {
        const int qc = soff * 32;
#pragma unroll
        for (int c = 0; c < 8; c++) {
            float4 v = *(const float4*)&Os[sd * OSP + qc + 4 * c];
            *(float4*)&yout[(size_t)sd * NL + q0 + qc + 4 * c] = v;
        }
    }
}

// ---------------------------------------------------------------------------
// BatchNorm (unchanged from round 5)
// ---------------------------------------------------------------------------
__global__ void __launch_bounds__(256) bn_stats_kernel()
{
    const int c = blockIdx.x;
    const int tid = threadIdx.x;
    float s0 = 0, s1 = 0, s2 = 0, s3 = 0, q0 = 0, q1 = 0, q2 = 0, q3 = 0;
#pragma unroll
    for (int r = 0; r < 8; r++) {
        int f = tid + 256 * r;
        int b = f >> 9, l4 = f & 511;
        float4 v = *reinterpret_cast<const float4*>(&d_wy[((size_t)b * NC + c) * NL + l4 * 4]);
        s0 += v.x; s1 += v.y; s2 += v.z; s3 += v.w;
        q0 = fmaf(v.x, v.x, q0); q1 = fmaf(v.y, v.y, q1);
        q2 = fmaf(v.z, v.z, q2); q3 = fmaf(v.w, v.w, q3);
    }
    __shared__ float sh[256], sh2[256];
    sh[tid] = (s0 + s1) + (s2 + s3);
    sh2[tid] = (q0 + q1) + (q2 + q3);
    __syncthreads();
    for (int off = 128; off > 0; off >>= 1) {
        if (tid < off) { sh[tid] += sh[tid + off]; sh2[tid] += sh2[tid + off]; }
        __syncthreads();
    }
    if (tid == 0) {
        float mean = sh[0] * (1.0f / (NB * NL));
        float var = sh2[0] * (1.0f / (NB * NL)) - mean * mean;
        d_bnmean[c] = mean;
        d_bnrstd[c] = rsqrtf(var + 1e-5f);
    }
}

__global__ void __launch_bounds__(256) bn_apply_kernel(
    const float* __restrict__ gamma, const float* __restrict__ beta,
    float* __restrict__ out)
{
    int i4 = blockIdx.x * 256 + threadIdx.x;
    int c = (i4 >> 9) & (NC - 1);
    float4 v = reinterpret_cast<const float4*>(d_wy)[i4];
    float m = d_bnmean[c], rs = d_bnrstd[c] * gamma[c], bt = beta[c];
    float4 o = make_float4((v.x - m) * rs + bt, (v.y - m) * rs + bt,
                           (v.z - m) * rs + bt, (v.w - m) * rs + bt);
    reinterpret_cast<float4*>(out)[i4] = o;
}

// ---------------------------------------------------------------------------
extern "C" void kernel_launch(void* const* d_in, const int* in_sizes, int n_in,
                              void* d_out, int out_size)
{
    const float* x     = (const float*)d_in[0];
    const float* gw    = (const float*)d_in[1];
    const float* gb    = (const float*)d_in[2];
    const float* tw    = (const float*)d_in[3];
    const float* tb    = (const float*)d_in[4];
    const float* pw    = (const float*)d_in[5];
    const float* pb    = (const float*)d_in[6];
    const float* ww    = (const float*)d_in[7];
    const float* wb    = (const float*)d_in[8];
    const float* gamma = (const float*)d_in[9];
    const float* beta  = (const float*)d_in[10];
    float* out = (float*)d_out;

    cudaFuncSetAttribute(proj_tc, cudaFuncAttributeMaxDynamicSharedMemorySize, DS_SMEM);
    cudaFuncSetAttribute(gemm2_tc, cudaFuncAttributeMaxDynamicSharedMemorySize, DS_SMEM);
    cudaFuncSetAttribute(attn_tc, cudaFuncAttributeMaxDynamicSharedMemorySize, AT_SMEM);

    prep_w<<<1024, 256>>>(gw, tw, pw, ww);
    prep_x<<<dim3(32, 8, 4), 256>>>(x);
    proj_tc<<<dim3(16, 12, 4), 256, DS_SMEM>>>(gb, tb, pb);
    attn_tc<<<dim3(16, 32), 256, AT_SMEM>>>();
    prep_y<<<dim3(32, 8, 4), 256>>>();
    gemm2_tc<<<dim3(16, 4, 4), 256, DS_SMEM>>>(wb);
    bn_stats_kernel<<<NC, 256>>>();
    bn_apply_kernel<<<(NB * NC * NL) / 1024, 256>>>(gamma, beta, out);
}

// round 7
// speedup vs baseline: 6.4010x; 1.5437x over previous
#include <cuda_runtime.h>
#include <cuda_fp16.h>
#include <cstdint>
#include <math.h>

#define NB 4
#define NC 512
#define NL 2048
#define NCI 512
#define NH 8
#define ND 64

__device__ __align__(256) float d_proj[3 * NB * NCI * NL]; // [which][b][ci][l]; 0=g,1=theta,2=phi
__device__ __align__(256) float d_y[NB * NCI * NL];
__device__ __align__(256) float d_wy[NB * NC * NL];
__device__ __align__(256) float d_wprep[4 * 512 * 512];    // [m][co][k-perm] tf32-rounded
__device__ __align__(256) float d_xprep[NB * NL * 512];    // [b][l][ci-perm]
__device__ __align__(256) float d_yprep[NB * NL * 512];    // [b][l][ci-perm]
__device__ float d_bnmean[NC];
__device__ float d_bnrstd[NC];

// ---------------- helpers ----------------
__device__ __forceinline__ float tfr(float x) {
    uint32_t u;
    asm("cvt.rna.tf32.f32 %0, %1;" : "=r"(u) : "f"(x));
    return __uint_as_float(u);
}
__device__ __forceinline__ uint32_t fu(float x) { return __float_as_uint(x); }

__device__ __forceinline__ void mma8(float* c,
                                     uint32_t a0, uint32_t a1, uint32_t a2, uint32_t a3,
                                     uint32_t b0, uint32_t b1) {
    asm("mma.sync.aligned.m16n8k8.row.col.f32.tf32.tf32.f32 "
        "{%0,%1,%2,%3},{%4,%5,%6,%7},{%8,%9},{%0,%1,%2,%3};"
        : "+f"(c[0]), "+f"(c[1]), "+f"(c[2]), "+f"(c[3])
        : "r"(a0), "r"(a1), "r"(a2), "r"(a3), "r"(b0), "r"(b1));
}
__device__ __forceinline__ void hmma(float* c,
                                     uint32_t a0, uint32_t a1, uint32_t a2, uint32_t a3,
                                     uint32_t b0, uint32_t b1) {
    asm("mma.sync.aligned.m16n8k16.row.col.f32.f16.f16.f32 "
        "{%0,%1,%2,%3},{%4,%5,%6,%7},{%8,%9},{%0,%1,%2,%3};"
        : "+f"(c[0]), "+f"(c[1]), "+f"(c[2]), "+f"(c[3])
        : "r"(a0), "r"(a1), "r"(a2), "r"(a3), "r"(b0), "r"(b1));
}
__device__ __forceinline__ void ldsm4(uint32_t& r0, uint32_t& r1, uint32_t& r2, uint32_t& r3,
                                      uint32_t addr) {
    asm volatile("ldmatrix.sync.aligned.m8n8.x4.shared.b16 {%0,%1,%2,%3}, [%4];"
                 : "=r"(r0), "=r"(r1), "=r"(r2), "=r"(r3) : "r"(addr));
}
__device__ __forceinline__ void ldsm4t(uint32_t& r0, uint32_t& r1, uint32_t& r2, uint32_t& r3,
                                       uint32_t addr) {
    asm volatile("ldmatrix.sync.aligned.m8n8.x4.trans.shared.b16 {%0,%1,%2,%3}, [%4];"
                 : "=r"(r0), "=r"(r1), "=r"(r2), "=r"(r3) : "r"(addr));
}
__device__ __forceinline__ uint32_t f2h2(float a, float b) {
    __half2 h = __floats2half2_rn(a, b);
    return *reinterpret_cast<uint32_t*>(&h);
}

__device__ __forceinline__ uint32_t smem_u32(const void* p) {
    uint32_t a;
    asm("{ .reg .u64 t; cvta.to.shared.u64 t, %1; cvt.u32.u64 %0, t; }" : "=r"(a) : "l"(p));
    return a;
}
__device__ __forceinline__ void cpa16(uint32_t dst, const void* src) {
    asm volatile("cp.async.ca.shared.global [%0], [%1], 16;" :: "r"(dst), "l"(src));
}
#define CP_COMMIT() asm volatile("cp.async.commit_group;" ::: "memory")
#define CP_WAIT2()  asm volatile("cp.async.wait_group 2;" ::: "memory")
#define CP_WAIT0()  asm volatile("cp.async.wait_group 0;" ::: "memory")

__device__ __forceinline__ void sts128(uint32_t a, uint32_t x, uint32_t y, uint32_t z, uint32_t w) {
    asm volatile("st.shared.v4.b32 [%0], {%1, %2, %3, %4};" :: "r"(a), "r"(x), "r"(y), "r"(z), "r"(w) : "memory");
}

__device__ __forceinline__ int kperm16(int k) { return ((k & 3) << 2) | ((k >> 2) & 3); }
__device__ __forceinline__ int cip512(int k) { return (k & ~15) | kperm16(k & 15); }

// ---------------------------------------------------------------------------
// Prep kernels (unchanged)
// ---------------------------------------------------------------------------
__global__ void __launch_bounds__(256) prep_w(
    const float* __restrict__ gw, const float* __restrict__ tw,
    const float* __restrict__ pw, const float* __restrict__ ww)
{
    int gid = blockIdx.x * 256 + threadIdx.x;
    int m = gid >> 16;
    int rem = gid & 65535;
    int co = rem >> 7, k4 = (rem & 127) * 4;
    const float* src = (m == 0) ? gw : (m == 1) ? tw : (m == 2) ? pw : ww;
    float4 v = *(const float4*)(src + (size_t)co * 512 + k4);
    float vv[4] = {v.x, v.y, v.z, v.w};
    float* dst = d_wprep + ((size_t)m * 512 + co) * 512;
#pragma unroll
    for (int j = 0; j < 4; j++) dst[cip512(k4 + j)] = tfr(vv[j]);
}

__device__ __forceinline__ void prep_T(const float* __restrict__ in, float* __restrict__ out)
{
    __shared__ float sm[64][65];
    const int tid = threadIdx.x;
    const int l0 = blockIdx.x * 64, ci0 = blockIdx.y * 64, b = blockIdx.z;
    const float* src = in + (size_t)b * 512 * NL;
    float* dst = out + (size_t)b * NL * 512;
#pragma unroll
    for (int it = 0; it < 4; it++) {
        int ci = (tid >> 4) + 16 * it;
        int ll = (tid & 15) * 4;
        float4 v = *(const float4*)(src + (size_t)(ci0 + ci) * NL + l0 + ll);
        sm[ci][ll] = v.x; sm[ci][ll + 1] = v.y; sm[ci][ll + 2] = v.z; sm[ci][ll + 3] = v.w;
    }
    __syncthreads();
#pragma unroll
    for (int it = 0; it < 4; it++) {
        int ll = (tid >> 4) + 16 * it;
        int cb = (tid & 15) * 4;
#pragma unroll
        for (int j = 0; j < 4; j++)
            dst[(size_t)(l0 + ll) * 512 + cip512(ci0 + cb + j)] = tfr(sm[cb + j][ll]);
    }
}
__global__ void __launch_bounds__(256) prep_x(const float* __restrict__ x) { prep_T(x, d_xprep); }
__global__ void __launch_bounds__(256) prep_y() { prep_T(d_y, d_yprep); }

// ---------------------------------------------------------------------------
// Dense GEMM (unchanged)
// ---------------------------------------------------------------------------
#define DS_SMEM 65536

__device__ __forceinline__ void gemm_body_tc(
    const float* __restrict__ Wp,
    const float* __restrict__ Xp,
    const float* __restrict__ bias,
    float* __restrict__ out,
    int l0)
{
    extern __shared__ float ds[];
    const uint32_t sbA = smem_u32(ds);
    const uint32_t sbB = sbA + 32768;
    const int tid = threadIdx.x, lane = tid & 31, w = tid >> 5;
    const int wm = w >> 2, wn = w & 3;
    const int row2 = tid >> 2, c4 = (tid & 3) * 16;
    const char* srcWb = (const char*)Wp;
    const char* srcXb = (const char*)(Xp + (size_t)l0 * 512);

    float acc[4][4][4];
#pragma unroll
    for (int i = 0; i < 4; i++)
#pragma unroll
        for (int j = 0; j < 4; j++)
#pragma unroll
            for (int k = 0; k < 4; k++) acc[i][j][k] = 0.f;

#define ISSUE_SLAB(kt) do { \
    int bs_ = (kt) & 3; \
    uint32_t da_ = sbA + bs_ * 8192, db_ = sbB + bs_ * 8192; \
    cpa16(da_ + row2 * 64 + c4, srcWb + (size_t)row2 * 2048 + (kt) * 64 + c4); \
    cpa16(da_ + (row2 + 64) * 64 + c4, srcWb + (size_t)(row2 + 64) * 2048 + (kt) * 64 + c4); \
    cpa16(db_ + row2 * 64 + c4, srcXb + (size_t)row2 * 2048 + (kt) * 64 + c4); \
    cpa16(db_ + (row2 + 64) * 64 + c4, srcXb + (size_t)(row2 + 64) * 2048 + (kt) * 64 + c4); \
    CP_COMMIT(); \
} while (0)

    ISSUE_SLAB(0); ISSUE_SLAB(1); ISSUE_SLAB(2);

    for (int kt = 0; kt < 32; kt++) {
        if (kt < 29) CP_WAIT2(); else CP_WAIT0();
        __syncthreads();
        if (kt + 3 < 32) ISSUE_SLAB(kt + 3);

        const int bs = kt & 3;
        const float* bufA = ds + bs * 2048;
        const float* bufB = ds + 8192 + bs * 2048;

        float4 bf[4];
#pragma unroll
        for (int in = 0; in < 4; in++) {
            int n = wn * 32 + in * 8 + (lane >> 2);
            bf[in] = *(const float4*)(bufB + n * 16 + (lane & 3) * 4);
        }
#pragma unroll
        for (int im = 0; im < 4; im++) {
            int r = wm * 64 + im * 16 + (lane >> 2);
            float4 a0 = *(const float4*)(bufA + r * 16 + (lane & 3) * 4);
            float4 a1 = *(const float4*)(bufA + (r + 8) * 16 + (lane & 3) * 4);
#pragma unroll
            for (int s = 0; s < 2; s++) {
                uint32_t r0 = fu(s ? a0.z : a0.x), r1 = fu(s ? a1.z : a1.x);
                uint32_t r2 = fu(s ? a0.w : a0.y), r3 = fu(s ? a1.w : a1.y);
#pragma unroll
                for (int in = 0; in < 4; in++)
                    mma8(acc[im][in], r0, r1, r2, r3,
                         fu(s ? bf[in].z : bf[in].x), fu(s ? bf[in].w : bf[in].y));
            }
        }
        __syncthreads();
    }
#undef ISSUE_SLAB

#pragma unroll
    for (int im = 0; im < 4; im++) {
        int row = wm * 64 + im * 16 + (lane >> 2);
        float b0 = bias[row], b1 = bias[row + 8];
#pragma unroll
        for (int in = 0; in < 4; in++) {
            int col = l0 + wn * 32 + in * 8 + (lane & 3) * 2;
            float2 lo = make_float2(acc[im][in][0] + b0, acc[im][in][1] + b0);
            float2 hi = make_float2(acc[im][in][2] + b1, acc[im][in][3] + b1);
            *(float2*)&out[(size_t)row * NL + col] = lo;
            *(float2*)&out[(size_t)(row + 8) * NL + col] = hi;
        }
    }
}

__global__ void __launch_bounds__(256) proj_tc(
    const float* __restrict__ gb, const float* __restrict__ tbb, const float* __restrict__ pb)
{
    const int which = blockIdx.y >> 2;
    const int co0 = (blockIdx.y & 3) * 128;
    const int b = blockIdx.z;
    const float* bias = (which == 0 ? gb : which == 1 ? tbb : pb);
    gemm_body_tc(d_wprep + ((size_t)which * 512 + co0) * 512,
                 d_xprep + (size_t)b * NL * 512,
                 bias + co0,
                 d_proj + ((size_t)which * NB + b) * NCI * NL + (size_t)co0 * NL,
                 blockIdx.x * 128);
}

__global__ void __launch_bounds__(256) gemm2_tc(const float* __restrict__ wb)
{
    const int co0 = blockIdx.y * 128;
    const int b = blockIdx.z;
    gemm_body_tc(d_wprep + ((size_t)3 * 512 + co0) * 512,
                 d_yprep + (size_t)b * NL * 512,
                 wb + co0,
                 d_wy + (size_t)b * NC * NL + (size_t)co0 * NL, blockIdx.x * 128);
}

// ---------------------------------------------------------------------------
// Attention v3: f16 m16n8k16, ldmatrix(.trans), warp = 32q x 64kk, 4-warp CTA.
// Smem (halves, XOR-swizzled 16B blocks within rows):
//   Qd [64 d][128 q]  @ 0      (16384 B)
//   Kd [64 d][64 kk]  @ 16384  (8192 B)
//   Vd [64 d][64 kk]  @ 24576  (8192 B)
// Epilogue reuse: Os f32 [64 d][132 q] (33792 B)
// ---------------------------------------------------------------------------
#define AT_SMEM 33792

__device__ __forceinline__ uint32_t qswz(uint32_t base, int d, int qblk) {
    return base + d * 256 + ((qblk ^ (d & 7)) << 4);
}
__device__ __forceinline__ uint32_t kswz(uint32_t base, int d, int cblk) {
    return base + d * 128 + ((cblk ^ (d & 7)) << 4);
}

__global__ void __launch_bounds__(128, 2) attn_tc()
{
    extern __shared__ char smc[];
    const uint32_t sb = smem_u32(smc);
    const uint32_t Qb = sb, Kb = sb + 16384, Vb = sb + 24576;
    float* Os = reinterpret_cast<float*>(smc);

    const int tid = threadIdx.x, lane = tid & 31, w = tid >> 5;
    const int r = lane >> 2, j = lane & 3;
    const int lt = lane >> 3, li = lane & 7;   // ldmatrix tile index / row-within-tile
    const int q0 = blockIdx.x * 128;
    const int b = blockIdx.y >> 3, h = blockIdx.y & 7;

    const float* theta = d_proj + ((size_t)(1 * NB + b) * NCI + h * ND) * NL;
    const float* phi   = d_proj + ((size_t)(2 * NB + b) * NCI + h * ND) * NL;
    const float* gx    = d_proj + ((size_t)(0 * NB + b) * NCI + h * ND) * NL;

    const int sd = tid >> 1, shf = tid & 1;    // staging: d row, half selector

    // ---- stage Q (once): Qd[d][q] halves, scaled 1/8
    {
        const float* tp = theta + (size_t)sd * NL + q0 + shf * 64;
#pragma unroll
        for (int u = 0; u < 8; u++) {
            float4 v0 = *(const float4*)(tp + u * 8);
            float4 v1 = *(const float4*)(tp + u * 8 + 4);
            sts128(qswz(Qb, sd, shf * 8 + u),
                   f2h2(v0.x * 0.125f, v0.y * 0.125f), f2h2(v0.z * 0.125f, v0.w * 0.125f),
                   f2h2(v1.x * 0.125f, v1.y * 0.125f), f2h2(v1.z * 0.125f, v1.w * 0.125f));
        }
    }

    float acc_o[2][8][4];
#pragma unroll
    for (int m = 0; m < 2; m++)
#pragma unroll
        for (int n = 0; n < 8; n++)
#pragma unroll
            for (int k = 0; k < 4; k++) acc_o[m][n][k] = 0.f;
    float psum[2][2] = {{0.f, 0.f}, {0.f, 0.f}};

    for (int it = 0; it < 32; it++) {
        __syncthreads();   // prior-iter readers done (covers Q staging on it 0)

        // ---- stage K, V: native [d][kk] halves
        {
            const float* pp = phi + (size_t)sd * NL + it * 64 + shf * 32;
            const float* gp = gx + (size_t)sd * NL + it * 64 + shf * 32;
#pragma unroll
            for (int u = 0; u < 4; u++) {
                float4 v0 = *(const float4*)(pp + u * 8);
                float4 v1 = *(const float4*)(pp + u * 8 + 4);
                sts128(kswz(Kb, sd, shf * 4 + u),
                       f2h2(v0.x, v0.y), f2h2(v0.z, v0.w), f2h2(v1.x, v1.y), f2h2(v1.z, v1.w));
                float4 g0 = *(const float4*)(gp + u * 8);
                float4 g1 = *(const float4*)(gp + u * 8 + 4);
                sts128(kswz(Vb, sd, shf * 4 + u),
                       f2h2(g0.x, g0.y), f2h2(g0.z, g0.w), f2h2(g1.x, g1.y), f2h2(g1.z, g1.w));
            }
        }
        __syncthreads();

        // ---- QK: S[32q][64kk]
        float s_acc[2][8][4];
#pragma unroll
        for (int m = 0; m < 2; m++)
#pragma unroll
            for (int n = 0; n < 8; n++)
#pragma unroll
                for (int k = 0; k < 4; k++) s_acc[m][n][k] = 0.f;

#pragma unroll
        for (int s = 0; s < 4; s++) {
            uint32_t qa[2][4];
#pragma unroll
            for (int m = 0; m < 2; m++) {
                // trans x4 tiles: (d-lo,q-lo),(d-lo,q-hi),(d-hi,q-lo),(d-hi,q-hi)
                int d = 16 * s + 8 * (lt >> 1) + li;
                int qblk = ((32 * w + 16 * m) >> 3) + (lt & 1);
                ldsm4t(qa[m][0], qa[m][1], qa[m][2], qa[m][3], qswz(Qb, d, qblk));
            }
#pragma unroll
            for (int np = 0; np < 4; np++) {
                // trans x4 tiles: (d-lo,kk-lo),(d-hi,kk-lo),(d-lo,kk-hi),(d-hi,kk-hi)
                uint32_t k0, k1, k2, k3;
                int d = 16 * s + 8 * (lt & 1) + li;
                int cb = 2 * np + (lt >> 1);
                ldsm4t(k0, k1, k2, k3, kswz(Kb, d, cb));
#pragma unroll
                for (int m = 0; m < 2; m++) {
                    hmma(s_acc[m][2 * np],     qa[m][0], qa[m][1], qa[m][2], qa[m][3], k0, k1);
                    hmma(s_acc[m][2 * np + 1], qa[m][0], qa[m][1], qa[m][2], qa[m][3], k2, k3);
                }
            }
        }

        // ---- exp + pack P into A-frags (no smem, no shuffles)
        uint32_t pa[2][4][4];
#pragma unroll
        for (int m = 0; m < 2; m++)
#pragma unroll
            for (int sv = 0; sv < 4; sv++) {
                float e00 = __expf(s_acc[m][2 * sv][0]);
                float e01 = __expf(s_acc[m][2 * sv][1]);
                float e02 = __expf(s_acc[m][2 * sv][2]);
                float e03 = __expf(s_acc[m][2 * sv][3]);
                float e10 = __expf(s_acc[m][2 * sv + 1][0]);
                float e11 = __expf(s_acc[m][2 * sv + 1][1]);
                float e12 = __expf(s_acc[m][2 * sv + 1][2]);
                float e13 = __expf(s_acc[m][2 * sv + 1][3]);
                psum[m][0] += (e00 + e01) + (e10 + e11);
                psum[m][1] += (e02 + e03) + (e12 + e13);
                pa[m][sv][0] = f2h2(e00, e01);
                pa[m][sv][1] = f2h2(e02, e03);
                pa[m][sv][2] = f2h2(e10, e11);
                pa[m][sv][3] = f2h2(e12, e13);
            }

        // ---- PV: O[32q][64d] += P V
#pragma unroll
        for (int sv = 0; sv < 4; sv++) {
#pragma unroll
            for (int dp = 0; dp < 4; dp++) {
                // plain x4 tiles: (d-lo,kk-lo),(d-lo,kk-hi),(d-hi,kk-lo),(d-hi,kk-hi)
                uint32_t v0, v1, v2, v3;
                int d = 16 * dp + 8 * (lt >> 1) + li;
                int cb = 2 * sv + (lt & 1);
                ldsm4(v0, v1, v2, v3, kswz(Vb, d, cb));
#pragma unroll
                for (int m = 0; m < 2; m++) {
                    hmma(acc_o[m][2 * dp],     pa[m][sv][0], pa[m][sv][1], pa[m][sv][2], pa[m][sv][3], v0, v1);
                    hmma(acc_o[m][2 * dp + 1], pa[m][sv][0], pa[m][sv][1], pa[m][sv][2], pa[m][sv][3], v2, v3);
                }
            }
        }
    }

    // ---- normalize factors
#pragma unroll
    for (int m = 0; m < 2; m++)
#pragma unroll
        for (int hh = 0; hh < 2; hh++) {
            float v = psum[m][hh];
            v += __shfl_xor_sync(0xffffffffu, v, 1);
            v += __shfl_xor_sync(0xffffffffu, v, 2);
            psum[m][hh] = 1.0f / v;
        }

    __syncthreads();   // all smem reads done before Os overwrites
#pragma unroll
    for (int m = 0; m < 2; m++) {
        int q = 32 * w + 16 * m + r;
#pragma unroll
        for (int nd = 0; nd < 8; nd++) {
            int d = 8 * nd + 2 * j;
            Os[d * 132 + q]           = acc_o[m][nd][0] * psum[m][0];
            Os[(d + 1) * 132 + q]     = acc_o[m][nd][1] * psum[m][0];
            Os[d * 132 + q + 8]       = acc_o[m][nd][2] * psum[m][1];
            Os[(d + 1) * 132 + q + 8] = acc_o[m][nd][3] * psum[m][1];
        }
    }
    __syncthreads();

    // ---- coalesced store [d][q] -> d_y
    {
        float* yout = d_y + ((size_t)b * NCI + h * ND + sd) * NL + q0 + shf * 64;
        const float* src = Os + sd * 132 + shf * 64;
#pragma unroll
        for (int u = 0; u < 16; u++) {
            float4 v = *(const float4*)(src + u * 4);
            *(float4*)(yout + u * 4) = v;
        }
    }
}

// ---------------------------------------------------------------------------
// BatchNorm (unchanged)
// ---------------------------------------------------------------------------
__global__ void __launch_bounds__(256) bn_stats_kernel()
{
    const int c = blockIdx.x;
    const int tid = threadIdx.x;
    float s0 = 0, s1 = 0, s2 = 0, s3 = 0, q0 = 0, q1 = 0, q2 = 0, q3 = 0;
#pragma unroll
    for (int r = 0; r < 8; r++) {
        int f = tid + 256 * r;
        int b = f >> 9, l4 = f & 511;
        float4 v = *reinterpret_cast<const float4*>(&d_wy[((size_t)b * NC + c) * NL + l4 * 4]);
        s0 += v.x; s1 += v.y; s2 += v.z; s3 += v.w;
        q0 = fmaf(v.x, v.x, q0); q1 = fmaf(v.y, v.y, q1);
        q2 = fmaf(v.z, v.z, q2); q3 = fmaf(v.w, v.w, q3);
    }
    __shared__ float sh[256], sh2[256];
    sh[tid] = (s0 + s1) + (s2 + s3);
    sh2[tid] = (q0 + q1) + (q2 + q3);
    __syncthreads();
    for (int off = 128; off > 0; off >>= 1) {
        if (tid < off) { sh[tid] += sh[tid + off]; sh2[tid] += sh2[tid + off]; }
        __syncthreads();
    }
    if (tid == 0) {
        float mean = sh[0] * (1.0f / (NB * NL));
        float var = sh2[0] * (1.0f / (NB * NL)) - mean * mean;
        d_bnmean[c] = mean;
        d_bnrstd[c] = rsqrtf(var + 1e-5f);
    }
}

__global__ void __launch_bounds__(256) bn_apply_kernel(
    const float* __restrict__ gamma, const float* __restrict__ beta,
    float* __restrict__ out)
{
    int i4 = blockIdx.x * 256 + threadIdx.x;
    int c = (i4 >> 9) & (NC - 1);
    float4 v = reinterpret_cast<const float4*>(d_wy)[i4];
    float m = d_bnmean[c], rs = d_bnrstd[c] * gamma[c], bt = beta[c];
    float4 o = make_float4((v.x - m) * rs + bt, (v.y - m) * rs + bt,
                           (v.z - m) * rs + bt, (v.w - m) * rs + bt);
    reinterpret_cast<float4*>(out)[i4] = o;
}

// ---------------------------------------------------------------------------
extern "C" void kernel_launch(void* const* d_in, const int* in_sizes, int n_in,
                              void* d_out, int out_size)
{
    const float* x     = (const float*)d_in[0];
    const float* gw    = (const float*)d_in[1];
    const float* gb    = (const float*)d_in[2];
    const float* tw    = (const float*)d_in[3];
    const float* tb    = (const float*)d_in[4];
    const float* pw    = (const float*)d_in[5];
    const float* pb    = (const float*)d_in[6];
    const float* ww    = (const float*)d_in[7];
    const float* wb    = (const float*)d_in[8];
    const float* gamma = (const float*)d_in[9];
    const float* beta  = (const float*)d_in[10];
    float* out = (float*)d_out;

    cudaFuncSetAttribute(proj_tc, cudaFuncAttributeMaxDynamicSharedMemorySize, DS_SMEM);
    cudaFuncSetAttribute(gemm2_tc, cudaFuncAttributeMaxDynamicSharedMemorySize, DS_SMEM);
    cudaFuncSetAttribute(attn_tc, cudaFuncAttributeMaxDynamicSharedMemorySize, AT_SMEM);

    prep_w<<<1024, 256>>>(gw, tw, pw, ww);
    prep_x<<<dim3(32, 8, 4), 256>>>(x);
    proj_tc<<<dim3(16, 12, 4), 256, DS_SMEM>>>(gb, tb, pb);
    attn_tc<<<dim3(16, 32), 128, AT_SMEM>>>();
    prep_y<<<dim3(32, 8, 4), 256>>>();
    gemm2_tc<<<dim3(16, 4, 4), 256, DS_SMEM>>>(wb);
    bn_stats_kernel<<<NC, 256>>>();
    bn_apply_kernel<<<(NB * NC * NL) / 1024, 256>>>(gamma, beta, out);
}

// round 8
// speedup vs baseline: 7.6025x; 1.1877x over previous
#include <cuda_runtime.h>
#include <cuda_fp16.h>
#include <cstdint>
#include <math.h>

#define NB 4
#define NC 512
#define NL 2048
#define NCI 512
#define NH 8
#define ND 64

__device__ __align__(256) __half d_projh[3 * NB * NCI * NL]; // [which][b][ci][l] f16; theta pre-scaled 1/8
__device__ __align__(256) float d_y[NB * NCI * NL];
__device__ __align__(256) float d_wy[NB * NC * NL];
__device__ __align__(256) float d_wprep[4 * 512 * 512];      // [m][co][k-perm] tf32-rounded
__device__ __align__(256) float d_xprep[NB * NL * 512];      // [b][l][ci-perm]
__device__ __align__(256) float d_yprep[NB * NL * 512];      // [b][l][ci-perm]
__device__ float d_bnmean[NC];
__device__ float d_bnrstd[NC];

// ---------------- helpers ----------------
__device__ __forceinline__ float tfr(float x) {
    uint32_t u;
    asm("cvt.rna.tf32.f32 %0, %1;" : "=r"(u) : "f"(x));
    return __uint_as_float(u);
}
__device__ __forceinline__ uint32_t fu(float x) { return __float_as_uint(x); }

__device__ __forceinline__ void mma8(float* c,
                                     uint32_t a0, uint32_t a1, uint32_t a2, uint32_t a3,
                                     uint32_t b0, uint32_t b1) {
    asm("mma.sync.aligned.m16n8k8.row.col.f32.tf32.tf32.f32 "
        "{%0,%1,%2,%3},{%4,%5,%6,%7},{%8,%9},{%0,%1,%2,%3};"
        : "+f"(c[0]), "+f"(c[1]), "+f"(c[2]), "+f"(c[3])
        : "r"(a0), "r"(a1), "r"(a2), "r"(a3), "r"(b0), "r"(b1));
}
__device__ __forceinline__ void hmma(float* c,
                                     uint32_t a0, uint32_t a1, uint32_t a2, uint32_t a3,
                                     uint32_t b0, uint32_t b1) {
    asm("mma.sync.aligned.m16n8k16.row.col.f32.f16.f16.f32 "
        "{%0,%1,%2,%3},{%4,%5,%6,%7},{%8,%9},{%0,%1,%2,%3};"
        : "+f"(c[0]), "+f"(c[1]), "+f"(c[2]), "+f"(c[3])
        : "r"(a0), "r"(a1), "r"(a2), "r"(a3), "r"(b0), "r"(b1));
}
__device__ __forceinline__ void ldsm4(uint32_t& r0, uint32_t& r1, uint32_t& r2, uint32_t& r3,
                                      uint32_t addr) {
    asm volatile("ldmatrix.sync.aligned.m8n8.x4.shared.b16 {%0,%1,%2,%3}, [%4];"
                 : "=r"(r0), "=r"(r1), "=r"(r2), "=r"(r3) : "r"(addr));
}
__device__ __forceinline__ void ldsm4t(uint32_t& r0, uint32_t& r1, uint32_t& r2, uint32_t& r3,
                                       uint32_t addr) {
    asm volatile("ldmatrix.sync.aligned.m8n8.x4.trans.shared.b16 {%0,%1,%2,%3}, [%4];"
                 : "=r"(r0), "=r"(r1), "=r"(r2), "=r"(r3) : "r"(addr));
}
__device__ __forceinline__ uint32_t f2h2(float a, float b) {
    __half2 h = __floats2half2_rn(a, b);
    return *reinterpret_cast<uint32_t*>(&h);
}

__device__ __forceinline__ uint32_t smem_u32(const void* p) {
    uint32_t a;
    asm("{ .reg .u64 t; cvta.to.shared.u64 t, %1; cvt.u32.u64 %0, t; }" : "=r"(a) : "l"(p));
    return a;
}
__device__ __forceinline__ void cpa16(uint32_t dst, const void* src) {
    asm volatile("cp.async.ca.shared.global [%0], [%1], 16;" :: "r"(dst), "l"(src));
}
#define CP_COMMIT() asm volatile("cp.async.commit_group;" ::: "memory")
#define CP_WAIT2()  asm volatile("cp.async.wait_group 2;" ::: "memory")
#define CP_WAIT1()  asm volatile("cp.async.wait_group 1;" ::: "memory")
#define CP_WAIT0()  asm volatile("cp.async.wait_group 0;" ::: "memory")

__device__ __forceinline__ int kperm16(int k) { return ((k & 3) << 2) | ((k >> 2) & 3); }
__device__ __forceinline__ int cip512(int k) { return (k & ~15) | kperm16(k & 15); }

// ---------------------------------------------------------------------------
// Prep kernels (unchanged)
// ---------------------------------------------------------------------------
__global__ void __launch_bounds__(256) prep_w(
    const float* __restrict__ gw, const float* __restrict__ tw,
    const float* __restrict__ pw, const float* __restrict__ ww)
{
    int gid = blockIdx.x * 256 + threadIdx.x;
    int m = gid >> 16;
    int rem = gid & 65535;
    int co = rem >> 7, k4 = (rem & 127) * 4;
    const float* src = (m == 0) ? gw : (m == 1) ? tw : (m == 2) ? pw : ww;
    float4 v = *(const float4*)(src + (size_t)co * 512 + k4);
    float vv[4] = {v.x, v.y, v.z, v.w};
    float* dst = d_wprep + ((size_t)m * 512 + co) * 512;
#pragma unroll
    for (int j = 0; j < 4; j++) dst[cip512(k4 + j)] = tfr(vv[j]);
}

__device__ __forceinline__ void prep_T(const float* __restrict__ in, float* __restrict__ out)
{
    __shared__ float sm[64][65];
    const int tid = threadIdx.x;
    const int l0 = blockIdx.x * 64, ci0 = blockIdx.y * 64, b = blockIdx.z;
    const float* src = in + (size_t)b * 512 * NL;
    float* dst = out + (size_t)b * NL * 512;
#pragma unroll
    for (int it = 0; it < 4; it++) {
        int ci = (tid >> 4) + 16 * it;
        int ll = (tid & 15) * 4;
        float4 v = *(const float4*)(src + (size_t)(ci0 + ci) * NL + l0 + ll);
        sm[ci][ll] = v.x; sm[ci][ll + 1] = v.y; sm[ci][ll + 2] = v.z; sm[ci][ll + 3] = v.w;
    }
    __syncthreads();
#pragma unroll
    for (int it = 0; it < 4; it++) {
        int ll = (tid >> 4) + 16 * it;
        int cb = (tid & 15) * 4;
#pragma unroll
        for (int j = 0; j < 4; j++)
            dst[(size_t)(l0 + ll) * 512 + cip512(ci0 + cb + j)] = tfr(sm[cb + j][ll]);
    }
}
__global__ void __launch_bounds__(256) prep_x(const float* __restrict__ x) { prep_T(x, d_xprep); }
__global__ void __launch_bounds__(256) prep_y() { prep_T(d_y, d_yprep); }

// ---------------------------------------------------------------------------
// Dense GEMM (tf32, cp.async) — templated epilogue: float out or half out*scale
// ---------------------------------------------------------------------------
#define DS_SMEM 65536

template <bool HALF_OUT>
__device__ __forceinline__ void gemm_body_tc(
    const float* __restrict__ Wp,
    const float* __restrict__ Xp,
    const float* __restrict__ bias,
    float* __restrict__ outf,
    __half* __restrict__ outh,
    float oscale,
    int l0)
{
    extern __shared__ float ds[];
    const uint32_t sbA = smem_u32(ds);
    const uint32_t sbB = sbA + 32768;
    const int tid = threadIdx.x, lane = tid & 31, w = tid >> 5;
    const int wm = w >> 2, wn = w & 3;
    const int row2 = tid >> 2, c4 = (tid & 3) * 16;
    const char* srcWb = (const char*)Wp;
    const char* srcXb = (const char*)(Xp + (size_t)l0 * 512);

    float acc[4][4][4];
#pragma unroll
    for (int i = 0; i < 4; i++)
#pragma unroll
        for (int j = 0; j < 4; j++)
#pragma unroll
            for (int k = 0; k < 4; k++) acc[i][j][k] = 0.f;

#define ISSUE_SLAB(kt) do { \
    int bs_ = (kt) & 3; \
    uint32_t da_ = sbA + bs_ * 8192, db_ = sbB + bs_ * 8192; \
    cpa16(da_ + row2 * 64 + c4, srcWb + (size_t)row2 * 2048 + (kt) * 64 + c4); \
    cpa16(da_ + (row2 + 64) * 64 + c4, srcWb + (size_t)(row2 + 64) * 2048 + (kt) * 64 + c4); \
    cpa16(db_ + row2 * 64 + c4, srcXb + (size_t)row2 * 2048 + (kt) * 64 + c4); \
    cpa16(db_ + (row2 + 64) * 64 + c4, srcXb + (size_t)(row2 + 64) * 2048 + (kt) * 64 + c4); \
    CP_COMMIT(); \
} while (0)

    ISSUE_SLAB(0); ISSUE_SLAB(1); ISSUE_SLAB(2);

    for (int kt = 0; kt < 32; kt++) {
        if (kt < 29) CP_WAIT2(); else CP_WAIT0();
        __syncthreads();
        if (kt + 3 < 32) ISSUE_SLAB(kt + 3);

        const int bs = kt & 3;
        const float* bufA = ds + bs * 2048;
        const float* bufB = ds + 8192 + bs * 2048;

        float4 bf[4];
#pragma unroll
        for (int in = 0; in < 4; in++) {
            int n = wn * 32 + in * 8 + (lane >> 2);
            bf[in] = *(const float4*)(bufB + n * 16 + (lane & 3) * 4);
        }
#pragma unroll
        for (int im = 0; im < 4; im++) {
            int r = wm * 64 + im * 16 + (lane >> 2);
            float4 a0 = *(const float4*)(bufA + r * 16 + (lane & 3) * 4);
            float4 a1 = *(const float4*)(bufA + (r + 8) * 16 + (lane & 3) * 4);
#pragma unroll
            for (int s = 0; s < 2; s++) {
                uint32_t r0 = fu(s ? a0.z : a0.x), r1 = fu(s ? a1.z : a1.x);
                uint32_t r2 = fu(s ? a0.w : a0.y), r3 = fu(s ? a1.w : a1.y);
#pragma unroll
                for (int in = 0; in < 4; in++)
                    mma8(acc[im][in], r0, r1, r2, r3,
                         fu(s ? bf[in].z : bf[in].x), fu(s ? bf[in].w : bf[in].y));
            }
        }
        __syncthreads();
    }
#undef ISSUE_SLAB

#pragma unroll
    for (int im = 0; im < 4; im++) {
        int row = wm * 64 + im * 16 + (lane >> 2);
        float b0 = bias[row], b1 = bias[row + 8];
#pragma unroll
        for (int in = 0; in < 4; in++) {
            int col = l0 + wn * 32 + in * 8 + (lane & 3) * 2;
            if (HALF_OUT) {
                __half2 lo = __floats2half2_rn((acc[im][in][0] + b0) * oscale,
                                               (acc[im][in][1] + b0) * oscale);
                __half2 hi = __floats2half2_rn((acc[im][in][2] + b1) * oscale,
                                               (acc[im][in][3] + b1) * oscale);
                *(__half2*)&outh[(size_t)row * NL + col] = lo;
                *(__half2*)&outh[(size_t)(row + 8) * NL + col] = hi;
            } else {
                float2 lo = make_float2(acc[im][in][0] + b0, acc[im][in][1] + b0);
                float2 hi = make_float2(acc[im][in][2] + b1, acc[im][in][3] + b1);
                *(float2*)&outf[(size_t)row * NL + col] = lo;
                *(float2*)&outf[(size_t)(row + 8) * NL + col] = hi;
            }
        }
    }
}

__global__ void __launch_bounds__(256) proj_tc(
    const float* __restrict__ gb, const float* __restrict__ tbb, const float* __restrict__ pb)
{
    const int which = blockIdx.y >> 2;
    const int co0 = (blockIdx.y & 3) * 128;
    const int b = blockIdx.z;
    const float* bias = (which == 0 ? gb : which == 1 ? tbb : pb);
    gemm_body_tc<true>(d_wprep + ((size_t)which * 512 + co0) * 512,
                       d_xprep + (size_t)b * NL * 512,
                       bias + co0,
                       nullptr,
                       d_projh + ((size_t)which * NB + b) * NCI * NL + (size_t)co0 * NL,
                       which == 1 ? 0.125f : 1.0f,
                       blockIdx.x * 128);
}

__global__ void __launch_bounds__(256) gemm2_tc(const float* __restrict__ wb)
{
    const int co0 = blockIdx.y * 128;
    const int b = blockIdx.z;
    gemm_body_tc<false>(d_wprep + ((size_t)3 * 512 + co0) * 512,
                        d_yprep + (size_t)b * NL * 512,
                        wb + co0,
                        d_wy + (size_t)b * NC * NL + (size_t)co0 * NL,
                        nullptr, 1.0f, blockIdx.x * 128);
}

// ---------------------------------------------------------------------------
// Attention v4: f16 inputs from d_projh, cp.async double-buffered K/V,
// 8 warps x 16q, ldmatrix + m16n8k16. Smem:
//   Qh [64 d][128 q] @ 0       (16384 B)
//   Kh [2][64 d][64 kk] @16384 (16384 B)
//   Vh [2][64 d][64 kk] @32768 (16384 B)
// Epilogue reuse: Os f32 [64 d][132 q] (33792 B). Total 49152 B, 2 CTAs/SM.
// ---------------------------------------------------------------------------
#define AT_SMEM 49152

__device__ __forceinline__ uint32_t qswz(uint32_t base, int d, int qblk) {
    return base + d * 256 + ((qblk ^ (d & 7)) << 4);
}
__device__ __forceinline__ uint32_t kswz(uint32_t base, int d, int cblk) {
    return base + d * 128 + ((cblk ^ (d & 7)) << 4);
}

__global__ void __launch_bounds__(256, 2) attn_tc()
{
    extern __shared__ char smc[];
    const uint32_t sb = smem_u32(smc);
    const uint32_t Qb = sb, Kb = sb + 16384, Vb = sb + 32768;
    float* Os = reinterpret_cast<float*>(smc);

    const int tid = threadIdx.x, lane = tid & 31, w = tid >> 5;
    const int r = lane >> 2, j = lane & 3;
    const int lt = lane >> 3, li = lane & 7;
    const int q0 = blockIdx.x * 128;
    const int b = blockIdx.y >> 3, h = blockIdx.y & 7;

    const __half* thetah = d_projh + ((size_t)(1 * NB + b) * NCI + h * ND) * NL;
    const __half* phih   = d_projh + ((size_t)(2 * NB + b) * NCI + h * ND) * NL;
    const __half* gxh    = d_projh + ((size_t)(0 * NB + b) * NCI + h * ND) * NL;

    const int srow = tid >> 2;     // staging d row (0..63)
    const int scix = tid & 3;      // staging chunk group

    // ---- stage Q (16 chunks/row) + tile 0 of K/V, one commit group
#pragma unroll
    for (int u = 0; u < 4; u++) {
        int ch = scix + 4 * u;
        cpa16(qswz(Qb, srow, ch), thetah + (size_t)srow * NL + q0 + ch * 8);
    }
#pragma unroll
    for (int u = 0; u < 2; u++) {
        int ch = scix + 4 * u;
        cpa16(kswz(Kb, srow, ch), phih + (size_t)srow * NL + ch * 8);
        cpa16(kswz(Vb, srow, ch), gxh + (size_t)srow * NL + ch * 8);
    }
    CP_COMMIT();

    float acc_o[8][4];
#pragma unroll
    for (int n = 0; n < 8; n++)
#pragma unroll
        for (int k = 0; k < 4; k++) acc_o[n][k] = 0.f;
    float psum[2] = {0.f, 0.f};

    for (int it = 0; it < 32; it++) {
        __syncthreads();   // all warps done reading the buffer we're about to overwrite
        if (it + 1 < 32) {
            const int nb_ = (it + 1) & 1;
            const size_t kko = (size_t)(it + 1) * 64;
#pragma unroll
            for (int u = 0; u < 2; u++) {
                int ch = scix + 4 * u;
                cpa16(kswz(Kb + nb_ * 8192, srow, ch), phih + (size_t)srow * NL + kko + ch * 8);
                cpa16(kswz(Vb + nb_ * 8192, srow, ch), gxh + (size_t)srow * NL + kko + ch * 8);
            }
            CP_COMMIT();
            CP_WAIT1();
        } else {
            CP_WAIT0();
        }
        __syncthreads();

        const uint32_t Kc = Kb + (it & 1) * 8192;
        const uint32_t Vc = Vb + (it & 1) * 8192;

        // ---- QK: S[16q][64kk]
        float s_acc[8][4];
#pragma unroll
        for (int n = 0; n < 8; n++)
#pragma unroll
            for (int k = 0; k < 4; k++) s_acc[n][k] = 0.f;

#pragma unroll
        for (int s = 0; s < 4; s++) {
            uint32_t qa0, qa1, qa2, qa3;
            {
                int d = 16 * s + 8 * (lt >> 1) + li;
                int qblk = 2 * w + (lt & 1);
                ldsm4t(qa0, qa1, qa2, qa3, qswz(Qb, d, qblk));
            }
#pragma unroll
            for (int np = 0; np < 4; np++) {
                uint32_t k0, k1, k2, k3;
                int d = 16 * s + 8 * (lt & 1) + li;
                int cb = 2 * np + (lt >> 1);
                ldsm4t(k0, k1, k2, k3, kswz(Kc, d, cb));
                hmma(s_acc[2 * np],     qa0, qa1, qa2, qa3, k0, k1);
                hmma(s_acc[2 * np + 1], qa0, qa1, qa2, qa3, k2, k3);
            }
        }

        // ---- exp + pack P into A-frags
        uint32_t pa[4][4];
#pragma unroll
        for (int sv = 0; sv < 4; sv++) {
            float e00 = __expf(s_acc[2 * sv][0]);
            float e01 = __expf(s_acc[2 * sv][1]);
            float e02 = __expf(s_acc[2 * sv][2]);
            float e03 = __expf(s_acc[2 * sv][3]);
            float e10 = __expf(s_acc[2 * sv + 1][0]);
            float e11 = __expf(s_acc[2 * sv + 1][1]);
            float e12 = __expf(s_acc[2 * sv + 1][2]);
            float e13 = __expf(s_acc[2 * sv + 1][3]);
            psum[0] += (e00 + e01) + (e10 + e11);
            psum[1] += (e02 + e03) + (e12 + e13);
            pa[sv][0] = f2h2(e00, e01);
            pa[sv][1] = f2h2(e02, e03);
            pa[sv][2] = f2h2(e10, e11);
            pa[sv][3] = f2h2(e12, e13);
        }

        // ---- PV: O[16q][64d] += P V
#pragma unroll
        for (int sv = 0; sv < 4; sv++) {
#pragma unroll
            for (int dp = 0; dp < 4; dp++) {
                uint32_t v0, v1, v2, v3;
                int d = 16 * dp + 8 * (lt >> 1) + li;
                int cb = 2 * sv + (lt & 1);
                ldsm4(v0, v1, v2, v3, kswz(Vc, d, cb));
                hmma(acc_o[2 * dp],     pa[sv][0], pa[sv][1], pa[sv][2], pa[sv][3], v0, v1);
                hmma(acc_o[2 * dp + 1], pa[sv][0], pa[sv][1], pa[sv][2], pa[sv][3], v2, v3);
            }
        }
    }

    // ---- normalize
#pragma unroll
    for (int hh = 0; hh < 2; hh++) {
        float v = psum[hh];
        v += __shfl_xor_sync(0xffffffffu, v, 1);
        v += __shfl_xor_sync(0xffffffffu, v, 2);
        psum[hh] = 1.0f / v;
    }

    __syncthreads();   // all smem reads done before Os overwrites
    {
        int q = 16 * w + r;
#pragma unroll
        for (int nd = 0; nd < 8; nd++) {
            int d = 8 * nd + 2 * j;
            Os[d * 132 + q]           = acc_o[nd][0] * psum[0];
            Os[(d + 1) * 132 + q]     = acc_o[nd][1] * psum[0];
            Os[d * 132 + q + 8]       = acc_o[nd][2] * psum[1];
            Os[(d + 1) * 132 + q + 8] = acc_o[nd][3] * psum[1];
        }
    }
    __syncthreads();

    // ---- coalesced store [d][q] -> d_y (float)
    {
        const int sd2 = tid >> 2;
        const int qq = (tid & 3) * 32;
        float* yout = d_y + ((size_t)b * NCI + h * ND + sd2) * NL + q0 + qq;
        const float* src = Os + sd2 * 132 + qq;
#pragma unroll
        for (int u = 0; u < 8; u++) {
            float4 v = *(const float4*)(src + u * 4);
            *(float4*)(yout + u * 4) = v;
        }
    }
}

// ---------------------------------------------------------------------------
// BatchNorm (unchanged)
// ---------------------------------------------------------------------------
__global__ void __launch_bounds__(256) bn_stats_kernel()
{
    const int c = blockIdx.x;
    const int tid = threadIdx.x;
    float s0 = 0, s1 = 0, s2 = 0, s3 = 0, q0 = 0, q1 = 0, q2 = 0, q3 = 0;
#pragma unroll
    for (int r = 0; r < 8; r++) {
        int f = tid + 256 * r;
        int b = f >> 9, l4 = f & 511;
        float4 v = *reinterpret_cast<const float4*>(&d_wy[((size_t)b * NC + c) * NL + l4 * 4]);
        s0 += v.x; s1 += v.y; s2 += v.z; s3 += v.w;
        q0 = fmaf(v.x, v.x, q0); q1 = fmaf(v.y, v.y, q1);
        q2 = fmaf(v.z, v.z, q2); q3 = fmaf(v.w, v.w, q3);
    }
    __shared__ float sh[256], sh2[256];
    sh[tid] = (s0 + s1) + (s2 + s3);
    sh2[tid] = (q0 + q1) + (q2 + q3);
    __syncthreads();
    for (int off = 128; off > 0; off >>= 1) {
        if (tid < off) { sh[tid] += sh[tid + off]; sh2[tid] += sh2[tid + off]; }
        __syncthreads();
    }
    if (tid == 0) {
        float mean = sh[0] * (1.0f / (NB * NL));
        float var = sh2[0] * (1.0f / (NB * NL)) - mean * mean;
        d_bnmean[c] = mean;
        d_bnrstd[c] = rsqrtf(var + 1e-5f);
    }
}

__global__ void __launch_bounds__(256) bn_apply_kernel(
    const float* __restrict__ gamma, const float* __restrict__ beta,
    float* __restrict__ out)
{
    int i4 = blockIdx.x * 256 + threadIdx.x;
    int c = (i4 >> 9) & (NC - 1);
    float4 v = reinterpret_cast<const float4*>(d_wy)[i4];
    float m = d_bnmean[c], rs = d_bnrstd[c] * gamma[c], bt = beta[c];
    float4 o = make_float4((v.x - m) * rs + bt, (v.y - m) * rs + bt,
                           (v.z - m) * rs + bt, (v.w - m) * rs + bt);
    reinterpret_cast<float4*>(out)[i4] = o;
}

// ---------------------------------------------------------------------------
extern "C" void kernel_launch(void* const* d_in, const int* in_sizes, int n_in,
                              void* d_out, int out_size)
{
    const float* x     = (const float*)d_in[0];
    const float* gw    = (const float*)d_in[1];
    const float* gb    = (const float*)d_in[2];
    const float* tw    = (const float*)d_in[3];
    const float* tb    = (const float*)d_in[4];
    const float* pw    = (const float*)d_in[5];
    const float* pb    = (const float*)d_in[6];
    const float* ww    = (const float*)d_in[7];
    const float* wb    = (const float*)d_in[8];
    const float* gamma = (const float*)d_in[9];
    const float* beta  = (const float*)d_in[10];
    float* out = (float*)d_out;

    cudaFuncSetAttribute(proj_tc, cudaFuncAttributeMaxDynamicSharedMemorySize, DS_SMEM);
    cudaFuncSetAttribute(gemm2_tc, cudaFuncAttributeMaxDynamicSharedMemorySize, DS_SMEM);
    cudaFuncSetAttribute(attn_tc, cudaFuncAttributeMaxDynamicSharedMemorySize, AT_SMEM);

    prep_w<<<1024, 256>>>(gw, tw, pw, ww);
    prep_x<<<dim3(32, 8, 4), 256>>>(x);
    proj_tc<<<dim3(16, 12, 4), 256, DS_SMEM>>>(gb, tb, pb);
    attn_tc<<<dim3(16, 32), 256, AT_SMEM>>>();
    prep_y<<<dim3(32, 8, 4), 256>>>();
    gemm2_tc<<<dim3(16, 4, 4), 256, DS_SMEM>>>(wb);
    bn_stats_kernel<<<NC, 256>>>();
    bn_apply_kernel<<<(NB * NC * NL) / 1024, 256>>>(gamma, beta, out);
}

// round 9
// speedup vs baseline: 9.8591x; 1.2968x over previous
#include <cuda_runtime.h>
#include <cuda_fp16.h>
#include <cstdint>
#include <math.h>

#define NB 4
#define NC 512
#define NL 2048
#define NCI 512
#define NH 8
#define ND 64

__device__ __align__(256) __half d_projh[3 * NB * NCI * NL]; // [which][b][ci][l] f16; theta pre-scaled 1/8
__device__ __align__(256) __half d_yh[NB * NL * NCI];        // [b][l][ci] f16 (attention out)
__device__ __align__(256) __half d_wh[4 * 512 * 512];        // [m][co][k] f16 weights
__device__ __align__(256) __half d_xh[NB * NL * 512];        // [b][l][ci] f16
__device__ __align__(256) float d_wy[NB * NC * NL];
__device__ float d_bnmean[NC];
__device__ float d_bnrstd[NC];

// ---------------- helpers ----------------
__device__ __forceinline__ uint32_t fu(float x) { return __float_as_uint(x); }

__device__ __forceinline__ void hmma(float* c,
                                     uint32_t a0, uint32_t a1, uint32_t a2, uint32_t a3,
                                     uint32_t b0, uint32_t b1) {
    asm("mma.sync.aligned.m16n8k16.row.col.f32.f16.f16.f32 "
        "{%0,%1,%2,%3},{%4,%5,%6,%7},{%8,%9},{%0,%1,%2,%3};"
        : "+f"(c[0]), "+f"(c[1]), "+f"(c[2]), "+f"(c[3])
        : "r"(a0), "r"(a1), "r"(a2), "r"(a3), "r"(b0), "r"(b1));
}
__device__ __forceinline__ void ldsm4(uint32_t& r0, uint32_t& r1, uint32_t& r2, uint32_t& r3,
                                      uint32_t addr) {
    asm volatile("ldmatrix.sync.aligned.m8n8.x4.shared.b16 {%0,%1,%2,%3}, [%4];"
                 : "=r"(r0), "=r"(r1), "=r"(r2), "=r"(r3) : "r"(addr));
}
__device__ __forceinline__ void ldsm4t(uint32_t& r0, uint32_t& r1, uint32_t& r2, uint32_t& r3,
                                       uint32_t addr) {
    asm volatile("ldmatrix.sync.aligned.m8n8.x4.trans.shared.b16 {%0,%1,%2,%3}, [%4];"
                 : "=r"(r0), "=r"(r1), "=r"(r2), "=r"(r3) : "r"(addr));
}
__device__ __forceinline__ uint32_t f2h2(float a, float b) {
    __half2 h = __floats2half2_rn(a, b);
    return *reinterpret_cast<uint32_t*>(&h);
}

__device__ __forceinline__ uint32_t smem_u32(const void* p) {
    uint32_t a;
    asm("{ .reg .u64 t; cvta.to.shared.u64 t, %1; cvt.u32.u64 %0, t; }" : "=r"(a) : "l"(p));
    return a;
}
__device__ __forceinline__ void cpa16(uint32_t dst, const void* src) {
    asm volatile("cp.async.ca.shared.global [%0], [%1], 16;" :: "r"(dst), "l"(src));
}
#define CP_COMMIT() asm volatile("cp.async.commit_group;" ::: "memory")
#define CP_WAIT1()  asm volatile("cp.async.wait_group 1;" ::: "memory")
#define CP_WAIT0()  asm volatile("cp.async.wait_group 0;" ::: "memory")

// ---------------------------------------------------------------------------
// Prep kernels: fp32 -> f16
// ---------------------------------------------------------------------------
__global__ void __launch_bounds__(256) prep_w(
    const float* __restrict__ gw, const float* __restrict__ tw,
    const float* __restrict__ pw, const float* __restrict__ ww)
{
    int gid = blockIdx.x * 256 + threadIdx.x;     // per float4
    int m = gid >> 16;
    int rem = gid & 65535;
    const float* src = (m == 0) ? gw : (m == 1) ? tw : (m == 2) ? pw : ww;
    float4 v = *(const float4*)(src + (size_t)rem * 4);
    uint2 o = make_uint2(f2h2(v.x, v.y), f2h2(v.z, v.w));
    *(uint2*)(d_wh + (size_t)m * 262144 + (size_t)rem * 4) = o;
}

// transpose [b][512 ci][2048 l] f32 -> [b][l][ci] f16; grid (32 lt, 8 cit, 4 b)
__global__ void __launch_bounds__(256) prep_x(const float* __restrict__ in)
{
    __shared__ float sm[64][65];
    const int tid = threadIdx.x;
    const int l0 = blockIdx.x * 64, ci0 = blockIdx.y * 64, b = blockIdx.z;
    const float* src = in + (size_t)b * 512 * NL;
    __half* dst = d_xh + (size_t)b * NL * 512;
#pragma unroll
    for (int it = 0; it < 4; it++) {
        int ci = (tid >> 4) + 16 * it;
        int ll = (tid & 15) * 4;
        float4 v = *(const float4*)(src + (size_t)(ci0 + ci) * NL + l0 + ll);
        sm[ci][ll] = v.x; sm[ci][ll + 1] = v.y; sm[ci][ll + 2] = v.z; sm[ci][ll + 3] = v.w;
    }
    __syncthreads();
#pragma unroll
    for (int it = 0; it < 4; it++) {
        int ll = (tid >> 4) + 16 * it;
        int cb = (tid & 15) * 4;
        uint2 o = make_uint2(f2h2(sm[cb][ll], sm[cb + 1][ll]),
                             f2h2(sm[cb + 2][ll], sm[cb + 3][ll]));
        *(uint2*)(dst + (size_t)(l0 + ll) * 512 + ci0 + cb) = o;
    }
}

// ---------------------------------------------------------------------------
// Dense GEMM f16: out[co][l] = sum_k W[co][k] * X[l][k] + bias[co]
// CTA 128co x 128l; k-slabs of 64 (8 slabs); 2-stage cp.async.
// smem rows 128B, chunk swizzle c^(row&7). A tile 16KB + B tile 16KB, x2 buf.
// 8 warps: wm=w>>2 (64 co), wn=w&3 (32 l).
// ---------------------------------------------------------------------------
#define DS_SMEM 65536

__device__ __forceinline__ uint32_t dswz(uint32_t base, int row, int c) {
    return base + row * 128 + ((c ^ (row & 7)) << 4);
}

template <bool HALF_OUT>
__device__ __forceinline__ void gemm_body_f16(
    const __half* __restrict__ Wp,    // offset to co0; row pitch 512
    const __half* __restrict__ Xp,    // [l][512]
    const float* __restrict__ bias,   // offset to co0
    float* __restrict__ outf,
    __half* __restrict__ outh,
    float oscale,
    int l0)
{
    extern __shared__ float ds[];
    const uint32_t sb = smem_u32(ds);
    const int tid = threadIdx.x, lane = tid & 31, w = tid >> 5;
    const int wm = w >> 2, wn = w & 3;
    const int lt = lane >> 3, li = lane & 7;
    const int srow = tid >> 1, scp = tid & 1;

    float acc[4][4][4];
#pragma unroll
    for (int i = 0; i < 4; i++)
#pragma unroll
        for (int j = 0; j < 4; j++)
#pragma unroll
            for (int k = 0; k < 4; k++) acc[i][j][k] = 0.f;

#define DISSUE(kt) do { \
    uint32_t bA = sb + ((kt) & 1) * 32768, bB = bA + 16384; \
    const __half* wsrc = Wp + (size_t)srow * 512 + (kt) * 64; \
    const __half* xsrc = Xp + (size_t)(l0 + srow) * 512 + (kt) * 64; \
    _Pragma("unroll") \
    for (int u = 0; u < 4; u++) { \
        int c = scp * 4 + u; \
        cpa16(dswz(bA, srow, c), wsrc + c * 8); \
        cpa16(dswz(bB, srow, c), xsrc + c * 8); \
    } \
    CP_COMMIT(); \
} while (0)

    DISSUE(0); DISSUE(1);

    for (int kt = 0; kt < 8; kt++) {
        if (kt < 7) CP_WAIT1(); else CP_WAIT0();
        __syncthreads();

        const uint32_t bA = sb + (kt & 1) * 32768, bB = bA + 16384;
#pragma unroll
        for (int kc = 0; kc < 4; kc++) {
            uint32_t af[4][4];
#pragma unroll
            for (int im = 0; im < 4; im++) {
                int row = wm * 64 + im * 16 + 8 * (lt & 1) + li;
                int c = 2 * kc + (lt >> 1);
                ldsm4(af[im][0], af[im][1], af[im][2], af[im][3], dswz(bA, row, c));
            }
#pragma unroll
            for (int bt = 0; bt < 2; bt++) {
                uint32_t b0, b1, b2, b3;
                int lrow = wn * 32 + bt * 16 + 8 * (lt >> 1) + li;
                int c = 2 * kc + (lt & 1);
                ldsm4(b0, b1, b2, b3, dswz(bB, lrow, c));
#pragma unroll
                for (int im = 0; im < 4; im++) {
                    hmma(acc[im][2 * bt],     af[im][0], af[im][1], af[im][2], af[im][3], b0, b1);
                    hmma(acc[im][2 * bt + 1], af[im][0], af[im][1], af[im][2], af[im][3], b2, b3);
                }
            }
        }
        __syncthreads();
        if (kt + 2 < 8) DISSUE(kt + 2);
    }
#undef DISSUE

    const int r = lane >> 2, j = lane & 3;
#pragma unroll
    for (int im = 0; im < 4; im++) {
        int row = wm * 64 + im * 16 + r;
        float b0 = bias[row], b1 = bias[row + 8];
#pragma unroll
        for (int nt = 0; nt < 4; nt++) {
            int col = l0 + wn * 32 + nt * 8 + 2 * j;
            if (HALF_OUT) {
                *(__half2*)&outh[(size_t)row * NL + col] =
                    __floats2half2_rn((acc[im][nt][0] + b0) * oscale, (acc[im][nt][1] + b0) * oscale);
                *(__half2*)&outh[(size_t)(row + 8) * NL + col] =
                    __floats2half2_rn((acc[im][nt][2] + b1) * oscale, (acc[im][nt][3] + b1) * oscale);
            } else {
                *(float2*)&outf[(size_t)row * NL + col] =
                    make_float2(acc[im][nt][0] + b0, acc[im][nt][1] + b0);
                *(float2*)&outf[(size_t)(row + 8) * NL + col] =
                    make_float2(acc[im][nt][2] + b1, acc[im][nt][3] + b1);
            }
        }
    }
}

__global__ void __launch_bounds__(256) proj_tc(
    const float* __restrict__ gb, const float* __restrict__ tbb, const float* __restrict__ pb)
{
    const int which = blockIdx.y >> 2;
    const int co0 = (blockIdx.y & 3) * 128;
    const int b = blockIdx.z;
    const float* bias = (which == 0 ? gb : which == 1 ? tbb : pb);
    gemm_body_f16<true>(d_wh + ((size_t)which * 512 + co0) * 512,
                        d_xh + (size_t)b * NL * 512,
                        bias + co0,
                        nullptr,
                        d_projh + ((size_t)which * NB + b) * NCI * NL + (size_t)co0 * NL,
                        which == 1 ? 0.125f : 1.0f,
                        blockIdx.x * 128);
}

__global__ void __launch_bounds__(256) gemm2_tc(const float* __restrict__ wb)
{
    const int co0 = blockIdx.y * 128;
    const int b = blockIdx.z;
    gemm_body_f16<false>(d_wh + ((size_t)3 * 512 + co0) * 512,
                         d_yh + (size_t)b * NL * 512,
                         wb + co0,
                         d_wy + (size_t)b * NC * NL + (size_t)co0 * NL,
                         nullptr, 1.0f, blockIdx.x * 128);
}

// ---------------------------------------------------------------------------
// Attention (round-8 core, direct-store epilogue to d_yh [b][l][ci])
// ---------------------------------------------------------------------------
#define AT_SMEM 49152

__device__ __forceinline__ uint32_t qswz(uint32_t base, int d, int qblk) {
    return base + d * 256 + ((qblk ^ (d & 7)) << 4);
}
__device__ __forceinline__ uint32_t kswz(uint32_t base, int d, int cblk) {
    return base + d * 128 + ((cblk ^ (d & 7)) << 4);
}

__global__ void __launch_bounds__(256, 2) attn_tc()
{
    extern __shared__ char smc[];
    const uint32_t sb = smem_u32(smc);
    const uint32_t Qb = sb, Kb = sb + 16384, Vb = sb + 32768;

    const int tid = threadIdx.x, lane = tid & 31, w = tid >> 5;
    const int r = lane >> 2, j = lane & 3;
    const int lt = lane >> 3, li = lane & 7;
    const int q0 = blockIdx.x * 128;
    const int b = blockIdx.y >> 3, h = blockIdx.y & 7;

    const __half* thetah = d_projh + ((size_t)(1 * NB + b) * NCI + h * ND) * NL;
    const __half* phih   = d_projh + ((size_t)(2 * NB + b) * NCI + h * ND) * NL;
    const __half* gxh    = d_projh + ((size_t)(0 * NB + b) * NCI + h * ND) * NL;

    const int srow = tid >> 2;
    const int scix = tid & 3;

#pragma unroll
    for (int u = 0; u < 4; u++) {
        int ch = scix + 4 * u;
        cpa16(qswz(Qb, srow, ch), thetah + (size_t)srow * NL + q0 + ch * 8);
    }
#pragma unroll
    for (int u = 0; u < 2; u++) {
        int ch = scix + 4 * u;
        cpa16(kswz(Kb, srow, ch), phih + (size_t)srow * NL + ch * 8);
        cpa16(kswz(Vb, srow, ch), gxh + (size_t)srow * NL + ch * 8);
    }
    CP_COMMIT();

    float acc_o[8][4];
#pragma unroll
    for (int n = 0; n < 8; n++)
#pragma unroll
        for (int k = 0; k < 4; k++) acc_o[n][k] = 0.f;
    float psum[2] = {0.f, 0.f};

    for (int it = 0; it < 32; it++) {
        __syncthreads();
        if (it + 1 < 32) {
            const int nb_ = (it + 1) & 1;
            const size_t kko = (size_t)(it + 1) * 64;
#pragma unroll
            for (int u = 0; u < 2; u++) {
                int ch = scix + 4 * u;
                cpa16(kswz(Kb + nb_ * 8192, srow, ch), phih + (size_t)srow * NL + kko + ch * 8);
                cpa16(kswz(Vb + nb_ * 8192, srow, ch), gxh + (size_t)srow * NL + kko + ch * 8);
            }
            CP_COMMIT();
            CP_WAIT1();
        } else {
            CP_WAIT0();
        }
        __syncthreads();

        const uint32_t Kc = Kb + (it & 1) * 8192;
        const uint32_t Vc = Vb + (it & 1) * 8192;

        float s_acc[8][4];
#pragma unroll
        for (int n = 0; n < 8; n++)
#pragma unroll
            for (int k = 0; k < 4; k++) s_acc[n][k] = 0.f;

#pragma unroll
        for (int s = 0; s < 4; s++) {
            uint32_t qa0, qa1, qa2, qa3;
            {
                int d = 16 * s + 8 * (lt >> 1) + li;
                int qblk = 2 * w + (lt & 1);
                ldsm4t(qa0, qa1, qa2, qa3, qswz(Qb, d, qblk));
            }
#pragma unroll
            for (int np = 0; np < 4; np++) {
                uint32_t k0, k1, k2, k3;
                int d = 16 * s + 8 * (lt & 1) + li;
                int cb = 2 * np + (lt >> 1);
                ldsm4t(k0, k1, k2, k3, kswz(Kc, d, cb));
                hmma(s_acc[2 * np],     qa0, qa1, qa2, qa3, k0, k1);
                hmma(s_acc[2 * np + 1], qa0, qa1, qa2, qa3, k2, k3);
            }
        }

        uint32_t pa[4][4];
#pragma unroll
        for (int sv = 0; sv < 4; sv++) {
            float e00 = __expf(s_acc[2 * sv][0]);
            float e01 = __expf(s_acc[2 * sv][1]);
            float e02 = __expf(s_acc[2 * sv][2]);
            float e03 = __expf(s_acc[2 * sv][3]);
            float e10 = __expf(s_acc[2 * sv + 1][0]);
            float e11 = __expf(s_acc[2 * sv + 1][1]);
            float e12 = __expf(s_acc[2 * sv + 1][2]);
            float e13 = __expf(s_acc[2 * sv + 1][3]);
            psum[0] += (e00 + e01) + (e10 + e11);
            psum[1] += (e02 + e03) + (e12 + e13);
            pa[sv][0] = f2h2(e00, e01);
            pa[sv][1] = f2h2(e02, e03);
            pa[sv][2] = f2h2(e10, e11);
            pa[sv][3] = f2h2(e12, e13);
        }

#pragma unroll
        for (int sv = 0; sv < 4; sv++) {
#pragma unroll
            for (int dp = 0; dp < 4; dp++) {
                uint32_t v0, v1, v2, v3;
                int d = 16 * dp + 8 * (lt >> 1) + li;
                int cb = 2 * sv + (lt & 1);
                ldsm4(v0, v1, v2, v3, kswz(Vc, d, cb));
                hmma(acc_o[2 * dp],     pa[sv][0], pa[sv][1], pa[sv][2], pa[sv][3], v0, v1);
                hmma(acc_o[2 * dp + 1], pa[sv][0], pa[sv][1], pa[sv][2], pa[sv][3], v2, v3);
            }
        }
    }

#pragma unroll
    for (int hh = 0; hh < 2; hh++) {
        float v = psum[hh];
        v += __shfl_xor_sync(0xffffffffu, v, 1);
        v += __shfl_xor_sync(0xffffffffu, v, 2);
        psum[hh] = 1.0f / v;
    }

    // ---- direct-store epilogue: O[q][d] -> d_yh[b][q0+q][h*64+d]
    {
        const int q = 16 * w + r;
        __half* y0 = d_yh + ((size_t)b * NL + q0 + q) * 512 + h * 64;
        __half* y1 = y0 + (size_t)8 * 512;
#pragma unroll
        for (int nd = 0; nd < 8; nd++) {
            int d = 8 * nd + 2 * j;
            *(__half2*)(y0 + d) = __floats2half2_rn(acc_o[nd][0] * psum[0], acc_o[nd][1] * psum[0]);
            *(__half2*)(y1 + d) = __floats2half2_rn(acc_o[nd][2] * psum[1], acc_o[nd][3] * psum[1]);
        }
    }
}

// ---------------------------------------------------------------------------
// BatchNorm (unchanged)
// ---------------------------------------------------------------------------
__global__ void __launch_bounds__(256) bn_stats_kernel()
{
    const int c = blockIdx.x;
    const int tid = threadIdx.x;
    float s0 = 0, s1 = 0, s2 = 0, s3 = 0, q0 = 0, q1 = 0, q2 = 0, q3 = 0;
#pragma unroll
    for (int r = 0; r < 8; r++) {
        int f = tid + 256 * r;
        int b = f >> 9, l4 = f & 511;
        float4 v = *reinterpret_cast<const float4*>(&d_wy[((size_t)b * NC + c) * NL + l4 * 4]);
        s0 += v.x; s1 += v.y; s2 += v.z; s3 += v.w;
        q0 = fmaf(v.x, v.x, q0); q1 = fmaf(v.y, v.y, q1);
        q2 = fmaf(v.z, v.z, q2); q3 = fmaf(v.w, v.w, q3);
    }
    __shared__ float sh[256], sh2[256];
    sh[tid] = (s0 + s1) + (s2 + s3);
    sh2[tid] = (q0 + q1) + (q2 + q3);
    __syncthreads();
    for (int off = 128; off > 0; off >>= 1) {
        if (tid < off) { sh[tid] += sh[tid + off]; sh2[tid] += sh2[tid + off]; }
        __syncthreads();
    }
    if (tid == 0) {
        float mean = sh[0] * (1.0f / (NB * NL));
        float var = sh2[0] * (1.0f / (NB * NL)) - mean * mean;
        d_bnmean[c] = mean;
        d_bnrstd[c] = rsqrtf(var + 1e-5f);
    }
}

__global__ void __launch_bounds__(256) bn_apply_kernel(
    const float* __restrict__ gamma, const float* __restrict__ beta,
    float* __restrict__ out)
{
    int i4 = blockIdx.x * 256 + threadIdx.x;
    int c = (i4 >> 9) & (NC - 1);
    float4 v = reinterpret_cast<const float4*>(d_wy)[i4];
    float m = d_bnmean[c], rs = d_bnrstd[c] * gamma[c], bt = beta[c];
    float4 o = make_float4((v.x - m) * rs + bt, (v.y - m) * rs + bt,
                           (v.z - m) * rs + bt, (v.w - m) * rs + bt);
    reinterpret_cast<float4*>(out)[i4] = o;
}

// ---------------------------------------------------------------------------
extern "C" void kernel_launch(void* const* d_in, const int* in_sizes, int n_in,
                              void* d_out, int out_size)
{
    const float* x     = (const float*)d_in[0];
    const float* gw    = (const float*)d_in[1];
    const float* gb    = (const float*)d_in[2];
    const float* tw    = (const float*)d_in[3];
    const float* tb    = (const float*)d_in[4];
    const float* pw    = (const float*)d_in[5];
    const float* pb    = (const float*)d_in[6];
    const float* ww    = (const float*)d_in[7];
    const float* wb    = (const float*)d_in[8];
    const float* gamma = (const float*)d_in[9];
    const float* beta  = (const float*)d_in[10];
    float* out = (float*)d_out;

    cudaFuncSetAttribute(proj_tc, cudaFuncAttributeMaxDynamicSharedMemorySize, DS_SMEM);
    cudaFuncSetAttribute(gemm2_tc, cudaFuncAttributeMaxDynamicSharedMemorySize, DS_SMEM);
    cudaFuncSetAttribute(attn_tc, cudaFuncAttributeMaxDynamicSharedMemorySize, AT_SMEM);

    prep_w<<<1024, 256>>>(gw, tw, pw, ww);
    prep_x<<<dim3(32, 8, 4), 256>>>(x);
    proj_tc<<<dim3(16, 12, 4), 256, DS_SMEM>>>(gb, tb, pb);
    attn_tc<<<dim3(16, 32), 256, AT_SMEM>>>();
    gemm2_tc<<<dim3(16, 4, 4), 256, DS_SMEM>>>(wb);
    bn_stats_kernel<<<NC, 256>>>();
    bn_apply_kernel<<<(NB * NC * NL) / 1024, 256>>>(gamma, beta, out);
}

// round 10
// speedup vs baseline: 10.0971x; 1.0241x over previous
#include <cuda_runtime.h>
#include <cuda_fp16.h>
#include <cstdint>
#include <math.h>

#define NB 4
#define NC 512
#define NL 2048
#define NCI 512
#define NH 8
#define ND 64

__device__ __align__(256) __half d_projh[3 * NB * NCI * NL]; // [which][b][ci][l]; theta pre-scaled 0.125*log2e
__device__ __align__(256) __half d_yh[NB * NL * NCI];        // [b][l][ci] f16 (attention out)
__device__ __align__(256) __half d_wh[4 * 512 * 512];        // [m][co][k] f16 weights
__device__ __align__(256) __half d_xh[NB * NL * 512];        // [b][l][ci] f16
__device__ __align__(256) float d_wy[NB * NC * NL];
__device__ float d_bnsum[NC];
__device__ float d_bnsq[NC];
__device__ float d_bnmean[NC];
__device__ float d_bnrstd[NC];

// ---------------- helpers ----------------
__device__ __forceinline__ uint32_t fu(float x) { return __float_as_uint(x); }
__device__ __forceinline__ float ex2f(float x) {
    float y;
    asm("ex2.approx.f32 %0, %1;" : "=f"(y) : "f"(x));
    return y;
}

__device__ __forceinline__ void hmma(float* c,
                                     uint32_t a0, uint32_t a1, uint32_t a2, uint32_t a3,
                                     uint32_t b0, uint32_t b1) {
    asm("mma.sync.aligned.m16n8k16.row.col.f32.f16.f16.f32 "
        "{%0,%1,%2,%3},{%4,%5,%6,%7},{%8,%9},{%0,%1,%2,%3};"
        : "+f"(c[0]), "+f"(c[1]), "+f"(c[2]), "+f"(c[3])
        : "r"(a0), "r"(a1), "r"(a2), "r"(a3), "r"(b0), "r"(b1));
}
__device__ __forceinline__ void ldsm4(uint32_t& r0, uint32_t& r1, uint32_t& r2, uint32_t& r3,
                                      uint32_t addr) {
    asm volatile("ldmatrix.sync.aligned.m8n8.x4.shared.b16 {%0,%1,%2,%3}, [%4];"
                 : "=r"(r0), "=r"(r1), "=r"(r2), "=r"(r3) : "r"(addr));
}
__device__ __forceinline__ void ldsm4t(uint32_t& r0, uint32_t& r1, uint32_t& r2, uint32_t& r3,
                                       uint32_t addr) {
    asm volatile("ldmatrix.sync.aligned.m8n8.x4.trans.shared.b16 {%0,%1,%2,%3}, [%4];"
                 : "=r"(r0), "=r"(r1), "=r"(r2), "=r"(r3) : "r"(addr));
}
__device__ __forceinline__ uint32_t f2h2(float a, float b) {
    __half2 h = __floats2half2_rn(a, b);
    return *reinterpret_cast<uint32_t*>(&h);
}

__device__ __forceinline__ uint32_t smem_u32(const void* p) {
    uint32_t a;
    asm("{ .reg .u64 t; cvta.to.shared.u64 t, %1; cvt.u32.u64 %0, t; }" : "=r"(a) : "l"(p));
    return a;
}
__device__ __forceinline__ void cpa16(uint32_t dst, const void* src) {
    asm volatile("cp.async.ca.shared.global [%0], [%1], 16;" :: "r"(dst), "l"(src));
}
#define CP_COMMIT() asm volatile("cp.async.commit_group;" ::: "memory")
#define CP_WAIT1()  asm volatile("cp.async.wait_group 1;" ::: "memory")
#define CP_WAIT0()  asm volatile("cp.async.wait_group 0;" ::: "memory")

// ---------------------------------------------------------------------------
// Prep kernels: fp32 -> f16 (+ zero BN accumulators)
// ---------------------------------------------------------------------------
__global__ void __launch_bounds__(256) prep_w(
    const float* __restrict__ gw, const float* __restrict__ tw,
    const float* __restrict__ pw, const float* __restrict__ ww)
{
    int gid = blockIdx.x * 256 + threadIdx.x;     // per float4
    if (gid < NC) { d_bnsum[gid] = 0.f; d_bnsq[gid] = 0.f; }
    int m = gid >> 16;
    int rem = gid & 65535;
    const float* src = (m == 0) ? gw : (m == 1) ? tw : (m == 2) ? pw : ww;
    float4 v = *(const float4*)(src + (size_t)rem * 4);
    uint2 o = make_uint2(f2h2(v.x, v.y), f2h2(v.z, v.w));
    *(uint2*)(d_wh + (size_t)m * 262144 + (size_t)rem * 4) = o;
}

// transpose [b][512 ci][2048 l] f32 -> [b][l][ci] f16; grid (32 lt, 8 cit, 4 b)
__global__ void __launch_bounds__(256) prep_x(const float* __restrict__ in)
{
    __shared__ float sm[64][65];
    const int tid = threadIdx.x;
    const int l0 = blockIdx.x * 64, ci0 = blockIdx.y * 64, b = blockIdx.z;
    const float* src = in + (size_t)b * 512 * NL;
    __half* dst = d_xh + (size_t)b * NL * 512;
#pragma unroll
    for (int it = 0; it < 4; it++) {
        int ci = (tid >> 4) + 16 * it;
        int ll = (tid & 15) * 4;
        float4 v = *(const float4*)(src + (size_t)(ci0 + ci) * NL + l0 + ll);
        sm[ci][ll] = v.x; sm[ci][ll + 1] = v.y; sm[ci][ll + 2] = v.z; sm[ci][ll + 3] = v.w;
    }
    __syncthreads();
#pragma unroll
    for (int it = 0; it < 4; it++) {
        int ll = (tid >> 4) + 16 * it;
        int cb = (tid & 15) * 4;
        uint2 o = make_uint2(f2h2(sm[cb][ll], sm[cb + 1][ll]),
                             f2h2(sm[cb + 2][ll], sm[cb + 3][ll]));
        *(uint2*)(dst + (size_t)(l0 + ll) * 512 + ci0 + cb) = o;
    }
}

// ---------------------------------------------------------------------------
// Dense GEMM f16 (2-stage cp.async, ldmatrix, m16n8k16)
// STATS: fused per-channel sum / sum-sq atomics (gemm2 only)
// ---------------------------------------------------------------------------
#define DS_SMEM 65536

__device__ __forceinline__ uint32_t dswz(uint32_t base, int row, int c) {
    return base + row * 128 + ((c ^ (row & 7)) << 4);
}

template <bool HALF_OUT, bool STATS>
__device__ __forceinline__ void gemm_body_f16(
    const __half* __restrict__ Wp,    // offset to co0; row pitch 512
    const __half* __restrict__ Xp,    // [l][512]
    const float* __restrict__ bias,   // offset to co0
    float* __restrict__ outf,
    __half* __restrict__ outh,
    float* __restrict__ bnsum,        // offset to co0 (STATS only)
    float* __restrict__ bnsq,
    float oscale,
    int l0)
{
    extern __shared__ float ds[];
    const uint32_t sb = smem_u32(ds);
    const int tid = threadIdx.x, lane = tid & 31, w = tid >> 5;
    const int wm = w >> 2, wn = w & 3;
    const int lt = lane >> 3, li = lane & 7;
    const int srow = tid >> 1, scp = tid & 1;

    float acc[4][4][4];
#pragma unroll
    for (int i = 0; i < 4; i++)
#pragma unroll
        for (int j = 0; j < 4; j++)
#pragma unroll
            for (int k = 0; k < 4; k++) acc[i][j][k] = 0.f;

#define DISSUE(kt) do { \
    uint32_t bA = sb + ((kt) & 1) * 32768, bB = bA + 16384; \
    const __half* wsrc = Wp + (size_t)srow * 512 + (kt) * 64; \
    const __half* xsrc = Xp + (size_t)(l0 + srow) * 512 + (kt) * 64; \
    _Pragma("unroll") \
    for (int u = 0; u < 4; u++) { \
        int c = scp * 4 + u; \
        cpa16(dswz(bA, srow, c), wsrc + c * 8); \
        cpa16(dswz(bB, srow, c), xsrc + c * 8); \
    } \
    CP_COMMIT(); \
} while (0)

    DISSUE(0); DISSUE(1);

    for (int kt = 0; kt < 8; kt++) {
        if (kt < 7) CP_WAIT1(); else CP_WAIT0();
        __syncthreads();

        const uint32_t bA = sb + (kt & 1) * 32768, bB = bA + 16384;
#pragma unroll
        for (int kc = 0; kc < 4; kc++) {
            uint32_t af[4][4];
#pragma unroll
            for (int im = 0; im < 4; im++) {
                int row = wm * 64 + im * 16 + 8 * (lt & 1) + li;
                int c = 2 * kc + (lt >> 1);
                ldsm4(af[im][0], af[im][1], af[im][2], af[im][3], dswz(bA, row, c));
            }
#pragma unroll
            for (int bt = 0; bt < 2; bt++) {
                uint32_t b0, b1, b2, b3;
                int lrow = wn * 32 + bt * 16 + 8 * (lt >> 1) + li;
                int c = 2 * kc + (lt & 1);
                ldsm4(b0, b1, b2, b3, dswz(bB, lrow, c));
#pragma unroll
                for (int im = 0; im < 4; im++) {
                    hmma(acc[im][2 * bt],     af[im][0], af[im][1], af[im][2], af[im][3], b0, b1);
                    hmma(acc[im][2 * bt + 1], af[im][0], af[im][1], af[im][2], af[im][3], b2, b3);
                }
            }
        }
        __syncthreads();
        if (kt + 2 < 8) DISSUE(kt + 2);
    }
#undef DISSUE

    const int r = lane >> 2, j = lane & 3;
#pragma unroll
    for (int im = 0; im < 4; im++) {
        int row = wm * 64 + im * 16 + r;
        float b0 = bias[row], b1 = bias[row + 8];
        float s0 = 0.f, q0 = 0.f, s1 = 0.f, q1 = 0.f;
#pragma unroll
        for (int nt = 0; nt < 4; nt++) {
            int col = l0 + wn * 32 + nt * 8 + 2 * j;
            float v00 = acc[im][nt][0] + b0, v01 = acc[im][nt][1] + b0;
            float v10 = acc[im][nt][2] + b1, v11 = acc[im][nt][3] + b1;
            if (HALF_OUT) {
                *(__half2*)&outh[(size_t)row * NL + col] =
                    __floats2half2_rn(v00 * oscale, v01 * oscale);
                *(__half2*)&outh[(size_t)(row + 8) * NL + col] =
                    __floats2half2_rn(v10 * oscale, v11 * oscale);
            } else {
                *(float2*)&outf[(size_t)row * NL + col] = make_float2(v00, v01);
                *(float2*)&outf[(size_t)(row + 8) * NL + col] = make_float2(v10, v11);
            }
            if (STATS) {
                s0 += v00 + v01; q0 = fmaf(v00, v00, fmaf(v01, v01, q0));
                s1 += v10 + v11; q1 = fmaf(v10, v10, fmaf(v11, v11, q1));
            }
        }
        if (STATS) {
            s0 += __shfl_xor_sync(0xffffffffu, s0, 1);
            s0 += __shfl_xor_sync(0xffffffffu, s0, 2);
            q0 += __shfl_xor_sync(0xffffffffu, q0, 1);
            q0 += __shfl_xor_sync(0xffffffffu, q0, 2);
            s1 += __shfl_xor_sync(0xffffffffu, s1, 1);
            s1 += __shfl_xor_sync(0xffffffffu, s1, 2);
            q1 += __shfl_xor_sync(0xffffffffu, q1, 1);
            q1 += __shfl_xor_sync(0xffffffffu, q1, 2);
            if (j == 0) {
                atomicAdd(&bnsum[row], s0);
                atomicAdd(&bnsq[row], q0);
                atomicAdd(&bnsum[row + 8], s1);
                atomicAdd(&bnsq[row + 8], q1);
            }
        }
    }
}

__global__ void __launch_bounds__(256) proj_tc(
    const float* __restrict__ gb, const float* __restrict__ tbb, const float* __restrict__ pb)
{
    const int which = blockIdx.y >> 2;
    const int co0 = (blockIdx.y & 3) * 128;
    const int b = blockIdx.z;
    const float* bias = (which == 0 ? gb : which == 1 ? tbb : pb);
    // theta gets 0.125 * log2(e) so attention can use ex2 directly
    gemm_body_f16<true, false>(d_wh + ((size_t)which * 512 + co0) * 512,
                               d_xh + (size_t)b * NL * 512,
                               bias + co0,
                               nullptr,
                               d_projh + ((size_t)which * NB + b) * NCI * NL + (size_t)co0 * NL,
                               nullptr, nullptr,
                               which == 1 ? 0.18033688f : 1.0f,
                               blockIdx.x * 128);
}

__global__ void __launch_bounds__(256) gemm2_tc(const float* __restrict__ wb)
{
    const int co0 = blockIdx.y * 128;
    const int b = blockIdx.z;
    gemm_body_f16<false, true>(d_wh + ((size_t)3 * 512 + co0) * 512,
                               d_yh + (size_t)b * NL * 512,
                               wb + co0,
                               d_wy + (size_t)b * NC * NL + (size_t)co0 * NL,
                               nullptr,
                               d_bnsum + co0, d_bnsq + co0,
                               1.0f, blockIdx.x * 128);
}

// ---------------------------------------------------------------------------
// Attention: f16 m16n8k16, cp.async double-buffered K/V, hoisted Q fragments,
// exp via ex2 (log2e pre-folded into theta), exp/PV interleaved.
// ---------------------------------------------------------------------------
#define AT_SMEM 49152

__device__ __forceinline__ uint32_t qswz(uint32_t base, int d, int qblk) {
    return base + d * 256 + ((qblk ^ (d & 7)) << 4);
}
__device__ __forceinline__ uint32_t kswz(uint32_t base, int d, int cblk) {
    return base + d * 128 + ((cblk ^ (d & 7)) << 4);
}

__global__ void __launch_bounds__(256, 2) attn_tc()
{
    extern __shared__ char smc[];
    const uint32_t sb = smem_u32(smc);
    const uint32_t Qb = sb, Kb = sb + 16384, Vb = sb + 32768;

    const int tid = threadIdx.x, lane = tid & 31, w = tid >> 5;
    const int r = lane >> 2, j = lane & 3;
    const int lt = lane >> 3, li = lane & 7;
    const int q0 = blockIdx.x * 128;
    const int b = blockIdx.y >> 3, h = blockIdx.y & 7;

    const __half* thetah = d_projh + ((size_t)(1 * NB + b) * NCI + h * ND) * NL;
    const __half* phih   = d_projh + ((size_t)(2 * NB + b) * NCI + h * ND) * NL;
    const __half* gxh    = d_projh + ((size_t)(0 * NB + b) * NCI + h * ND) * NL;

    const int srow = tid >> 2;
    const int scix = tid & 3;

#pragma unroll
    for (int u = 0; u < 4; u++) {
        int ch = scix + 4 * u;
        cpa16(qswz(Qb, srow, ch), thetah + (size_t)srow * NL + q0 + ch * 8);
    }
#pragma unroll
    for (int u = 0; u < 2; u++) {
        int ch = scix + 4 * u;
        cpa16(kswz(Kb, srow, ch), phih + (size_t)srow * NL + ch * 8);
        cpa16(kswz(Vb, srow, ch), gxh + (size_t)srow * NL + ch * 8);
    }
    CP_COMMIT();

    uint32_t qf[4][4];          // hoisted Q fragments (loaded at it==0)
    float acc_o[8][4];
#pragma unroll
    for (int n = 0; n < 8; n++)
#pragma unroll
        for (int k = 0; k < 4; k++) acc_o[n][k] = 0.f;
    float psum[2] = {0.f, 0.f};

    for (int it = 0; it < 32; it++) {
        __syncthreads();
        if (it + 1 < 32) {
            const int nb_ = (it + 1) & 1;
            const size_t kko = (size_t)(it + 1) * 64;
#pragma unroll
            for (int u = 0; u < 2; u++) {
                int ch = scix + 4 * u;
                cpa16(kswz(Kb + nb_ * 8192, srow, ch), phih + (size_t)srow * NL + kko + ch * 8);
                cpa16(kswz(Vb + nb_ * 8192, srow, ch), gxh + (size_t)srow * NL + kko + ch * 8);
            }
            CP_COMMIT();
            CP_WAIT1();
        } else {
            CP_WAIT0();
        }
        __syncthreads();

        if (it == 0) {
#pragma unroll
            for (int s = 0; s < 4; s++) {
                int d = 16 * s + 8 * (lt >> 1) + li;
                int qblk = 2 * w + (lt & 1);
                ldsm4t(qf[s][0], qf[s][1], qf[s][2], qf[s][3], qswz(Qb, d, qblk));
            }
        }

        const uint32_t Kc = Kb + (it & 1) * 8192;
        const uint32_t Vc = Vb + (it & 1) * 8192;

        // ---- QK: S[16q][64kk]  (S is already in log2 units)
        float s_acc[8][4];
#pragma unroll
        for (int n = 0; n < 8; n++)
#pragma unroll
            for (int k = 0; k < 4; k++) s_acc[n][k] = 0.f;

#pragma unroll
        for (int s = 0; s < 4; s++) {
#pragma unroll
            for (int np = 0; np < 4; np++) {
                uint32_t k0, k1, k2, k3;
                int d = 16 * s + 8 * (lt & 1) + li;
                int cb = 2 * np + (lt >> 1);
                ldsm4t(k0, k1, k2, k3, kswz(Kc, d, cb));
                hmma(s_acc[2 * np],     qf[s][0], qf[s][1], qf[s][2], qf[s][3], k0, k1);
                hmma(s_acc[2 * np + 1], qf[s][0], qf[s][1], qf[s][2], qf[s][3], k2, k3);
            }
        }

        // ---- exp (ex2) + PV interleaved; pa transient per sv
#pragma unroll
        for (int sv = 0; sv < 4; sv++) {
            float e00 = ex2f(s_acc[2 * sv][0]);
            float e01 = ex2f(s_acc[2 * sv][1]);
            float e02 = ex2f(s_acc[2 * sv][2]);
            float e03 = ex2f(s_acc[2 * sv][3]);
            float e10 = ex2f(s_acc[2 * sv + 1][0]);
            float e11 = ex2f(s_acc[2 * sv + 1][1]);
            float e12 = ex2f(s_acc[2 * sv + 1][2]);
            float e13 = ex2f(s_acc[2 * sv + 1][3]);
            psum[0] += (e00 + e01) + (e10 + e11);
            psum[1] += (e02 + e03) + (e12 + e13);
            uint32_t pa0 = f2h2(e00, e01);
            uint32_t pa1 = f2h2(e02, e03);
            uint32_t pa2 = f2h2(e10, e11);
            uint32_t pa3 = f2h2(e12, e13);
#pragma unroll
            for (int dp = 0; dp < 4; dp++) {
                uint32_t v0, v1, v2, v3;
                int d = 16 * dp + 8 * (lt >> 1) + li;
                int cb = 2 * sv + (lt & 1);
                ldsm4(v0, v1, v2, v3, kswz(Vc, d, cb));
                hmma(acc_o[2 * dp],     pa0, pa1, pa2, pa3, v0, v1);
                hmma(acc_o[2 * dp + 1], pa0, pa1, pa2, pa3, v2, v3);
            }
        }
    }

#pragma unroll
    for (int hh = 0; hh < 2; hh++) {
        float v = psum[hh];
        v += __shfl_xor_sync(0xffffffffu, v, 1);
        v += __shfl_xor_sync(0xffffffffu, v, 2);
        psum[hh] = 1.0f / v;
    }

    // ---- direct-store epilogue: O[q][d] -> d_yh[b][q0+q][h*64+d]
    {
        const int q = 16 * w + r;
        __half* y0 = d_yh + ((size_t)b * NL + q0 + q) * 512 + h * 64;
        __half* y1 = y0 + (size_t)8 * 512;
#pragma unroll
        for (int nd = 0; nd < 8; nd++) {
            int d = 8 * nd + 2 * j;
            *(__half2*)(y0 + d) = __floats2half2_rn(acc_o[nd][0] * psum[0], acc_o[nd][1] * psum[0]);
            *(__half2*)(y1 + d) = __floats2half2_rn(acc_o[nd][2] * psum[1], acc_o[nd][3] * psum[1]);
        }
    }
}

// ---------------------------------------------------------------------------
// BatchNorm: finalize (stats fused into gemm2) + apply
// ---------------------------------------------------------------------------
__global__ void __launch_bounds__(256) bn_finalize()
{
    int c = blockIdx.x * 256 + threadIdx.x;
    float mean = d_bnsum[c] * (1.0f / (NB * NL));
    float var = d_bnsq[c] * (1.0f / (NB * NL)) - mean * mean;
    d_bnmean[c] = mean;
    d_bnrstd[c] = rsqrtf(var + 1e-5f);
}

__global__ void __launch_bounds__(256) bn_apply_kernel(
    const float* __restrict__ gamma, const float* __restrict__ beta,
    float* __restrict__ out)
{
    int i4 = blockIdx.x * 256 + threadIdx.x;
    int c = (i4 >> 9) & (NC - 1);
    float4 v = reinterpret_cast<const float4*>(d_wy)[i4];
    float m = d_bnmean[c], rs = d_bnrstd[c] * gamma[c], bt = beta[c];
    float4 o = make_float4((v.x - m) * rs + bt, (v.y - m) * rs + bt,
                           (v.z - m) * rs + bt, (v.w - m) * rs + bt);
    reinterpret_cast<float4*>(out)[i4] = o;
}

// ---------------------------------------------------------------------------
extern "C" void kernel_launch(void* const* d_in, const int* in_sizes, int n_in,
                              void* d_out, int out_size)
{
    const float* x     = (const float*)d_in[0];
    const float* gw    = (const float*)d_in[1];
    const float* gb    = (const float*)d_in[2];
    const float* tw    = (const float*)d_in[3];
    const float* tb    = (const float*)d_in[4];
    const float* pw    = (const float*)d_in[5];
    const float* pb    = (const float*)d_in[6];
    const float* ww    = (const float*)d_in[7];
    const float* wb    = (const float*)d_in[8];
    const float* gamma = (const float*)d_in[9];
    const float* beta  = (const float*)d_in[10];
    float* out = (float*)d_out;

    cudaFuncSetAttribute(proj_tc, cudaFuncAttributeMaxDynamicSharedMemorySize, DS_SMEM);
    cudaFuncSetAttribute(gemm2_tc, cudaFuncAttributeMaxDynamicSharedMemorySize, DS_SMEM);
    cudaFuncSetAttribute(attn_tc, cudaFuncAttributeMaxDynamicSharedMemorySize, AT_SMEM);

    prep_w<<<1024, 256>>>(gw, tw, pw, ww);
    prep_x<<<dim3(32, 8, 4), 256>>>(x);
    proj_tc<<<dim3(16, 12, 4), 256, DS_SMEM>>>(gb, tb, pb);
    attn_tc<<<dim3(16, 32), 256, AT_SMEM>>>();
    gemm2_tc<<<dim3(16, 4, 4), 256, DS_SMEM>>>(wb);
    bn_finalize<<<2, 256>>>();
    bn_apply_kernel<<<(NB * NC * NL) / 1024, 256>>>(gamma, beta, out);
}

// round 11
// speedup vs baseline: 10.2987x; 1.0200x over previous
#include <cuda_runtime.h>
#include <cuda_fp16.h>
#include <cstdint>
#include <math.h>

#define NB 4
#define NC 512
#define NL 2048
#define NCI 512
#define NH 8
#define ND 64

__device__ __align__(256) __half d_projh[3 * NB * NCI * NL]; // [which][b][ci][l]; theta pre-scaled 0.125*log2e
__device__ __align__(256) __half d_yh[NB * NL * NCI];        // [b][l][ci] f16 (attention out)
__device__ __align__(256) __half d_wh[4 * 512 * 512];        // [m][co][k] f16 weights
__device__ __align__(256) __half d_xh[NB * NL * 512];        // [b][l][ci] f16
__device__ __align__(256) float d_wy[NB * NC * NL];
__device__ float d_bnsum[NC];
__device__ float d_bnsq[NC];
__device__ float d_bnmean[NC];
__device__ float d_bnrstd[NC];

// ---------------- helpers ----------------
__device__ __forceinline__ uint32_t fu(float x) { return __float_as_uint(x); }

__device__ __forceinline__ void hmma(float* c,
                                     uint32_t a0, uint32_t a1, uint32_t a2, uint32_t a3,
                                     uint32_t b0, uint32_t b1) {
    asm("mma.sync.aligned.m16n8k16.row.col.f32.f16.f16.f32 "
        "{%0,%1,%2,%3},{%4,%5,%6,%7},{%8,%9},{%0,%1,%2,%3};"
        : "+f"(c[0]), "+f"(c[1]), "+f"(c[2]), "+f"(c[3])
        : "r"(a0), "r"(a1), "r"(a2), "r"(a3), "r"(b0), "r"(b1));
}
__device__ __forceinline__ void ldsm4(uint32_t& r0, uint32_t& r1, uint32_t& r2, uint32_t& r3,
                                      uint32_t addr) {
    asm volatile("ldmatrix.sync.aligned.m8n8.x4.shared.b16 {%0,%1,%2,%3}, [%4];"
                 : "=r"(r0), "=r"(r1), "=r"(r2), "=r"(r3) : "r"(addr));
}
__device__ __forceinline__ void ldsm4t(uint32_t& r0, uint32_t& r1, uint32_t& r2, uint32_t& r3,
                                       uint32_t addr) {
    asm volatile("ldmatrix.sync.aligned.m8n8.x4.trans.shared.b16 {%0,%1,%2,%3}, [%4];"
                 : "=r"(r0), "=r"(r1), "=r"(r2), "=r"(r3) : "r"(addr));
}
__device__ __forceinline__ uint32_t f2h2(float a, float b) {
    __half2 h = __floats2half2_rn(a, b);
    return *reinterpret_cast<uint32_t*>(&h);
}
// packed half2 exp2: one MUFU op for two elements
__device__ __forceinline__ uint32_t h2ex2(uint32_t x) {
    uint32_t y;
    asm("ex2.approx.f16x2 %0, %1;" : "=r"(y) : "r"(x));
    return y;
}

__device__ __forceinline__ uint32_t smem_u32(const void* p) {
    uint32_t a;
    asm("{ .reg .u64 t; cvta.to.shared.u64 t, %1; cvt.u32.u64 %0, t; }" : "=r"(a) : "l"(p));
    return a;
}
__device__ __forceinline__ void cpa16(uint32_t dst, const void* src) {
    asm volatile("cp.async.ca.shared.global [%0], [%1], 16;" :: "r"(dst), "l"(src));
}
#define CP_COMMIT() asm volatile("cp.async.commit_group;" ::: "memory")
#define CP_WAIT1()  asm volatile("cp.async.wait_group 1;" ::: "memory")
#define CP_WAIT0()  asm volatile("cp.async.wait_group 0;" ::: "memory")

// ---------------------------------------------------------------------------
// Prep kernels: fp32 -> f16 (+ zero BN accumulators)
// ---------------------------------------------------------------------------
__global__ void __launch_bounds__(256) prep_w(
    const float* __restrict__ gw, const float* __restrict__ tw,
    const float* __restrict__ pw, const float* __restrict__ ww)
{
    int gid = blockIdx.x * 256 + threadIdx.x;     // per float4
    if (gid < NC) { d_bnsum[gid] = 0.f; d_bnsq[gid] = 0.f; }
    int m = gid >> 16;
    int rem = gid & 65535;
    const float* src = (m == 0) ? gw : (m == 1) ? tw : (m == 2) ? pw : ww;
    float4 v = *(const float4*)(src + (size_t)rem * 4);
    uint2 o = make_uint2(f2h2(v.x, v.y), f2h2(v.z, v.w));
    *(uint2*)(d_wh + (size_t)m * 262144 + (size_t)rem * 4) = o;
}

// transpose [b][512 ci][2048 l] f32 -> [b][l][ci] f16; grid (32 lt, 8 cit, 4 b)
__global__ void __launch_bounds__(256) prep_x(const float* __restrict__ in)
{
    __shared__ float sm[64][65];
    const int tid = threadIdx.x;
    const int l0 = blockIdx.x * 64, ci0 = blockIdx.y * 64, b = blockIdx.z;
    const float* src = in + (size_t)b * 512 * NL;
    __half* dst = d_xh + (size_t)b * NL * 512;
#pragma unroll
    for (int it = 0; it < 4; it++) {
        int ci = (tid >> 4) + 16 * it;
        int ll = (tid & 15) * 4;
        float4 v = *(const float4*)(src + (size_t)(ci0 + ci) * NL + l0 + ll);
        sm[ci][ll] = v.x; sm[ci][ll + 1] = v.y; sm[ci][ll + 2] = v.z; sm[ci][ll + 3] = v.w;
    }
    __syncthreads();
#pragma unroll
    for (int it = 0; it < 4; it++) {
        int ll = (tid >> 4) + 16 * it;
        int cb = (tid & 15) * 4;
        uint2 o = make_uint2(f2h2(sm[cb][ll], sm[cb + 1][ll]),
                             f2h2(sm[cb + 2][ll], sm[cb + 3][ll]));
        *(uint2*)(dst + (size_t)(l0 + ll) * 512 + ci0 + cb) = o;
    }
}

// ---------------------------------------------------------------------------
// Dense GEMM f16 (2-stage cp.async, ldmatrix, m16n8k16)
// STATS: fused per-channel sum / sum-sq atomics (gemm2 only)
// ---------------------------------------------------------------------------
#define DS_SMEM 65536

__device__ __forceinline__ uint32_t dswz(uint32_t base, int row, int c) {
    return base + row * 128 + ((c ^ (row & 7)) << 4);
}

template <bool HALF_OUT, bool STATS>
__device__ __forceinline__ void gemm_body_f16(
    const __half* __restrict__ Wp,    // offset to co0; row pitch 512
    const __half* __restrict__ Xp,    // [l][512]
    const float* __restrict__ bias,   // offset to co0
    float* __restrict__ outf,
    __half* __restrict__ outh,
    float* __restrict__ bnsum,        // offset to co0 (STATS only)
    float* __restrict__ bnsq,
    float oscale,
    int l0)
{
    extern __shared__ float ds[];
    const uint32_t sb = smem_u32(ds);
    const int tid = threadIdx.x, lane = tid & 31, w = tid >> 5;
    const int wm = w >> 2, wn = w & 3;
    const int lt = lane >> 3, li = lane & 7;
    const int srow = tid >> 1, scp = tid & 1;

    float acc[4][4][4];
#pragma unroll
    for (int i = 0; i < 4; i++)
#pragma unroll
        for (int j = 0; j < 4; j++)
#pragma unroll
            for (int k = 0; k < 4; k++) acc[i][j][k] = 0.f;

#define DISSUE(kt) do { \
    uint32_t bA = sb + ((kt) & 1) * 32768, bB = bA + 16384; \
    const __half* wsrc = Wp + (size_t)srow * 512 + (kt) * 64; \
    const __half* xsrc = Xp + (size_t)(l0 + srow) * 512 + (kt) * 64; \
    _Pragma("unroll") \
    for (int u = 0; u < 4; u++) { \
        int c = scp * 4 + u; \
        cpa16(dswz(bA, srow, c), wsrc + c * 8); \
        cpa16(dswz(bB, srow, c), xsrc + c * 8); \
    } \
    CP_COMMIT(); \
} while (0)

    DISSUE(0); DISSUE(1);

    for (int kt = 0; kt < 8; kt++) {
        if (kt < 7) CP_WAIT1(); else CP_WAIT0();
        __syncthreads();

        const uint32_t bA = sb + (kt & 1) * 32768, bB = bA + 16384;
#pragma unroll
        for (int kc = 0; kc < 4; kc++) {
            uint32_t af[4][4];
#pragma unroll
            for (int im = 0; im < 4; im++) {
                int row = wm * 64 + im * 16 + 8 * (lt & 1) + li;
                int c = 2 * kc + (lt >> 1);
                ldsm4(af[im][0], af[im][1], af[im][2], af[im][3], dswz(bA, row, c));
            }
#pragma unroll
            for (int bt = 0; bt < 2; bt++) {
                uint32_t b0, b1, b2, b3;
                int lrow = wn * 32 + bt * 16 + 8 * (lt >> 1) + li;
                int c = 2 * kc + (lt & 1);
                ldsm4(b0, b1, b2, b3, dswz(bB, lrow, c));
#pragma unroll
                for (int im = 0; im < 4; im++) {
                    hmma(acc[im][2 * bt],     af[im][0], af[im][1], af[im][2], af[im][3], b0, b1);
                    hmma(acc[im][2 * bt + 1], af[im][0], af[im][1], af[im][2], af[im][3], b2, b3);
                }
            }
        }
        __syncthreads();
        if (kt + 2 < 8) DISSUE(kt + 2);
    }
#undef DISSUE

    const int r = lane >> 2, j = lane & 3;
#pragma unroll
    for (int im = 0; im < 4; im++) {
        int row = wm * 64 + im * 16 + r;
        float b0 = bias[row], b1 = bias[row + 8];
        float s0 = 0.f, q0 = 0.f, s1 = 0.f, q1 = 0.f;
#pragma unroll
        for (int nt = 0; nt < 4; nt++) {
            int col = l0 + wn * 32 + nt * 8 + 2 * j;
            float v00 = acc[im][nt][0] + b0, v01 = acc[im][nt][1] + b0;
            float v10 = acc[im][nt][2] + b1, v11 = acc[im][nt][3] + b1;
            if (HALF_OUT) {
                *(__half2*)&outh[(size_t)row * NL + col] =
                    __floats2half2_rn(v00 * oscale, v01 * oscale);
                *(__half2*)&outh[(size_t)(row + 8) * NL + col] =
                    __floats2half2_rn(v10 * oscale, v11 * oscale);
            } else {
                *(float2*)&outf[(size_t)row * NL + col] = make_float2(v00, v01);
                *(float2*)&outf[(size_t)(row + 8) * NL + col] = make_float2(v10, v11);
            }
            if (STATS) {
                s0 += v00 + v01; q0 = fmaf(v00, v00, fmaf(v01, v01, q0));
                s1 += v10 + v11; q1 = fmaf(v10, v10, fmaf(v11, v11, q1));
            }
        }
        if (STATS) {
            s0 += __shfl_xor_sync(0xffffffffu, s0, 1);
            s0 += __shfl_xor_sync(0xffffffffu, s0, 2);
            q0 += __shfl_xor_sync(0xffffffffu, q0, 1);
            q0 += __shfl_xor_sync(0xffffffffu, q0, 2);
            s1 += __shfl_xor_sync(0xffffffffu, s1, 1);
            s1 += __shfl_xor_sync(0xffffffffu, s1, 2);
            q1 += __shfl_xor_sync(0xffffffffu, q1, 1);
            q1 += __shfl_xor_sync(0xffffffffu, q1, 2);
            if (j == 0) {
                atomicAdd(&bnsum[row], s0);
                atomicAdd(&bnsq[row], q0);
                atomicAdd(&bnsum[row + 8], s1);
                atomicAdd(&bnsq[row + 8], q1);
            }
        }
    }
}

__global__ void __launch_bounds__(256) proj_tc(
    const float* __restrict__ gb, const float* __restrict__ tbb, const float* __restrict__ pb)
{
    const int which = blockIdx.y >> 2;
    const int co0 = (blockIdx.y & 3) * 128;
    const int b = blockIdx.z;
    const float* bias = (which == 0 ? gb : which == 1 ? tbb : pb);
    // theta gets 0.125 * log2(e) so attention can use ex2 directly
    gemm_body_f16<true, false>(d_wh + ((size_t)which * 512 + co0) * 512,
                               d_xh + (size_t)b * NL * 512,
                               bias + co0,
                               nullptr,
                               d_projh + ((size_t)which * NB + b) * NCI * NL + (size_t)co0 * NL,
                               nullptr, nullptr,
                               which == 1 ? 0.18033688f : 1.0f,
                               blockIdx.x * 128);
}

__global__ void __launch_bounds__(256) gemm2_tc(const float* __restrict__ wb)
{
    const int co0 = blockIdx.y * 128;
    const int b = blockIdx.z;
    gemm_body_f16<false, true>(d_wh + ((size_t)3 * 512 + co0) * 512,
                               d_yh + (size_t)b * NL * 512,
                               wb + co0,
                               d_wy + (size_t)b * NC * NL + (size_t)co0 * NL,
                               nullptr,
                               d_bnsum + co0, d_bnsq + co0,
                               1.0f, blockIdx.x * 128);
}

// ---------------------------------------------------------------------------
// Attention: f16 m16n8k16, cp.async double-buffered K/V, hoisted Q fragments,
// packed f16x2 ex2 (half the MUFU ops), row-sums via ones-HMMA (no FADD/shuffles)
// ---------------------------------------------------------------------------
#define AT_SMEM 49152

__device__ __forceinline__ uint32_t qswz(uint32_t base, int d, int qblk) {
    return base + d * 256 + ((qblk ^ (d & 7)) << 4);
}
__device__ __forceinline__ uint32_t kswz(uint32_t base, int d, int cblk) {
    return base + d * 128 + ((cblk ^ (d & 7)) << 4);
}

__global__ void __launch_bounds__(256, 2) attn_tc()
{
    extern __shared__ char smc[];
    const uint32_t sb = smem_u32(smc);
    const uint32_t Qb = sb, Kb = sb + 16384, Vb = sb + 32768;

    const int tid = threadIdx.x, lane = tid & 31, w = tid >> 5;
    const int r = lane >> 2, j = lane & 3;
    const int lt = lane >> 3, li = lane & 7;
    const int q0 = blockIdx.x * 128;
    const int b = blockIdx.y >> 3, h = blockIdx.y & 7;

    const __half* thetah = d_projh + ((size_t)(1 * NB + b) * NCI + h * ND) * NL;
    const __half* phih   = d_projh + ((size_t)(2 * NB + b) * NCI + h * ND) * NL;
    const __half* gxh    = d_projh + ((size_t)(0 * NB + b) * NCI + h * ND) * NL;

    const int srow = tid >> 2;
    const int scix = tid & 3;

#pragma unroll
    for (int u = 0; u < 4; u++) {
        int ch = scix + 4 * u;
        cpa16(qswz(Qb, srow, ch), thetah + (size_t)srow * NL + q0 + ch * 8);
    }
#pragma unroll
    for (int u = 0; u < 2; u++) {
        int ch = scix + 4 * u;
        cpa16(kswz(Kb, srow, ch), phih + (size_t)srow * NL + ch * 8);
        cpa16(kswz(Vb, srow, ch), gxh + (size_t)srow * NL + ch * 8);
    }
    CP_COMMIT();

    const uint32_t ONES = 0x3C003C00u;   // half2(1.0, 1.0)
    uint32_t qf[4][4];                   // hoisted Q fragments
    float acc_o[8][4];
    float acc_l[4];                      // row sums via ones-HMMA
#pragma unroll
    for (int n = 0; n < 8; n++)
#pragma unroll
        for (int k = 0; k < 4; k++) acc_o[n][k] = 0.f;
#pragma unroll
    for (int k = 0; k < 4; k++) acc_l[k] = 0.f;

    for (int it = 0; it < 32; it++) {
        __syncthreads();
        if (it + 1 < 32) {
            const int nb_ = (it + 1) & 1;
            const size_t kko = (size_t)(it + 1) * 64;
#pragma unroll
            for (int u = 0; u < 2; u++) {
                int ch = scix + 4 * u;
                cpa16(kswz(Kb + nb_ * 8192, srow, ch), phih + (size_t)srow * NL + kko + ch * 8);
                cpa16(kswz(Vb + nb_ * 8192, srow, ch), gxh + (size_t)srow * NL + kko + ch * 8);
            }
            CP_COMMIT();
            CP_WAIT1();
        } else {
            CP_WAIT0();
        }
        __syncthreads();

        if (it == 0) {
#pragma unroll
            for (int s = 0; s < 4; s++) {
                int d = 16 * s + 8 * (lt >> 1) + li;
                int qblk = 2 * w + (lt & 1);
                ldsm4t(qf[s][0], qf[s][1], qf[s][2], qf[s][3], qswz(Qb, d, qblk));
            }
        }

        const uint32_t Kc = Kb + (it & 1) * 8192;
        const uint32_t Vc = Vb + (it & 1) * 8192;

        // ---- QK: S[16q][64kk]  (S is already in log2 units)
        float s_acc[8][4];
#pragma unroll
        for (int n = 0; n < 8; n++)
#pragma unroll
            for (int k = 0; k < 4; k++) s_acc[n][k] = 0.f;

#pragma unroll
        for (int s = 0; s < 4; s++) {
#pragma unroll
            for (int np = 0; np < 4; np++) {
                uint32_t k0, k1, k2, k3;
                int d = 16 * s + 8 * (lt & 1) + li;
                int cb = 2 * np + (lt >> 1);
                ldsm4t(k0, k1, k2, k3, kswz(Kc, d, cb));
                hmma(s_acc[2 * np],     qf[s][0], qf[s][1], qf[s][2], qf[s][3], k0, k1);
                hmma(s_acc[2 * np + 1], qf[s][0], qf[s][1], qf[s][2], qf[s][3], k2, k3);
            }
        }

        // ---- packed exp (f16x2 MUFU) + rowsum-HMMA + PV, interleaved per sv
#pragma unroll
        for (int sv = 0; sv < 4; sv++) {
            uint32_t pa0 = h2ex2(f2h2(s_acc[2 * sv][0],     s_acc[2 * sv][1]));
            uint32_t pa1 = h2ex2(f2h2(s_acc[2 * sv][2],     s_acc[2 * sv][3]));
            uint32_t pa2 = h2ex2(f2h2(s_acc[2 * sv + 1][0], s_acc[2 * sv + 1][1]));
            uint32_t pa3 = h2ex2(f2h2(s_acc[2 * sv + 1][2], s_acc[2 * sv + 1][3]));
            hmma(acc_l, pa0, pa1, pa2, pa3, ONES, ONES);   // row sums of this k16 slab
#pragma unroll
            for (int dp = 0; dp < 4; dp++) {
                uint32_t v0, v1, v2, v3;
                int d = 16 * dp + 8 * (lt >> 1) + li;
                int cb = 2 * sv + (lt & 1);
                ldsm4(v0, v1, v2, v3, kswz(Vc, d, cb));
                hmma(acc_o[2 * dp],     pa0, pa1, pa2, pa3, v0, v1);
                hmma(acc_o[2 * dp + 1], pa0, pa1, pa2, pa3, v2, v3);
            }
        }
    }

    // acc_l: c0 = rowsum(q=16w+r), c2 = rowsum(q+8) — identical in all lanes/cols
    const float inv0 = 1.0f / acc_l[0];
    const float inv1 = 1.0f / acc_l[2];

    // ---- direct-store epilogue: O[q][d] -> d_yh[b][q0+q][h*64+d]
    {
        const int q = 16 * w + r;
        __half* y0 = d_yh + ((size_t)b * NL + q0 + q) * 512 + h * 64;
        __half* y1 = y0 + (size_t)8 * 512;
#pragma unroll
        for (int nd = 0; nd < 8; nd++) {
            int d = 8 * nd + 2 * j;
            *(__half2*)(y0 + d) = __floats2half2_rn(acc_o[nd][0] * inv0, acc_o[nd][1] * inv0);
            *(__half2*)(y1 + d) = __floats2half2_rn(acc_o[nd][2] * inv1, acc_o[nd][3] * inv1);
        }
    }
}

// ---------------------------------------------------------------------------
// BatchNorm: finalize (stats fused into gemm2) + apply
// ---------------------------------------------------------------------------
__global__ void __launch_bounds__(256) bn_finalize()
{
    int c = blockIdx.x * 256 + threadIdx.x;
    float mean = d_bnsum[c] * (1.0f / (NB * NL));
    float var = d_bnsq[c] * (1.0f / (NB * NL)) - mean * mean;
    d_bnmean[c] = mean;
    d_bnrstd[c] = rsqrtf(var + 1e-5f);
}

__global__ void __launch_bounds__(256) bn_apply_kernel(
    const float* __restrict__ gamma, const float* __restrict__ beta,
    float* __restrict__ out)
{
    int i4 = blockIdx.x * 256 + threadIdx.x;
    int c = (i4 >> 9) & (NC - 1);
    float4 v = reinterpret_cast<const float4*>(d_wy)[i4];
    float m = d_bnmean[c], rs = d_bnrstd[c] * gamma[c], bt = beta[c];
    float4 o = make_float4((v.x - m) * rs + bt, (v.y - m) * rs + bt,
                           (v.z - m) * rs + bt, (v.w - m) * rs + bt);
    reinterpret_cast<float4*>(out)[i4] = o;
}

// ---------------------------------------------------------------------------
extern "C" void kernel_launch(void* const* d_in, const int* in_sizes, int n_in,
                              void* d_out, int out_size)
{
    const float* x     = (const float*)d_in[0];
    const float* gw    = (const float*)d_in[1];
    const float* gb    = (const float*)d_in[2];
    const float* tw    = (const float*)d_in[3];
    const float* tb    = (const float*)d_in[4];
    const float* pw    = (const float*)d_in[5];
    const float* pb    = (const float*)d_in[6];
    const float* ww    = (const float*)d_in[7];
    const float* wb    = (const float*)d_in[8];
    const float* gamma = (const float*)d_in[9];
    const float* beta  = (const float*)d_in[10];
    float* out = (float*)d_out;

    cudaFuncSetAttribute(proj_tc, cudaFuncAttributeMaxDynamicSharedMemorySize, DS_SMEM);
    cudaFuncSetAttribute(gemm2_tc, cudaFuncAttributeMaxDynamicSharedMemorySize, DS_SMEM);
    cudaFuncSetAttribute(attn_tc, cudaFuncAttributeMaxDynamicSharedMemorySize, AT_SMEM);

    prep_w<<<1024, 256>>>(gw, tw, pw, ww);
    prep_x<<<dim3(32, 8, 4), 256>>>(x);
    proj_tc<<<dim3(16, 12, 4), 256, DS_SMEM>>>(gb, tb, pb);
    attn_tc<<<dim3(16, 32), 256, AT_SMEM>>>();
    gemm2_tc<<<dim3(16, 4, 4), 256, DS_SMEM>>>(wb);
    bn_finalize<<<2, 256>>>();
    bn_apply_kernel<<<(NB * NC * NL) / 1024, 256>>>(gamma, beta, out);
}

// round 12
// speedup vs baseline: 10.9293x; 1.0612x over previous
#include <cuda_runtime.h>
#include <cuda_fp16.h>
#include <cstdint>
#include <math.h>

#define NB 4
#define NC 512
#define NL 2048
#define NCI 512
#define NH 8
#define ND 64

__device__ __align__(256) __half d_projh[3 * NB * NCI * NL]; // [which][b][ci][l]; theta pre-scaled 0.125*log2e
__device__ __align__(256) __half d_yh[NB * NL * NCI];        // [b][l][ci] f16 (attention out)
__device__ __align__(256) __half d_wh[4 * 512 * 512];        // [m][co][k] f16 weights
__device__ __align__(256) __half d_xh[NB * NL * 512];        // [b][l][ci] f16
__device__ __align__(256) float d_wy[NB * NC * NL];
__device__ float d_bnsum[NC];
__device__ float d_bnsq[NC];
__device__ float d_bnmean[NC];
__device__ float d_bnrstd[NC];

// ---------------- helpers ----------------
__device__ __forceinline__ uint32_t fu(float x) { return __float_as_uint(x); }

__device__ __forceinline__ void hmma(float* c,
                                     uint32_t a0, uint32_t a1, uint32_t a2, uint32_t a3,
                                     uint32_t b0, uint32_t b1) {
    asm("mma.sync.aligned.m16n8k16.row.col.f32.f16.f16.f32 "
        "{%0,%1,%2,%3},{%4,%5,%6,%7},{%8,%9},{%0,%1,%2,%3};"
        : "+f"(c[0]), "+f"(c[1]), "+f"(c[2]), "+f"(c[3])
        : "r"(a0), "r"(a1), "r"(a2), "r"(a3), "r"(b0), "r"(b1));
}
__device__ __forceinline__ void ldsm4(uint32_t& r0, uint32_t& r1, uint32_t& r2, uint32_t& r3,
                                      uint32_t addr) {
    asm volatile("ldmatrix.sync.aligned.m8n8.x4.shared.b16 {%0,%1,%2,%3}, [%4];"
                 : "=r"(r0), "=r"(r1), "=r"(r2), "=r"(r3) : "r"(addr));
}
__device__ __forceinline__ void ldsm4t(uint32_t& r0, uint32_t& r1, uint32_t& r2, uint32_t& r3,
                                       uint32_t addr) {
    asm volatile("ldmatrix.sync.aligned.m8n8.x4.trans.shared.b16 {%0,%1,%2,%3}, [%4];"
                 : "=r"(r0), "=r"(r1), "=r"(r2), "=r"(r3) : "r"(addr));
}
__device__ __forceinline__ uint32_t f2h2(float a, float b) {
    __half2 h = __floats2half2_rn(a, b);
    return *reinterpret_cast<uint32_t*>(&h);
}
// packed half2 exp2: one MUFU op for two elements
__device__ __forceinline__ uint32_t h2ex2(uint32_t x) {
    uint32_t y;
    asm("ex2.approx.f16x2 %0, %1;" : "=r"(y) : "r"(x));
    return y;
}

__device__ __forceinline__ uint32_t smem_u32(const void* p) {
    uint32_t a;
    asm("{ .reg .u64 t; cvta.to.shared.u64 t, %1; cvt.u32.u64 %0, t; }" : "=r"(a) : "l"(p));
    return a;
}
__device__ __forceinline__ void cpa16(uint32_t dst, const void* src) {
    asm volatile("cp.async.ca.shared.global [%0], [%1], 16;" :: "r"(dst), "l"(src));
}
#define CP_COMMIT() asm volatile("cp.async.commit_group;" ::: "memory")
#define CP_WAIT1()  asm volatile("cp.async.wait_group 1;" ::: "memory")
#define CP_WAIT0()  asm volatile("cp.async.wait_group 0;" ::: "memory")

// ---------------------------------------------------------------------------
// Prep kernels: fp32 -> f16 (+ zero BN accumulators)
// ---------------------------------------------------------------------------
__global__ void __launch_bounds__(256) prep_w(
    const float* __restrict__ gw, const float* __restrict__ tw,
    const float* __restrict__ pw, const float* __restrict__ ww)
{
    int gid = blockIdx.x * 256 + threadIdx.x;     // per float4
    if (gid < NC) { d_bnsum[gid] = 0.f; d_bnsq[gid] = 0.f; }
    int m = gid >> 16;
    int rem = gid & 65535;
    const float* src = (m == 0) ? gw : (m == 1) ? tw : (m == 2) ? pw : ww;
    float4 v = *(const float4*)(src + (size_t)rem * 4);
    uint2 o = make_uint2(f2h2(v.x, v.y), f2h2(v.z, v.w));
    *(uint2*)(d_wh + (size_t)m * 262144 + (size_t)rem * 4) = o;
}

// transpose [b][512 ci][2048 l] f32 -> [b][l][ci] f16; grid (32 lt, 8 cit, 4 b)
__global__ void __launch_bounds__(256) prep_x(const float* __restrict__ in)
{
    __shared__ float sm[64][65];
    const int tid = threadIdx.x;
    const int l0 = blockIdx.x * 64, ci0 = blockIdx.y * 64, b = blockIdx.z;
    const float* src = in + (size_t)b * 512 * NL;
    __half* dst = d_xh + (size_t)b * NL * 512;
#pragma unroll
    for (int it = 0; it < 4; it++) {
        int ci = (tid >> 4) + 16 * it;
        int ll = (tid & 15) * 4;
        float4 v = *(const float4*)(src + (size_t)(ci0 + ci) * NL + l0 + ll);
        sm[ci][ll] = v.x; sm[ci][ll + 1] = v.y; sm[ci][ll + 2] = v.z; sm[ci][ll + 3] = v.w;
    }
    __syncthreads();
#pragma unroll
    for (int it = 0; it < 4; it++) {
        int ll = (tid >> 4) + 16 * it;
        int cb = (tid & 15) * 4;
        uint2 o = make_uint2(f2h2(sm[cb][ll], sm[cb + 1][ll]),
                             f2h2(sm[cb + 2][ll], sm[cb + 3][ll]));
        *(uint2*)(dst + (size_t)(l0 + ll) * 512 + ci0 + cb) = o;
    }
}

// ---------------------------------------------------------------------------
// Dense GEMM f16 (2-stage cp.async, ldmatrix, m16n8k16)
// STATS: fused per-channel sum / sum-sq atomics (gemm2 only)
// ---------------------------------------------------------------------------
#define DS_SMEM 65536

__device__ __forceinline__ uint32_t dswz(uint32_t base, int row, int c) {
    return base + row * 128 + ((c ^ (row & 7)) << 4);
}

template <bool HALF_OUT, bool STATS>
__device__ __forceinline__ void gemm_body_f16(
    const __half* __restrict__ Wp,    // offset to co0; row pitch 512
    const __half* __restrict__ Xp,    // [l][512]
    const float* __restrict__ bias,   // offset to co0
    float* __restrict__ outf,
    __half* __restrict__ outh,
    float* __restrict__ bnsum,        // offset to co0 (STATS only)
    float* __restrict__ bnsq,
    float oscale,
    int l0)
{
    extern __shared__ float ds[];
    const uint32_t sb = smem_u32(ds);
    const int tid = threadIdx.x, lane = tid & 31, w = tid >> 5;
    const int wm = w >> 2, wn = w & 3;
    const int lt = lane >> 3, li = lane & 7;
    const int srow = tid >> 1, scp = tid & 1;

    float acc[4][4][4];
#pragma unroll
    for (int i = 0; i < 4; i++)
#pragma unroll
        for (int j = 0; j < 4; j++)
#pragma unroll
            for (int k = 0; k < 4; k++) acc[i][j][k] = 0.f;

#define DISSUE(kt) do { \
    uint32_t bA = sb + ((kt) & 1) * 32768, bB = bA + 16384; \
    const __half* wsrc = Wp + (size_t)srow * 512 + (kt) * 64; \
    const __half* xsrc = Xp + (size_t)(l0 + srow) * 512 + (kt) * 64; \
    _Pragma("unroll") \
    for (int u = 0; u < 4; u++) { \
        int c = scp * 4 + u; \
        cpa16(dswz(bA, srow, c), wsrc + c * 8); \
        cpa16(dswz(bB, srow, c), xsrc + c * 8); \
    } \
    CP_COMMIT(); \
} while (0)

    DISSUE(0); DISSUE(1);

    for (int kt = 0; kt < 8; kt++) {
        if (kt < 7) CP_WAIT1(); else CP_WAIT0();
        __syncthreads();

        const uint32_t bA = sb + (kt & 1) * 32768, bB = bA + 16384;
#pragma unroll
        for (int kc = 0; kc < 4; kc++) {
            uint32_t af[4][4];
#pragma unroll
            for (int im = 0; im < 4; im++) {
                int row = wm * 64 + im * 16 + 8 * (lt & 1) + li;
                int c = 2 * kc + (lt >> 1);
                ldsm4(af[im][0], af[im][1], af[im][2], af[im][3], dswz(bA, row, c));
            }
#pragma unroll
            for (int bt = 0; bt < 2; bt++) {
                uint32_t b0, b1, b2, b3;
                int lrow = wn * 32 + bt * 16 + 8 * (lt >> 1) + li;
                int c = 2 * kc + (lt & 1);
                ldsm4(b0, b1, b2, b3, dswz(bB, lrow, c));
#pragma unroll
                for (int im = 0; im < 4; im++) {
                    hmma(acc[im][2 * bt],     af[im][0], af[im][1], af[im][2], af[im][3], b0, b1);
                    hmma(acc[im][2 * bt + 1], af[im][0], af[im][1], af[im][2], af[im][3], b2, b3);
                }
            }
        }
        __syncthreads();
        if (kt + 2 < 8) DISSUE(kt + 2);
    }
#undef DISSUE

    const int r = lane >> 2, j = lane & 3;
#pragma unroll
    for (int im = 0; im < 4; im++) {
        int row = wm * 64 + im * 16 + r;
        float b0 = bias[row], b1 = bias[row + 8];
        float s0 = 0.f, q0 = 0.f, s1 = 0.f, q1 = 0.f;
#pragma unroll
        for (int nt = 0; nt < 4; nt++) {
            int col = l0 + wn * 32 + nt * 8 + 2 * j;
            float v00 = acc[im][nt][0] + b0, v01 = acc[im][nt][1] + b0;
            float v10 = acc[im][nt][2] + b1, v11 = acc[im][nt][3] + b1;
            if (HALF_OUT) {
                *(__half2*)&outh[(size_t)row * NL + col] =
                    __floats2half2_rn(v00 * oscale, v01 * oscale);
                *(__half2*)&outh[(size_t)(row + 8) * NL + col] =
                    __floats2half2_rn(v10 * oscale, v11 * oscale);
            } else {
                *(float2*)&outf[(size_t)row * NL + col] = make_float2(v00, v01);
                *(float2*)&outf[(size_t)(row + 8) * NL + col] = make_float2(v10, v11);
            }
            if (STATS) {
                s0 += v00 + v01; q0 = fmaf(v00, v00, fmaf(v01, v01, q0));
                s1 += v10 + v11; q1 = fmaf(v10, v10, fmaf(v11, v11, q1));
            }
        }
        if (STATS) {
            s0 += __shfl_xor_sync(0xffffffffu, s0, 1);
            s0 += __shfl_xor_sync(0xffffffffu, s0, 2);
            q0 += __shfl_xor_sync(0xffffffffu, q0, 1);
            q0 += __shfl_xor_sync(0xffffffffu, q0, 2);
            s1 += __shfl_xor_sync(0xffffffffu, s1, 1);
            s1 += __shfl_xor_sync(0xffffffffu, s1, 2);
            q1 += __shfl_xor_sync(0xffffffffu, q1, 1);
            q1 += __shfl_xor_sync(0xffffffffu, q1, 2);
            if (j == 0) {
                atomicAdd(&bnsum[row], s0);
                atomicAdd(&bnsq[row], q0);
                atomicAdd(&bnsum[row + 8], s1);
                atomicAdd(&bnsq[row + 8], q1);
            }
        }
    }
}

__global__ void __launch_bounds__(256) proj_tc(
    const float* __restrict__ gb, const float* __restrict__ tbb, const float* __restrict__ pb)
{
    const int which = blockIdx.y >> 2;
    const int co0 = (blockIdx.y & 3) * 128;
    const int b = blockIdx.z;
    const float* bias = (which == 0 ? gb : which == 1 ? tbb : pb);
    // theta gets 0.125 * log2(e) so attention can use ex2 directly
    gemm_body_f16<true, false>(d_wh + ((size_t)which * 512 + co0) * 512,
                               d_xh + (size_t)b * NL * 512,
                               bias + co0,
                               nullptr,
                               d_projh + ((size_t)which * NB + b) * NCI * NL + (size_t)co0 * NL,
                               nullptr, nullptr,
                               which == 1 ? 0.18033688f : 1.0f,
                               blockIdx.x * 128);
}

__global__ void __launch_bounds__(256) gemm2_tc(const float* __restrict__ wb)
{
    const int co0 = blockIdx.y * 128;
    const int b = blockIdx.z;
    gemm_body_f16<false, true>(d_wh + ((size_t)3 * 512 + co0) * 512,
                               d_yh + (size_t)b * NL * 512,
                               wb + co0,
                               d_wy + (size_t)b * NC * NL + (size_t)co0 * NL,
                               nullptr,
                               d_bnsum + co0, d_bnsq + co0,
                               1.0f, blockIdx.x * 128);
}

// ---------------------------------------------------------------------------
// Attention v6: 4 warps x 32q (2 m-tiles/warp) — K/V fragments amortized over
// 2x the MACs (ldsm-per-MAC halved). 128-thread CTAs, 2 CTAs/SM.
// f16 m16n8k16, cp.async double-buffered K/V, hoisted Q frags, f16x2 ex2,
// row sums via ones-HMMA.
// ---------------------------------------------------------------------------
#define AT_SMEM 49152

__device__ __forceinline__ uint32_t qswz(uint32_t base, int d, int qblk) {
    return base + d * 256 + ((qblk ^ (d & 7)) << 4);
}
__device__ __forceinline__ uint32_t kswz(uint32_t base, int d, int cblk) {
    return base + d * 128 + ((cblk ^ (d & 7)) << 4);
}

__global__ void __launch_bounds__(128, 2) attn_tc()
{
    extern __shared__ char smc[];
    const uint32_t sb = smem_u32(smc);
    const uint32_t Qb = sb, Kb = sb + 16384, Vb = sb + 32768;

    const int tid = threadIdx.x, lane = tid & 31, w = tid >> 5;   // w in 0..3
    const int r = lane >> 2, j = lane & 3;
    const int lt = lane >> 3, li = lane & 7;
    const int q0 = blockIdx.x * 128;
    const int b = blockIdx.y >> 3, h = blockIdx.y & 7;

    const __half* thetah = d_projh + ((size_t)(1 * NB + b) * NCI + h * ND) * NL;
    const __half* phih   = d_projh + ((size_t)(2 * NB + b) * NCI + h * ND) * NL;
    const __half* gxh    = d_projh + ((size_t)(0 * NB + b) * NCI + h * ND) * NL;

    const int srow = tid >> 1;      // staging d row (0..63)
    const int shalf = tid & 1;

    // ---- stage Q (8 chunks/thread) + tile 0 of K/V (4 chunks each)
#pragma unroll
    for (int u = 0; u < 8; u++) {
        int ch = shalf * 8 + u;
        cpa16(qswz(Qb, srow, ch), thetah + (size_t)srow * NL + q0 + ch * 8);
    }
#pragma unroll
    for (int u = 0; u < 4; u++) {
        int ch = shalf * 4 + u;
        cpa16(kswz(Kb, srow, ch), phih + (size_t)srow * NL + ch * 8);
        cpa16(kswz(Vb, srow, ch), gxh + (size_t)srow * NL + ch * 8);
    }
    CP_COMMIT();

    const uint32_t ONES = 0x3C003C00u;
    uint32_t qf[2][4][4];            // hoisted Q fragments, 2 m-tiles
    float acc_o[2][8][4];
    float acc_l[2][4];
#pragma unroll
    for (int m = 0; m < 2; m++) {
#pragma unroll
        for (int n = 0; n < 8; n++)
#pragma unroll
            for (int k = 0; k < 4; k++) acc_o[m][n][k] = 0.f;
#pragma unroll
        for (int k = 0; k < 4; k++) acc_l[m][k] = 0.f;
    }

    for (int it = 0; it < 32; it++) {
        __syncthreads();
        if (it + 1 < 32) {
            const int nb_ = (it + 1) & 1;
            const size_t kko = (size_t)(it + 1) * 64;
#pragma unroll
            for (int u = 0; u < 4; u++) {
                int ch = shalf * 4 + u;
                cpa16(kswz(Kb + nb_ * 8192, srow, ch), phih + (size_t)srow * NL + kko + ch * 8);
                cpa16(kswz(Vb + nb_ * 8192, srow, ch), gxh + (size_t)srow * NL + kko + ch * 8);
            }
            CP_COMMIT();
            CP_WAIT1();
        } else {
            CP_WAIT0();
        }
        __syncthreads();

        if (it == 0) {
#pragma unroll
            for (int m = 0; m < 2; m++)
#pragma unroll
                for (int s = 0; s < 4; s++) {
                    int d = 16 * s + 8 * (lt >> 1) + li;
                    int qblk = 4 * w + 2 * m + (lt & 1);
                    ldsm4t(qf[m][s][0], qf[m][s][1], qf[m][s][2], qf[m][s][3], qswz(Qb, d, qblk));
                }
        }

        const uint32_t Kc = Kb + (it & 1) * 8192;
        const uint32_t Vc = Vb + (it & 1) * 8192;

        // ---- QK: S[32q][64kk]; K fragments shared across both m-tiles
        float s_acc[2][8][4];
#pragma unroll
        for (int m = 0; m < 2; m++)
#pragma unroll
            for (int n = 0; n < 8; n++)
#pragma unroll
                for (int k = 0; k < 4; k++) s_acc[m][n][k] = 0.f;

#pragma unroll
        for (int s = 0; s < 4; s++) {
#pragma unroll
            for (int np = 0; np < 4; np++) {
                uint32_t k0, k1, k2, k3;
                int d = 16 * s + 8 * (lt & 1) + li;
                int cb = 2 * np + (lt >> 1);
                ldsm4t(k0, k1, k2, k3, kswz(Kc, d, cb));
#pragma unroll
                for (int m = 0; m < 2; m++) {
                    hmma(s_acc[m][2 * np],     qf[m][s][0], qf[m][s][1], qf[m][s][2], qf[m][s][3], k0, k1);
                    hmma(s_acc[m][2 * np + 1], qf[m][s][0], qf[m][s][1], qf[m][s][2], qf[m][s][3], k2, k3);
                }
            }
        }

        // ---- packed exp + rowsum-HMMA + PV; V fragments shared across m-tiles
#pragma unroll
        for (int sv = 0; sv < 4; sv++) {
            uint32_t pa[2][4];
#pragma unroll
            for (int m = 0; m < 2; m++) {
                pa[m][0] = h2ex2(f2h2(s_acc[m][2 * sv][0],     s_acc[m][2 * sv][1]));
                pa[m][1] = h2ex2(f2h2(s_acc[m][2 * sv][2],     s_acc[m][2 * sv][3]));
                pa[m][2] = h2ex2(f2h2(s_acc[m][2 * sv + 1][0], s_acc[m][2 * sv + 1][1]));
                pa[m][3] = h2ex2(f2h2(s_acc[m][2 * sv + 1][2], s_acc[m][2 * sv + 1][3]));
                hmma(acc_l[m], pa[m][0], pa[m][1], pa[m][2], pa[m][3], ONES, ONES);
            }
#pragma unroll
            for (int dp = 0; dp < 4; dp++) {
                uint32_t v0, v1, v2, v3;
                int d = 16 * dp + 8 * (lt >> 1) + li;
                int cb = 2 * sv + (lt & 1);
                ldsm4(v0, v1, v2, v3, kswz(Vc, d, cb));
#pragma unroll
                for (int m = 0; m < 2; m++) {
                    hmma(acc_o[m][2 * dp],     pa[m][0], pa[m][1], pa[m][2], pa[m][3], v0, v1);
                    hmma(acc_o[m][2 * dp + 1], pa[m][0], pa[m][1], pa[m][2], pa[m][3], v2, v3);
                }
            }
        }
    }

    // ---- epilogue: normalize + direct store O[q][d] -> d_yh[b][q0+q][h*64+d]
#pragma unroll
    for (int m = 0; m < 2; m++) {
        const float inv0 = 1.0f / acc_l[m][0];
        const float inv1 = 1.0f / acc_l[m][2];
        const int q = 32 * w + 16 * m + r;
        __half* y0 = d_yh + ((size_t)b * NL + q0 + q) * 512 + h * 64;
        __half* y1 = y0 + (size_t)8 * 512;
#pragma unroll
        for (int nd = 0; nd < 8; nd++) {
            int d = 8 * nd + 2 * j;
            *(__half2*)(y0 + d) = __floats2half2_rn(acc_o[m][nd][0] * inv0, acc_o[m][nd][1] * inv0);
            *(__half2*)(y1 + d) = __floats2half2_rn(acc_o[m][nd][2] * inv1, acc_o[m][nd][3] * inv1);
        }
    }
}

// ---------------------------------------------------------------------------
// BatchNorm: finalize (stats fused into gemm2) + apply
// ---------------------------------------------------------------------------
__global__ void __launch_bounds__(256) bn_finalize()
{
    int c = blockIdx.x * 256 + threadIdx.x;
    float mean = d_bnsum[c] * (1.0f / (NB * NL));
    float var = d_bnsq[c] * (1.0f / (NB * NL)) - mean * mean;
    d_bnmean[c] = mean;
    d_bnrstd[c] = rsqrtf(var + 1e-5f);
}

__global__ void __launch_bounds__(256) bn_apply_kernel(
    const float* __restrict__ gamma, const float* __restrict__ beta,
    float* __restrict__ out)
{
    int i4 = blockIdx.x * 256 + threadIdx.x;
    int c = (i4 >> 9) & (NC - 1);
    float4 v = reinterpret_cast<const float4*>(d_wy)[i4];
    float m = d_bnmean[c], rs = d_bnrstd[c] * gamma[c], bt = beta[c];
    float4 o = make_float4((v.x - m) * rs + bt, (v.y - m) * rs + bt,
                           (v.z - m) * rs + bt, (v.w - m) * rs + bt);
    reinterpret_cast<float4*>(out)[i4] = o;
}

// ---------------------------------------------------------------------------
extern "C" void kernel_launch(void* const* d_in, const int* in_sizes, int n_in,
                              void* d_out, int out_size)
{
    const float* x     = (const float*)d_in[0];
    const float* gw    = (const float*)d_in[1];
    const float* gb    = (const float*)d_in[2];
    const float* tw    = (const float*)d_in[3];
    const float* tb    = (const float*)d_in[4];
    const float* pw    = (const float*)d_in[5];
    const float* pb    = (const float*)d_in[6];
    const float* ww    = (const float*)d_in[7];
    const float* wb    = (const float*)d_in[8];
    const float* gamma = (const float*)d_in[9];
    const float* beta  = (const float*)d_in[10];
    float* out = (float*)d_out;

    cudaFuncSetAttribute(proj_tc, cudaFuncAttributeMaxDynamicSharedMemorySize, DS_SMEM);
    cudaFuncSetAttribute(gemm2_tc, cudaFuncAttributeMaxDynamicSharedMemorySize, DS_SMEM);
    cudaFuncSetAttribute(attn_tc, cudaFuncAttributeMaxDynamicSharedMemorySize, AT_SMEM);

    prep_w<<<1024, 256>>>(gw, tw, pw, ww);
    prep_x<<<dim3(32, 8, 4), 256>>>(x);
    proj_tc<<<dim3(16, 12, 4), 256, DS_SMEM>>>(gb, tb, pb);
    attn_tc<<<dim3(16, 32), 128, AT_SMEM>>>();
    gemm2_tc<<<dim3(16, 4, 4), 256, DS_SMEM>>>(wb);
    bn_finalize<<<2, 256>>>();
    bn_apply_kernel<<<(NB * NC * NL) / 1024, 256>>>(gamma, beta, out);
}

// round 13
// speedup vs baseline: 10.9837x; 1.0050x over previous
#include <cuda_runtime.h>
#include <cuda_fp16.h>
#include <cstdint>
#include <math.h>

#define NB 4
#define NC 512
#define NL 2048
#define NCI 512
#define NH 8
#define ND 64

__device__ __align__(256) __half d_projh[3 * NB * NCI * NL]; // [which][b][ci][l]; theta pre-scaled 0.125*log2e
__device__ __align__(256) __half d_yh[NB * NL * NCI];        // [b][l][ci] f16 (attention out)
__device__ __align__(256) __half d_wh[4 * 512 * 512];        // [m][co][k] f16 weights
__device__ __align__(256) __half d_xh[NB * NL * 512];        // [b][l][ci] f16
__device__ __align__(256) float d_wy[NB * NC * NL];
__device__ float d_bnsum[NC];
__device__ float d_bnsq[NC];
__device__ float d_bnmean[NC];
__device__ float d_bnrstd[NC];

// ---------------- helpers ----------------
__device__ __forceinline__ uint32_t fu(float x) { return __float_as_uint(x); }

__device__ __forceinline__ void hmma(float* c,
                                     uint32_t a0, uint32_t a1, uint32_t a2, uint32_t a3,
                                     uint32_t b0, uint32_t b1) {
    asm("mma.sync.aligned.m16n8k16.row.col.f32.f16.f16.f32 "
        "{%0,%1,%2,%3},{%4,%5,%6,%7},{%8,%9},{%0,%1,%2,%3};"
        : "+f"(c[0]), "+f"(c[1]), "+f"(c[2]), "+f"(c[3])
        : "r"(a0), "r"(a1), "r"(a2), "r"(a3), "r"(b0), "r"(b1));
}
__device__ __forceinline__ void ldsm4(uint32_t& r0, uint32_t& r1, uint32_t& r2, uint32_t& r3,
                                      uint32_t addr) {
    asm volatile("ldmatrix.sync.aligned.m8n8.x4.shared.b16 {%0,%1,%2,%3}, [%4];"
                 : "=r"(r0), "=r"(r1), "=r"(r2), "=r"(r3) : "r"(addr));
}
__device__ __forceinline__ void ldsm4t(uint32_t& r0, uint32_t& r1, uint32_t& r2, uint32_t& r3,
                                       uint32_t addr) {
    asm volatile("ldmatrix.sync.aligned.m8n8.x4.trans.shared.b16 {%0,%1,%2,%3}, [%4];"
                 : "=r"(r0), "=r"(r1), "=r"(r2), "=r"(r3) : "r"(addr));
}
__device__ __forceinline__ uint32_t f2h2(float a, float b) {
    __half2 h = __floats2half2_rn(a, b);
    return *reinterpret_cast<uint32_t*>(&h);
}
// packed half2 exp2: one MUFU op for two elements
__device__ __forceinline__ uint32_t h2ex2(uint32_t x) {
    uint32_t y;
    asm("ex2.approx.f16x2 %0, %1;" : "=r"(y) : "r"(x));
    return y;
}

__device__ __forceinline__ uint32_t smem_u32(const void* p) {
    uint32_t a;
    asm("{ .reg .u64 t; cvta.to.shared.u64 t, %1; cvt.u32.u64 %0, t; }" : "=r"(a) : "l"(p));
    return a;
}
__device__ __forceinline__ void cpa16(uint32_t dst, const void* src) {
    asm volatile("cp.async.ca.shared.global [%0], [%1], 16;" :: "r"(dst), "l"(src));
}
#define CP_COMMIT() asm volatile("cp.async.commit_group;" ::: "memory")
#define CP_WAIT1()  asm volatile("cp.async.wait_group 1;" ::: "memory")
#define CP_WAIT0()  asm volatile("cp.async.wait_group 0;" ::: "memory")

// ---------------------------------------------------------------------------
// Prep kernels: fp32 -> f16 (+ zero BN accumulators)
// ---------------------------------------------------------------------------
__global__ void __launch_bounds__(256) prep_w(
    const float* __restrict__ gw, const float* __restrict__ tw,
    const float* __restrict__ pw, const float* __restrict__ ww)
{
    int gid = blockIdx.x * 256 + threadIdx.x;     // per float4
    if (gid < NC) { d_bnsum[gid] = 0.f; d_bnsq[gid] = 0.f; }
    int m = gid >> 16;
    int rem = gid & 65535;
    const float* src = (m == 0) ? gw : (m == 1) ? tw : (m == 2) ? pw : ww;
    float4 v = *(const float4*)(src + (size_t)rem * 4);
    uint2 o = make_uint2(f2h2(v.x, v.y), f2h2(v.z, v.w));
    *(uint2*)(d_wh + (size_t)m * 262144 + (size_t)rem * 4) = o;
}

// transpose [b][512 ci][2048 l] f32 -> [b][l][ci] f16; grid (32 lt, 8 cit, 4 b)
__global__ void __launch_bounds__(256) prep_x(const float* __restrict__ in)
{
    __shared__ float sm[64][65];
    const int tid = threadIdx.x;
    const int l0 = blockIdx.x * 64, ci0 = blockIdx.y * 64, b = blockIdx.z;
    const float* src = in + (size_t)b * 512 * NL;
    __half* dst = d_xh + (size_t)b * NL * 512;
#pragma unroll
    for (int it = 0; it < 4; it++) {
        int ci = (tid >> 4) + 16 * it;
        int ll = (tid & 15) * 4;
        float4 v = *(const float4*)(src + (size_t)(ci0 + ci) * NL + l0 + ll);
        sm[ci][ll] = v.x; sm[ci][ll + 1] = v.y; sm[ci][ll + 2] = v.z; sm[ci][ll + 3] = v.w;
    }
    __syncthreads();
#pragma unroll
    for (int it = 0; it < 4; it++) {
        int ll = (tid >> 4) + 16 * it;
        int cb = (tid & 15) * 4;
        uint2 o = make_uint2(f2h2(sm[cb][ll], sm[cb + 1][ll]),
                             f2h2(sm[cb + 2][ll], sm[cb + 3][ll]));
        *(uint2*)(dst + (size_t)(l0 + ll) * 512 + ci0 + cb) = o;
    }
}

// ---------------------------------------------------------------------------
// Dense GEMM f16 v2: CTA 128co x 256l, 8 warps (2 wm x 4 wn), warp tile 64x64.
// Per k16: 4 A-ldsm + 4 B-ldsm -> 32 HMMA (4.0 HMMA/ldsm).
// k-slabs of 64, 2-stage cp.async; smem 96KB (A 16KB + B 32KB per stage).
// STATS: fused per-channel sum / sum-sq atomics (gemm2 only)
// ---------------------------------------------------------------------------
#define DS_SMEM 98304

__device__ __forceinline__ uint32_t dswz(uint32_t base, int row, int c) {
    return base + row * 128 + ((c ^ (row & 7)) << 4);
}

template <bool HALF_OUT, bool STATS>
__device__ __forceinline__ void gemm_body_f16(
    const __half* __restrict__ Wp,    // offset to co0; row pitch 512
    const __half* __restrict__ Xp,    // [l][512]
    const float* __restrict__ bias,   // offset to co0
    float* __restrict__ outf,
    __half* __restrict__ outh,
    float* __restrict__ bnsum,        // offset to co0 (STATS only)
    float* __restrict__ bnsq,
    float oscale,
    int l0)                           // 256-wide l tile
{
    extern __shared__ float ds[];
    const uint32_t sb = smem_u32(ds);
    const int tid = threadIdx.x, lane = tid & 31, w = tid >> 5;
    const int wm = w >> 2, wn = w & 3;
    const int lt = lane >> 3, li = lane & 7;
    const int srowA = tid >> 1, scpA = tid & 1;

    float acc[4][8][4];
#pragma unroll
    for (int i = 0; i < 4; i++)
#pragma unroll
        for (int j = 0; j < 8; j++)
#pragma unroll
            for (int k = 0; k < 4; k++) acc[i][j][k] = 0.f;

#define DISSUE(kt) do { \
    uint32_t bA = sb + ((kt) & 1) * 49152, bB = bA + 16384; \
    const __half* wsrc = Wp + (size_t)srowA * 512 + (kt) * 64; \
    const __half* xsrc = Xp + (size_t)(l0 + tid) * 512 + (kt) * 64; \
    _Pragma("unroll") \
    for (int u = 0; u < 4; u++) { \
        int c = scpA * 4 + u; \
        cpa16(dswz(bA, srowA, c), wsrc + c * 8); \
    } \
    _Pragma("unroll") \
    for (int u = 0; u < 8; u++) { \
        cpa16(dswz(bB, tid, u), xsrc + u * 8); \
    } \
    CP_COMMIT(); \
} while (0)

    DISSUE(0); DISSUE(1);

    for (int kt = 0; kt < 8; kt++) {
        if (kt < 7) CP_WAIT1(); else CP_WAIT0();
        __syncthreads();

        const uint32_t bA = sb + (kt & 1) * 49152, bB = bA + 16384;
#pragma unroll
        for (int kc = 0; kc < 4; kc++) {
            uint32_t af[4][4];
#pragma unroll
            for (int im = 0; im < 4; im++) {
                int row = wm * 64 + im * 16 + 8 * (lt & 1) + li;
                int c = 2 * kc + (lt >> 1);
                ldsm4(af[im][0], af[im][1], af[im][2], af[im][3], dswz(bA, row, c));
            }
#pragma unroll
            for (int bt = 0; bt < 4; bt++) {
                uint32_t b0, b1, b2, b3;
                int lrow = wn * 64 + bt * 16 + 8 * (lt >> 1) + li;
                int c = 2 * kc + (lt & 1);
                ldsm4(b0, b1, b2, b3, dswz(bB, lrow, c));
#pragma unroll
                for (int im = 0; im < 4; im++) {
                    hmma(acc[im][2 * bt],     af[im][0], af[im][1], af[im][2], af[im][3], b0, b1);
                    hmma(acc[im][2 * bt + 1], af[im][0], af[im][1], af[im][2], af[im][3], b2, b3);
                }
            }
        }
        __syncthreads();
        if (kt + 2 < 8) DISSUE(kt + 2);
    }
#undef DISSUE

    const int r = lane >> 2, j = lane & 3;
#pragma unroll
    for (int im = 0; im < 4; im++) {
        int row = wm * 64 + im * 16 + r;
        float b0 = bias[row], b1 = bias[row + 8];
        float s0 = 0.f, q0 = 0.f, s1 = 0.f, q1 = 0.f;
#pragma unroll
        for (int nt = 0; nt < 8; nt++) {
            int col = l0 + wn * 64 + nt * 8 + 2 * j;
            float v00 = acc[im][nt][0] + b0, v01 = acc[im][nt][1] + b0;
            float v10 = acc[im][nt][2] + b1, v11 = acc[im][nt][3] + b1;
            if (HALF_OUT) {
                *(__half2*)&outh[(size_t)row * NL + col] =
                    __floats2half2_rn(v00 * oscale, v01 * oscale);
                *(__half2*)&outh[(size_t)(row + 8) * NL + col] =
                    __floats2half2_rn(v10 * oscale, v11 * oscale);
            } else {
                *(float2*)&outf[(size_t)row * NL + col] = make_float2(v00, v01);
                *(float2*)&outf[(size_t)(row + 8) * NL + col] = make_float2(v10, v11);
            }
            if (STATS) {
                s0 += v00 + v01; q0 = fmaf(v00, v00, fmaf(v01, v01, q0));
                s1 += v10 + v11; q1 = fmaf(v10, v10, fmaf(v11, v11, q1));
            }
        }
        if (STATS) {
            s0 += __shfl_xor_sync(0xffffffffu, s0, 1);
            s0 += __shfl_xor_sync(0xffffffffu, s0, 2);
            q0 += __shfl_xor_sync(0xffffffffu, q0, 1);
            q0 += __shfl_xor_sync(0xffffffffu, q0, 2);
            s1 += __shfl_xor_sync(0xffffffffu, s1, 1);
            s1 += __shfl_xor_sync(0xffffffffu, s1, 2);
            q1 += __shfl_xor_sync(0xffffffffu, q1, 1);
            q1 += __shfl_xor_sync(0xffffffffu, q1, 2);
            if (j == 0) {
                atomicAdd(&bnsum[row], s0);
                atomicAdd(&bnsq[row], q0);
                atomicAdd(&bnsum[row + 8], s1);
                atomicAdd(&bnsq[row + 8], q1);
            }
        }
    }
}

__global__ void __launch_bounds__(256) proj_tc(
    const float* __restrict__ gb, const float* __restrict__ tbb, const float* __restrict__ pb)
{
    const int which = blockIdx.y >> 2;
    const int co0 = (blockIdx.y & 3) * 128;
    const int b = blockIdx.z;
    const float* bias = (which == 0 ? gb : which == 1 ? tbb : pb);
    // theta gets 0.125 * log2(e) so attention can use ex2 directly
    gemm_body_f16<true, false>(d_wh + ((size_t)which * 512 + co0) * 512,
                               d_xh + (size_t)b * NL * 512,
                               bias + co0,
                               nullptr,
                               d_projh + ((size_t)which * NB + b) * NCI * NL + (size_t)co0 * NL,
                               nullptr, nullptr,
                               which == 1 ? 0.18033688f : 1.0f,
                               blockIdx.x * 256);
}

__global__ void __launch_bounds__(256) gemm2_tc(const float* __restrict__ wb)
{
    const int co0 = blockIdx.y * 128;
    const int b = blockIdx.z;
    gemm_body_f16<false, true>(d_wh + ((size_t)3 * 512 + co0) * 512,
                               d_yh + (size_t)b * NL * 512,
                               wb + co0,
                               d_wy + (size_t)b * NC * NL + (size_t)co0 * NL,
                               nullptr,
                               d_bnsum + co0, d_bnsq + co0,
                               1.0f, blockIdx.x * 256);
}

// ---------------------------------------------------------------------------
// Attention (round-12, unchanged): 4 warps x 32q, f16 m16n8k16, cp.async,
// hoisted Q frags, f16x2 ex2, row sums via ones-HMMA.
// ---------------------------------------------------------------------------
#define AT_SMEM 49152

__device__ __forceinline__ uint32_t qswz(uint32_t base, int d, int qblk) {
    return base + d * 256 + ((qblk ^ (d & 7)) << 4);
}
__device__ __forceinline__ uint32_t kswz(uint32_t base, int d, int cblk) {
    return base + d * 128 + ((cblk ^ (d & 7)) << 4);
}

__global__ void __launch_bounds__(128, 2) attn_tc()
{
    extern __shared__ char smc[];
    const uint32_t sb = smem_u32(smc);
    const uint32_t Qb = sb, Kb = sb + 16384, Vb = sb + 32768;

    const int tid = threadIdx.x, lane = tid & 31, w = tid >> 5;   // w in 0..3
    const int r = lane >> 2, j = lane & 3;
    const int lt = lane >> 3, li = lane & 7;
    const int q0 = blockIdx.x * 128;
    const int b = blockIdx.y >> 3, h = blockIdx.y & 7;

    const __half* thetah = d_projh + ((size_t)(1 * NB + b) * NCI + h * ND) * NL;
    const __half* phih   = d_projh + ((size_t)(2 * NB + b) * NCI + h * ND) * NL;
    const __half* gxh    = d_projh + ((size_t)(0 * NB + b) * NCI + h * ND) * NL;

    const int srow = tid >> 1;      // staging d row (0..63)
    const int shalf = tid & 1;

#pragma unroll
    for (int u = 0; u < 8; u++) {
        int ch = shalf * 8 + u;
        cpa16(qswz(Qb, srow, ch), thetah + (size_t)srow * NL + q0 + ch * 8);
    }
#pragma unroll
    for (int u = 0; u < 4; u++) {
        int ch = shalf * 4 + u;
        cpa16(kswz(Kb, srow, ch), phih + (size_t)srow * NL + ch * 8);
        cpa16(kswz(Vb, srow, ch), gxh + (size_t)srow * NL + ch * 8);
    }
    CP_COMMIT();

    const uint32_t ONES = 0x3C003C00u;
    uint32_t qf[2][4][4];
    float acc_o[2][8][4];
    float acc_l[2][4];
#pragma unroll
    for (int m = 0; m < 2; m++) {
#pragma unroll
        for (int n = 0; n < 8; n++)
#pragma unroll
            for (int k = 0; k < 4; k++) acc_o[m][n][k] = 0.f;
#pragma unroll
        for (int k = 0; k < 4; k++) acc_l[m][k] = 0.f;
    }

    for (int it = 0; it < 32; it++) {
        __syncthreads();
        if (it + 1 < 32) {
            const int nb_ = (it + 1) & 1;
            const size_t kko = (size_t)(it + 1) * 64;
#pragma unroll
            for (int u = 0; u < 4; u++) {
                int ch = shalf * 4 + u;
                cpa16(kswz(Kb + nb_ * 8192, srow, ch), phih + (size_t)srow * NL + kko + ch * 8);
                cpa16(kswz(Vb + nb_ * 8192, srow, ch), gxh + (size_t)srow * NL + kko + ch * 8);
            }
            CP_COMMIT();
            CP_WAIT1();
        } else {
            CP_WAIT0();
        }
        __syncthreads();

        if (it == 0) {
#pragma unroll
            for (int m = 0; m < 2; m++)
#pragma unroll
                for (int s = 0; s < 4; s++) {
                    int d = 16 * s + 8 * (lt >> 1) + li;
                    int qblk = 4 * w + 2 * m + (lt & 1);
                    ldsm4t(qf[m][s][0], qf[m][s][1], qf[m][s][2], qf[m][s][3], qswz(Qb, d, qblk));
                }
        }

        const uint32_t Kc = Kb + (it & 1) * 8192;
        const uint32_t Vc = Vb + (it & 1) * 8192;

        float s_acc[2][8][4];
#pragma unroll
        for (int m = 0; m < 2; m++)
#pragma unroll
            for (int n = 0; n < 8; n++)
#pragma unroll
                for (int k = 0; k < 4; k++) s_acc[m][n][k] = 0.f;

#pragma unroll
        for (int s = 0; s < 4; s++) {
#pragma unroll
            for (int np = 0; np < 4; np++) {
                uint32_t k0, k1, k2, k3;
                int d = 16 * s + 8 * (lt & 1) + li;
                int cb = 2 * np + (lt >> 1);
                ldsm4t(k0, k1, k2, k3, kswz(Kc, d, cb));
#pragma unroll
                for (int m = 0; m < 2; m++) {
                    hmma(s_acc[m][2 * np],     qf[m][s][0], qf[m][s][1], qf[m][s][2], qf[m][s][3], k0, k1);
                    hmma(s_acc[m][2 * np + 1], qf[m][s][0], qf[m][s][1], qf[m][s][2], qf[m][s][3], k2, k3);
                }
            }
        }

#pragma unroll
        for (int sv = 0; sv < 4; sv++) {
            uint32_t pa[2][4];
#pragma unroll
            for (int m = 0; m < 2; m++) {
                pa[m][0] = h2ex2(f2h2(s_acc[m][2 * sv][0],     s_acc[m][2 * sv][1]));
                pa[m][1] = h2ex2(f2h2(s_acc[m][2 * sv][2],     s_acc[m][2 * sv][3]));
                pa[m][2] = h2ex2(f2h2(s_acc[m][2 * sv + 1][0], s_acc[m][2 * sv + 1][1]));
                pa[m][3] = h2ex2(f2h2(s_acc[m][2 * sv + 1][2], s_acc[m][2 * sv + 1][3]));
                hmma(acc_l[m], pa[m][0], pa[m][1], pa[m][2], pa[m][3], ONES, ONES);
            }
#pragma unroll
            for (int dp = 0; dp < 4; dp++) {
                uint32_t v0, v1, v2, v3;
                int d = 16 * dp + 8 * (lt >> 1) + li;
                int cb = 2 * sv + (lt & 1);
                ldsm4(v0, v1, v2, v3, kswz(Vc, d, cb));
#pragma unroll
                for (int m = 0; m < 2; m++) {
                    hmma(acc_o[m][2 * dp],     pa[m][0], pa[m][1], pa[m][2], pa[m][3], v0, v1);
                    hmma(acc_o[m][2 * dp + 1], pa[m][0], pa[m][1], pa[m][2], pa[m][3], v2, v3);
                }
            }
        }
    }

#pragma unroll
    for (int m = 0; m < 2; m++) {
        const float inv0 = 1.0f / acc_l[m][0];
        const float inv1 = 1.0f / acc_l[m][2];
        const int q = 32 * w + 16 * m + r;
        __half* y0 = d_yh + ((size_t)b * NL + q0 + q) * 512 + h * 64;
        __half* y1 = y0 + (size_t)8 * 512;
#pragma unroll
        for (int nd = 0; nd < 8; nd++) {
            int d = 8 * nd + 2 * j;
            *(__half2*)(y0 + d) = __floats2half2_rn(acc_o[m][nd][0] * inv0, acc_o[m][nd][1] * inv0);
            *(__half2*)(y1 + d) = __floats2half2_rn(acc_o[m][nd][2] * inv1, acc_o[m][nd][3] * inv1);
        }
    }
}

// ---------------------------------------------------------------------------
// BatchNorm: finalize (stats fused into gemm2) + apply
// ---------------------------------------------------------------------------
__global__ void __launch_bounds__(256) bn_finalize()
{
    int c = blockIdx.x * 256 + threadIdx.x;
    float mean = d_bnsum[c] * (1.0f / (NB * NL));
    float var = d_bnsq[c] * (1.0f / (NB * NL)) - mean * mean;
    d_bnmean[c] = mean;
    d_bnrstd[c] = rsqrtf(var + 1e-5f);
}

__global__ void __launch_bounds__(256) bn_apply_kernel(
    const float* __restrict__ gamma, const float* __restrict__ beta,
    float* __restrict__ out)
{
    int i4 = blockIdx.x * 256 + threadIdx.x;
    int c = (i4 >> 9) & (NC - 1);
    float4 v = reinterpret_cast<const float4*>(d_wy)[i4];
    float m = d_bnmean[c], rs = d_bnrstd[c] * gamma[c], bt = beta[c];
    float4 o = make_float4((v.x - m) * rs + bt, (v.y - m) * rs + bt,
                           (v.z - m) * rs + bt, (v.w - m) * rs + bt);
    reinterpret_cast<float4*>(out)[i4] = o;
}

// ---------------------------------------------------------------------------
extern "C" void kernel_launch(void* const* d_in, const int* in_sizes, int n_in,
                              void* d_out, int out_size)
{
    const float* x     = (const float*)d_in[0];
    const float* gw    = (const float*)d_in[1];
    const float* gb    = (const float*)d_in[2];
    const float* tw    = (const float*)d_in[3];
    const float* tb    = (const float*)d_in[4];
    const float* pw    = (const float*)d_in[5];
    const float* pb    = (const float*)d_in[6];
    const float* ww    = (const float*)d_in[7];
    const float* wb    = (const float*)d_in[8];
    const float* gamma = (const float*)d_in[9];
    const float* beta  = (const float*)d_in[10];
    float* out = (float*)d_out;

    cudaFuncSetAttribute(proj_tc, cudaFuncAttributeMaxDynamicSharedMemorySize, DS_SMEM);
    cudaFuncSetAttribute(gemm2_tc, cudaFuncAttributeMaxDynamicSharedMemorySize, DS_SMEM);
    cudaFuncSetAttribute(attn_tc, cudaFuncAttributeMaxDynamicSharedMemorySize, AT_SMEM);

    prep_w<<<1024, 256>>>(gw, tw, pw, ww);
    prep_x<<<dim3(32, 8, 4), 256>>>(x);
    proj_tc<<<dim3(8, 12, 4), 256, DS_SMEM>>>(gb, tb, pb);
    attn_tc<<<dim3(16, 32), 128, AT_SMEM>>>();
    gemm2_tc<<<dim3(8, 4, 4), 256, DS_SMEM>>>(wb);
    bn_finalize<<<2, 256>>>();
    bn_apply_kernel<<<(NB * NC * NL) / 1024, 256>>>(gamma, beta, out);
}